// round 9
// baseline (speedup 1.0000x reference)
#include <cuda_runtime.h>
#include <cuda_bf16.h>
#include <math.h>
#include <stdint.h>

typedef __nv_bfloat16 bf16;
typedef __nv_bfloat162 bf162;

#define MAXN   120000
#define SLOPEF 0.01f
#define EPSF   1e-6f
#define PVMAX  (3*MAXN*64)

// ---------------- static device scratch (bf16 split: [hi | lo]) -------------
__device__ __align__(16) bf16  g_vecS[2*PVMAX];
__device__ __align__(16) bf16  g_viAs[2*PVMAX];
__device__ __align__(16) bf16  g_viNs[2*PVMAX];   // later: vi2n
__device__ __align__(16) bf16  g_uas [2*PVMAX];
__device__ __align__(16) bf16  g_uns [2*PVMAX];
__device__ __align__(16) bf16  g_vas [2*PVMAX];   // later: fv
__device__ __align__(16) bf16  g_vns [2*PVMAX];
__device__ __align__(16) bf16  g_scaX[2*MAXN*256];
__device__ __align__(16) bf16  g_lrS [2*MAXN*256];
__device__ __align__(16) bf16  g_Sas [2*MAXN*256]; // later: fs
__device__ __align__(16) bf16  g_Sns [2*MAXN*256];
__device__ __align__(16) bf16  g_nA1 [2*MAXN*64];
__device__ __align__(16) bf16  g_nN1 [2*MAXN*64];
__device__ __align__(16) bf16  g_nA2 [2*MAXN*64];
__device__ __align__(16) bf16  g_nN2 [2*MAXN*64];
__device__ __align__(16) bf16  g_Baug[1048576];
__device__ float g_Ga  [MAXN*64];
__device__ float g_Gn  [MAXN*64];
__device__ float g_att [MAXN];
__device__ float g_w   [MAXN];
__device__ int   g_seg [4100];

// ---------------- helpers ----------------
__device__ __forceinline__ uint32_t smem_u32(const void* p) {
    return (uint32_t)__cvta_generic_to_shared(p);
}
__device__ __forceinline__ void split2(float x, bf16& h, bf16& l) {
    h = __float2bfloat16(x);
    l = __float2bfloat16(x - __bfloat162float(h));
}
__device__ __forceinline__ float join2(bf16 h, bf16 l) {
    return __bfloat162float(h) + __bfloat162float(l);
}
__device__ __forceinline__ void store_split2(bf16* H, bf16* L, size_t o, float v0, float v1) {
    bf16 h0, l0, h1, l1;
    split2(v0, h0, l0); split2(v1, h1, l1);
    bf162 th; th.x = h0; th.y = h1;
    bf162 tl; tl.x = l0; tl.y = l1;
    *(bf162*)(H + o) = th;
    *(bf162*)(L + o) = tl;
}

#define MMA16816(d, a, b)                                                     \
    asm volatile("mma.sync.aligned.m16n8k16.row.col.f32.bf16.bf16.f32 "      \
        "{%0,%1,%2,%3}, {%4,%5,%6,%7}, {%8,%9}, {%0,%1,%2,%3};"              \
        : "+f"((d)[0]), "+f"((d)[1]), "+f"((d)[2]), "+f"((d)[3])             \
        : "r"((a)[0]), "r"((a)[1]), "r"((a)[2]), "r"((a)[3]),                \
          "r"((b)[0]), "r"((b)[1]))

#define LDSM_X4(r0, r1, r2, r3, addr)                                        \
    asm volatile("ldmatrix.sync.aligned.m8n8.x4.shared.b16 {%0,%1,%2,%3}, [%4];" \
        : "=r"(r0), "=r"(r1), "=r"(r2), "=r"(r3) : "r"(addr))

#define CP_ASYNC16(sa, ga)                                                   \
    asm volatile("cp.async.cg.shared.global [%0], [%1], 16;" :: "r"(sa), "l"(ga))
#define CP_ASYNC16_P(sa, ga, p)                                              \
    asm volatile("cp.async.cg.shared.global [%0], [%1], 16, %2;" :: "r"(sa), "l"(ga), "r"(p))
#define CP_COMMIT() asm volatile("cp.async.commit_group;")
#define CP_WAIT0()  asm volatile("cp.async.wait_group 0;")

// ---------------------------------------------------------------------------
// generic HMMA GEMM with two A regions: cols [0,K1) from A1, [K1,K) from A2
// C[M,NC] = epi( (A1|A2)hi+lo @ B^T ), B prepacked [NC][hi K | lo K]
// NC=64: 256 thr (8 warps 4x2). NC=256: 512 thr (16 warps 4x4).
// Stage loop: ONE barrier per stage; load(s+1) issued after the barrier so
// cp.async drains underneath the MMA burst.
// ---------------------------------------------------------------------------
struct GSet {
    const bf16 *A1h, *A1l, *A2h, *A2l;
    int K1;
    const bf16* B;
    float* Cf; bf16 *Chi, *Clo;
    bf16 *Lhi, *Llo;                 // optional lrelu split side-output
    const float *bias, *gate;
    int act;
};

template <int NC>
__global__ void __launch_bounds__(NC == 256 ? 512 : 256)
gemm_bf16(GSet s0, GSet s1, int M, int K, int Nn) {
    constexpr int NTH   = (NC == 256) ? 512 : 256;
    constexpr int NWN   = (NC == 256) ? 4 : 2;
    constexpr int WCOLS = NC / NWN;
    constexpr int NT    = WCOLS / 8;
    constexpr int A_ST  = 128 * 40;
    constexpr int B_ST  = NC * 40;

    extern __shared__ bf16 sm[];
    bf16* smA = sm;
    bf16* smB = sm + 2 * A_ST;

    const int tid = threadIdx.x;
    const int lane = tid & 31, wid = tid >> 5;
    const int wm = wid / NWN, wn = wid % NWN;
    const GSet S = (blockIdx.y == 0) ? s0 : s1;
    const int m0 = blockIdx.x * 128;
    const int KC = K >> 5;
    const int ST = 2 * KC;
    const size_t K2 = (size_t)2 * K;
    const int K2w = K - S.K1;

    float acc[2][NT][4];
#pragma unroll
    for (int i = 0; i < 2; i++)
#pragma unroll
        for (int j = 0; j < NT; j++)
#pragma unroll
            for (int k = 0; k < 4; k++) acc[i][j][k] = 0.f;

    auto load_stage = [&](int s, int buf) {
        bool hp = (s < KC);
        int kc = hp ? s : s - KC;
        int kof = kc * 32;
        const bf16* base; int stride, col;
        if (kof < S.K1) { base = hp ? S.A1h : S.A1l; stride = S.K1; col = kof; }
        else            { base = hp ? S.A2h : S.A2l; stride = K2w;  col = kof - S.K1; }
        for (int i = tid; i < 512; i += NTH) {
            int r = i >> 2, sg = i & 3;
            int m = m0 + r;
            uint32_t sa = smem_u32(smA + buf * A_ST + r * 40 + sg * 8);
            const bf16* ga = base + ((m < M) ? ((size_t)m * stride + col + sg * 8) : 0);
            CP_ASYNC16_P(sa, ga, (m < M) ? 16 : 0);
        }
        int c0 = kc * 32;
        for (int i = tid; i < NC * 4; i += NTH) {
            int r = i >> 2, sg = i & 3;
            uint32_t sa = smem_u32(smB + (buf * 2 + 0) * B_ST + r * 40 + sg * 8);
            CP_ASYNC16(sa, S.B + (size_t)r * K2 + c0 + sg * 8);
        }
        if (hp) {
            int c1 = K + kc * 32;
            for (int i = tid; i < NC * 4; i += NTH) {
                int r = i >> 2, sg = i & 3;
                uint32_t sa = smem_u32(smB + (buf * 2 + 1) * B_ST + r * 40 + sg * 8);
                CP_ASYNC16(sa, S.B + (size_t)r * K2 + c1 + sg * 8);
            }
        }
        CP_COMMIT();
    };

    load_stage(0, 0);
    for (int s = 0; s < ST; s++) {
        int buf = s & 1;
        CP_WAIT0();
        __syncthreads();                       // data(s) visible; buf^1 free
        if (s + 1 < ST) load_stage(s + 1, buf ^ 1);   // overlaps the MMAs below
        const bool dual = (s < KC);
#pragma unroll
        for (int kk = 0; kk < 2; kk++) {
            const int k16 = kk * 16;
            uint32_t a[2][4];
#pragma unroll
            for (int mt = 0; mt < 2; mt++) {
                uint32_t ad = smem_u32(smA + buf * A_ST
                                       + (wm * 32 + mt * 16 + (lane & 15)) * 40
                                       + k16 + (lane >> 4) * 8);
                LDSM_X4(a[mt][0], a[mt][1], a[mt][2], a[mt][3], ad);
            }
#pragma unroll
            for (int sub = 0; sub < 2; sub++) {
                if (sub == 1 && !dual) break;
                uint32_t b[NT][2];
#pragma unroll
                for (int half = 0; half < NT / 2; half++) {
                    int g = lane >> 3, r = lane & 7;
                    int nt8 = (g >> 1), ko = (g & 1) * 8;
                    uint32_t ad = smem_u32(smB + (buf * 2 + sub) * B_ST
                                           + (wn * WCOLS + half * 16 + nt8 * 8 + r) * 40
                                           + k16 + ko);
                    uint32_t r0, r1, r2, r3;
                    LDSM_X4(r0, r1, r2, r3, ad);
                    b[half * 2 + 0][0] = r0; b[half * 2 + 0][1] = r1;
                    b[half * 2 + 1][0] = r2; b[half * 2 + 1][1] = r3;
                }
#pragma unroll
                for (int mt = 0; mt < 2; mt++)
#pragma unroll
                    for (int nt = 0; nt < NT; nt++)
                        MMA16816(acc[mt][nt], a[mt], b[nt]);
            }
        }
    }

#pragma unroll
    for (int mt = 0; mt < 2; mt++) {
#pragma unroll
        for (int hh = 0; hh < 2; hh++) {
            int m = m0 + wm * 32 + mt * 16 + (lane >> 2) + hh * 8;
            if (m >= M) continue;
            int node = m % Nn;
#pragma unroll
            for (int nt = 0; nt < NT; nt++) {
                int col = wn * WCOLS + nt * 8 + (lane & 3) * 2;
                float v0 = acc[mt][nt][hh * 2 + 0];
                float v1 = acc[mt][nt][hh * 2 + 1];
                if (S.act) {
                    v0 = 1.f / (1.f + __expf(-(v0 + S.bias[col])));
                    v1 = 1.f / (1.f + __expf(-(v1 + S.bias[col + 1])));
                }
                if (S.gate) {
                    v0 *= S.gate[(size_t)node * 64 + col];
                    v1 *= S.gate[(size_t)node * 64 + col + 1];
                }
                size_t o = (size_t)m * NC + col;
                if (S.Cf) *(float2*)(S.Cf + o) = make_float2(v0, v1);
                if (S.Chi) store_split2(S.Chi, S.Clo, o, v0, v1);
                if (S.Lhi) {
                    float l0 = (v0 >= 0.f) ? v0 : SLOPEF * v0;
                    float l1 = (v1 >= 0.f) ? v1 : SLOPEF * v1;
                    store_split2(S.Lhi, S.Llo, o, l0, l1);
                }
            }
        }
    }
}

// ---------------------------------------------------------------------------
// 3-plane VN GEMM (K=64, NC=64): one block = 128 nodes x 64 cols, loops d=0..2
// internally with B resident in smem. Epilogue holds all 3 components:
//   - optional vn_lrelu against u (Uhi/Ulo planes)
//   - optional plane outputs Chi/Clo, optional norm outputs Nhi/Nlo [n,64]
// ---------------------------------------------------------------------------
struct VSet {
    const bf16 *Ahi, *Alo;      // planes [d][n][64]
    const bf16 *B;              // [64][128]  (hi 64 | lo 64)
    const bf16 *Uhi, *Ulo;      // vn_lrelu input planes (or null)
    bf16 *Chi, *Clo;            // plane outputs (or null)
    bf16 *Nhi, *Nlo;            // norm outputs [n,64] (or null)
};

__global__ void __launch_bounds__(256)
gemm_vn3(VSet s0, VSet s1, int Nn) {
    __shared__ bf16 Bs[64 * 136];
    __shared__ bf16 As[2][128 * 40];
    const int tid = threadIdx.x, lane = tid & 31, wid = tid >> 5;
    const int wm = wid >> 1, wn = wid & 1;
    const VSet S = blockIdx.y ? s1 : s0;
    const int m0 = blockIdx.x * 128;
    const size_t P = (size_t)Nn * 64;

    // B resident: 64 rows x 128 bf16 cols = 16 chunks of 16B per row
    for (int i = tid; i < 1024; i += 256) {
        int r = i >> 4, c8 = i & 15;
        CP_ASYNC16(smem_u32(Bs + r * 136 + c8 * 8), S.B + r * 128 + c8 * 8);
    }
    CP_COMMIT();

    float acc[3][2][4][4];
#pragma unroll
    for (int d = 0; d < 3; d++)
#pragma unroll
        for (int i = 0; i < 2; i++)
#pragma unroll
            for (int j = 0; j < 4; j++)
#pragma unroll
                for (int k = 0; k < 4; k++) acc[d][i][j][k] = 0.f;

    auto loadA = [&](int gs, int buf) {
        int d = gs >> 2, s = gs & 3;
        const bf16* Ab = (s < 2) ? S.Ahi : S.Alo;
        int kof = (s & 1) * 32;
        for (int i = tid; i < 512; i += 256) {
            int r = i >> 2, sg = i & 3;
            int m = m0 + r;
            uint32_t sa = smem_u32(As[buf] + r * 40 + sg * 8);
            const bf16* ga = Ab + d * P + ((m < Nn) ? ((size_t)m * 64 + kof + sg * 8) : 0);
            CP_ASYNC16_P(sa, ga, (m < Nn) ? 16 : 0);
        }
        CP_COMMIT();
    };

    loadA(0, 0);
    for (int gs = 0; gs < 12; gs++) {
        int buf = gs & 1;
        CP_WAIT0();
        __syncthreads();
        if (gs + 1 < 12) loadA(gs + 1, buf ^ 1);
        int d = gs >> 2, s = gs & 3;
        bool dual = (s < 2);
        int kc = s & 1;
#pragma unroll
        for (int kk = 0; kk < 2; kk++) {
            const int k16 = kk * 16;
            uint32_t a[2][4];
#pragma unroll
            for (int mt = 0; mt < 2; mt++) {
                uint32_t ad = smem_u32(As[buf] + (wm * 32 + mt * 16 + (lane & 15)) * 40
                                       + k16 + (lane >> 4) * 8);
                LDSM_X4(a[mt][0], a[mt][1], a[mt][2], a[mt][3], ad);
            }
#pragma unroll
            for (int sub = 0; sub < 2; sub++) {
                if (sub == 1 && !dual) break;
                int bcol = sub * 64 + kc * 32;
                uint32_t b[4][2];
                {
                    int g = lane >> 3, r = lane & 7;
                    int nt8 = (g >> 1), ko = (g & 1) * 8;
#pragma unroll
                    for (int half = 0; half < 2; half++) {
                        uint32_t ad = smem_u32(Bs + (wn * 32 + half * 16 + nt8 * 8 + r) * 136
                                               + bcol + k16 + ko);
                        uint32_t r0, r1, r2, r3;
                        LDSM_X4(r0, r1, r2, r3, ad);
                        b[half * 2 + 0][0] = r0; b[half * 2 + 0][1] = r1;
                        b[half * 2 + 1][0] = r2; b[half * 2 + 1][1] = r3;
                    }
                }
#pragma unroll
                for (int mt = 0; mt < 2; mt++)
#pragma unroll
                    for (int nt = 0; nt < 4; nt++)
                        MMA16816(acc[d][mt][nt], a[mt], b[nt]);
            }
        }
    }

    // -------- fused epilogue --------
#pragma unroll
    for (int mt = 0; mt < 2; mt++) {
#pragma unroll
        for (int hh = 0; hh < 2; hh++) {
            int m = m0 + wm * 32 + mt * 16 + (lane >> 2) + hh * 8;
            if (m >= Nn) continue;
#pragma unroll
            for (int nt = 0; nt < 4; nt++) {
                int col = wn * 32 + nt * 8 + (lane & 3) * 2;
                float v[3][2];
#pragma unroll
                for (int d = 0; d < 3; d++) {
                    v[d][0] = acc[d][mt][nt][hh * 2 + 0];
                    v[d][1] = acc[d][mt][nt][hh * 2 + 1];
                }
                if (S.Uhi) {
                    float u[3][2];
#pragma unroll
                    for (int d = 0; d < 3; d++) {
                        size_t q = d * P + (size_t)m * 64 + col;
                        bf162 uh = *(const bf162*)(S.Uhi + q);
                        bf162 ul = *(const bf162*)(S.Ulo + q);
                        u[d][0] = join2(uh.x, ul.x);
                        u[d][1] = join2(uh.y, ul.y);
                    }
#pragma unroll
                    for (int e = 0; e < 2; e++) {
                        float dot = u[0][e] * v[0][e] + u[1][e] * v[1][e] + u[2][e] * v[2][e];
                        float dsq = v[0][e] * v[0][e] + v[1][e] * v[1][e] + v[2][e] * v[2][e];
                        float sc = dot / (dsq + EPSF);
#pragma unroll
                        for (int d = 0; d < 3; d++) {
                            float x = u[d][e];
                            float r = (dot >= 0.f) ? x
                                     : (SLOPEF * x + (1.f - SLOPEF) * (x - sc * v[d][e]));
                            v[d][e] = r;
                        }
                    }
                }
                if (S.Chi) {
#pragma unroll
                    for (int d = 0; d < 3; d++)
                        store_split2(S.Chi, S.Clo, d * P + (size_t)m * 64 + col, v[d][0], v[d][1]);
                }
                if (S.Nhi) {
                    float n0 = sqrtf(v[0][0] * v[0][0] + v[1][0] * v[1][0] + v[2][0] * v[2][0]);
                    float n1 = sqrtf(v[0][1] * v[0][1] + v[1][1] * v[1][1] + v[2][1] * v[2][1]);
                    store_split2(S.Nhi, S.Nlo, (size_t)m * 64 + col, n0, n1);
                }
            }
        }
    }
}

// ---------------------------------------------------------------------------
// weight prepack: W(nc,k) fp32 -> Baug(nc,2k) bf16 rows [hi | lo]
// ---------------------------------------------------------------------------
struct PPk { const float* w; bf16* o; int nc; int k; };
struct PPargs { PPk e[15]; };
__global__ void k_prepack(PPargs pa) {
    PPk p = pa.e[blockIdx.y];
    int tot = p.nc * p.k;
    for (int i = blockIdx.x * 256 + threadIdx.x; i < tot; i += gridDim.x * 256) {
        float x = p.w[i];
        bf16 h, l; split2(x, h, l);
        int r = i / p.k, kk = i - r * p.k;
        bf16* row = p.o + (size_t)r * 2 * p.k;
        row[kk] = h; row[p.k + kk] = l;
    }
}

// ---------------------------------------------------------------------------
// prep: vec -> split planes; sca = h_sca + te[t] -> shared split [n,256]
// ---------------------------------------------------------------------------
__global__ void k_prep(const float* __restrict__ h_vec, const float* __restrict__ h_sca,
                       const float* __restrict__ te, const int* __restrict__ tptr,
                       bf16* __restrict__ vhi, bf16* __restrict__ scah, int Nn) {
    size_t PV = (size_t)3 * Nn * 64;
    bf16* vlo = vhi + PV;
    bf16* scal = scah + (size_t)Nn * 256;
    int i = blockIdx.x * 256 + threadIdx.x;
    int half = Nn * 64;
    if (i < half) {
        int node = i >> 6, c = i & 63;
#pragma unroll
        for (int d = 0; d < 3; d++) {
            float x = h_vec[(size_t)node * 192 + c * 3 + d];
            bf16 h, l; split2(x, h, l);
            size_t o = (size_t)d * Nn * 64 + (size_t)node * 64 + c;
            vhi[o] = h; vlo[o] = l;
        }
    } else if (i < 2 * half) {
        int j = i - half;
        int node = j >> 6, q4 = (j & 63) * 4;
        int t = *tptr;
        float4 hs = *(const float4*)(h_sca + (size_t)node * 256 + q4);
        float4 tv = *(const float4*)(te + (size_t)t * 256 + q4);
        size_t o = (size_t)node * 256 + q4;
        store_split2(scah, scal, o,     hs.x + tv.x, hs.y + tv.y);
        store_split2(scah, scal, o + 2, hs.z + tv.z, hs.w + tv.w);
    }
}

// att[n] = Ws[0:64].|vi2a| + Ws[64:320].lrelu(Sa)
__global__ void k_att(const bf16* __restrict__ Nh, const bf16* __restrict__ Sa,
                      const float* __restrict__ Ws, float* __restrict__ att, int Nn) {
    __shared__ float ws[320];
    int tid = threadIdx.x, w = tid >> 5, lane = tid & 31;
    for (int i = tid; i < 320; i += 256) ws[i] = Ws[i];
    __syncthreads();
    int node = blockIdx.x * 8 + w;
    if (node >= Nn) return;
    const bf16* Nl = Nh + (size_t)Nn * 64;
    const bf16* Sal = Sa + (size_t)Nn * 256;
    float p = 0.f;
    for (int c = lane; c < 64; c += 32) {
        size_t q = (size_t)node * 64 + c;
        p = fmaf(ws[c], join2(Nh[q], Nl[q]), p);
    }
    for (int k = lane; k < 256; k += 32) {
        size_t q = (size_t)node * 256 + k;
        float sv = join2(Sa[q], Sal[q]);
        sv = (sv >= 0.f) ? sv : SLOPEF * sv;
        p = fmaf(ws[64 + k], sv, p);
    }
#pragma unroll
    for (int o = 16; o > 0; o >>= 1) p += __shfl_down_sync(0xffffffff, p, o);
    if (lane == 0) att[node] = p;
}

__global__ void k_segstart(const int* __restrict__ bid, int n, int B, int* __restrict__ start) {
    int b = blockIdx.x * blockDim.x + threadIdx.x;
    if (b > B) return;
    int lo = 0, hi = n;
    while (lo < hi) { int mid = (lo + hi) >> 1; if (bid[mid] < b) lo = mid + 1; else hi = mid; }
    start[b] = lo;
}

__global__ void k_softmax(const float* __restrict__ att, const int* __restrict__ start,
                          float* __restrict__ w) {
    int b = blockIdx.x;
    int s = start[b], e = start[b + 1];
    if (s >= e) return;
    __shared__ float red[256];
    int tid = threadIdx.x;
    float m = -INFINITY;
    for (int i = s + tid; i < e; i += 256) m = fmaxf(m, att[i]);
    red[tid] = m; __syncthreads();
    for (int o = 128; o > 0; o >>= 1) { if (tid < o) red[tid] = fmaxf(red[tid], red[tid + o]); __syncthreads(); }
    m = red[0]; __syncthreads();
    float zs = 0.f;
    for (int i = s + tid; i < e; i += 256) zs += __expf(att[i] - m);
    red[tid] = zs; __syncthreads();
    for (int o = 128; o > 0; o >>= 1) { if (tid < o) red[tid] += red[tid + o]; __syncthreads(); }
    float inv = 1.f / red[0];
    for (int i = s + tid; i < e; i += 256) w[i] = __expf(att[i] - m) * inv;
}

__global__ void k_reduce(const float* __restrict__ w, const bf16* __restrict__ fs,
                         const bf16* __restrict__ fv, const float* __restrict__ pos,
                         const int* __restrict__ start, int B, int Nn, float* __restrict__ out) {
    int b = blockIdx.x, j = threadIdx.x;
    int s = start[b], e = start[b + 1];
    size_t P = (size_t)Nn * 64, PV = 3 * P;
    const bf16* fsl = fs + (size_t)Nn * 256;
    int c = j / 3, d = j - c * 3;
    float a256 = 0.f, a192 = 0.f, a3 = 0.f;
    for (int i = s; i < e; i++) {
        float wi = w[i];
        size_t q = (size_t)i * 256 + j;
        a256 = fmaf(wi, join2(fs[q], fsl[q]), a256);
        if (j < 192) {
            size_t qv = (size_t)d * P + (size_t)i * 64 + c;
            a192 = fmaf(wi, join2(fv[qv], fv[PV + qv]), a192);
        }
        if (j < 3) a3 = fmaf(wi, pos[(size_t)i * 3 + j], a3);
    }
    out[(size_t)b * 256 + j] = a256;
    if (j < 192) out[(size_t)B * 256 + (size_t)b * 192 + j] = a192;
    if (j < 3)   out[(size_t)B * 256 + (size_t)B * 192 + (size_t)b * 3 + j] = a3;
}

// ---------------------------------------------------------------------------
extern "C" void kernel_launch(void* const* d_in, const int* in_sizes, int n_in,
                              void* d_out, int out_size) {
    const float* h_sca = (const float*)d_in[0];
    const float* h_vec = (const float*)d_in[1];
    const float* pos   = (const float*)d_in[2];
    const float* te    = (const float*)d_in[3];
    const float* W[26];
    for (int i = 4; i <= 25; i++) W[i] = (const float*)d_in[i];
    const int* tptr = (const int*)d_in[26];
    const int* bid  = (const int*)d_in[27];

    int n = in_sizes[0] / 256;
    int B = out_size / 451;

    bf16 *vecS, *viAs, *viNs, *uas, *uns, *vas, *vns, *scaX, *lrS, *Sas, *Sns;
    bf16 *nA1, *nN1, *nA2, *nN2, *Baug;
    float *Ga, *Gn, *att, *wgt;
    int* segs;
    cudaGetSymbolAddress((void**)&vecS, g_vecS);
    cudaGetSymbolAddress((void**)&viAs, g_viAs);
    cudaGetSymbolAddress((void**)&viNs, g_viNs);
    cudaGetSymbolAddress((void**)&uas,  g_uas);
    cudaGetSymbolAddress((void**)&uns,  g_uns);
    cudaGetSymbolAddress((void**)&vas,  g_vas);
    cudaGetSymbolAddress((void**)&vns,  g_vns);
    cudaGetSymbolAddress((void**)&scaX, g_scaX);
    cudaGetSymbolAddress((void**)&lrS,  g_lrS);
    cudaGetSymbolAddress((void**)&Sas,  g_Sas);
    cudaGetSymbolAddress((void**)&Sns,  g_Sns);
    cudaGetSymbolAddress((void**)&nA1,  g_nA1);
    cudaGetSymbolAddress((void**)&nN1,  g_nN1);
    cudaGetSymbolAddress((void**)&nA2,  g_nA2);
    cudaGetSymbolAddress((void**)&nN2,  g_nN2);
    cudaGetSymbolAddress((void**)&Baug, g_Baug);
    cudaGetSymbolAddress((void**)&Ga,   g_Ga);
    cudaGetSymbolAddress((void**)&Gn,   g_Gn);
    cudaGetSymbolAddress((void**)&att,  g_att);
    cudaGetSymbolAddress((void**)&wgt,  g_w);
    cudaGetSymbolAddress((void**)&segs, g_seg);

    static const int widx[15] = {4,15, 6,17, 7,18, 5,16, 9,20, 10,21, 23,24,22};
    static const int wnc[15]  = {64,64, 256,256, 64,64, 64,64, 64,64, 64,64, 256,64,64};
    static const int wk[15]   = {64,64, 320,320, 256,256, 64,64, 64,64, 64,64, 320,256,64};
    PPargs pa;
    size_t boff[15]; size_t acc = 0;
    for (int i = 0; i < 15; i++) {
        boff[i] = acc;
        pa.e[i] = PPk{W[widx[i]], Baug + acc, wnc[i], wk[i]};
        acc += (size_t)wnc[i] * 2 * wk[i];
    }
    const bf16 *B_a1Wv1 = Baug + boff[0],  *B_n1Wv1 = Baug + boff[1];
    const bf16 *B_a1Ws  = Baug + boff[2],  *B_n1Ws  = Baug + boff[3];
    const bf16 *B_a1Wg  = Baug + boff[4],  *B_n1Wg  = Baug + boff[5];
    const bf16 *B_a1Wv2 = Baug + boff[6],  *B_n1Wv2 = Baug + boff[7];
    const bf16 *B_a1Wd  = Baug + boff[8],  *B_n1Wd  = Baug + boff[9];
    const bf16 *B_a2Wv1 = Baug + boff[10], *B_n2Wv1 = Baug + boff[11];
    const bf16 *B_n2Ws  = Baug + boff[12], *B_n2Wg  = Baug + boff[13];
    const bf16 *B_n2Wv2 = Baug + boff[14];

    size_t PV = (size_t)3 * n * 64;
    size_t H64 = (size_t)n * 64, H256 = (size_t)n * 256;
    int M3 = 3 * n;
    int gv = (n + 127) / 128;
    int g3 = (M3 + 127) / 128;

    constexpr int SM64  = (2 * 128 * 40 + 4 * 64 * 40) * 2;
    constexpr int SM256 = (2 * 128 * 40 + 4 * 256 * 40) * 2;
    cudaFuncSetAttribute((const void*)gemm_bf16<64>,
                         cudaFuncAttributeMaxDynamicSharedMemorySize, SM64);
    cudaFuncSetAttribute((const void*)gemm_bf16<256>,
                         cudaFuncAttributeMaxDynamicSharedMemorySize, SM256);

    auto GS = [](const bf16* a1h, const bf16* a1l, const bf16* a2h, const bf16* a2l, int K1,
                 const bf16* b, float* cf, bf16* ch, bf16* cl, bf16* lh, bf16* ll,
                 const float* bias, const float* gate, int act) {
        GSet g; g.A1h = a1h; g.A1l = a1l; g.A2h = a2h; g.A2l = a2l; g.K1 = K1;
        g.B = b; g.Cf = cf; g.Chi = ch; g.Clo = cl; g.Lhi = lh; g.Llo = ll;
        g.bias = bias; g.gate = gate; g.act = act; return g;
    };
    auto VS = [](const bf16* ah, const bf16* al, const bf16* b,
                 const bf16* uh, const bf16* ul, bf16* ch, bf16* cl, bf16* nh, bf16* nl) {
        VSet v; v.Ahi = ah; v.Alo = al; v.B = b; v.Uhi = uh; v.Ulo = ul;
        v.Chi = ch; v.Clo = cl; v.Nhi = nh; v.Nlo = nl; return v;
    };

    k_prepack<<<dim3(64, 15), 256>>>(pa);
    k_prep<<<(n * 128 + 255) / 256, 256>>>(h_vec, h_sca, te, tptr, vecS, scaX, n);

    // vi pair: planes + norms
    gemm_vn3<<<dim3(gv, 2), 256>>>(
        VS(vecS, vecS + PV, B_a1Wv1, nullptr, nullptr, viAs, viAs + PV, nA1, nA1 + H64),
        VS(vecS, vecS + PV, B_n1Wv1, nullptr, nullptr, viNs, viNs + PV, nN1, nN1 + H64), n);
    // S pair: A = (norms | sca shared);  net side also emits lrelu(Sn)
    gemm_bf16<256><<<dim3(gv, 2), 512, SM256>>>(
        GS(nA1, nA1 + H64, scaX, scaX + H256, 64, B_a1Ws,
           nullptr, Sas, Sas + H256, nullptr, nullptr, nullptr, nullptr, 0),
        GS(nN1, nN1 + H64, scaX, scaX + H256, 64, B_n1Ws,
           nullptr, Sns, Sns + H256, lrS, lrS + H256, nullptr, nullptr, 0),
        n, 320, n);
    // gates pair
    gemm_bf16<64><<<dim3(gv, 2), 256, SM64>>>(
        GS(Sas, Sas + H256, nullptr, nullptr, 256, B_a1Wg,
           Ga, nullptr, nullptr, nullptr, nullptr, W[8], nullptr, 1),
        GS(Sns, Sns + H256, nullptr, nullptr, 256, B_n1Wg,
           Gn, nullptr, nullptr, nullptr, nullptr, W[19], nullptr, 1),
        n, 256, n);
    // u pair (per-plane rows M3, gated)
    gemm_bf16<64><<<dim3(g3, 2), 256, SM64>>>(
        GS(viAs, viAs + PV, nullptr, nullptr, 64, B_a1Wv2,
           nullptr, uas, uas + PV, nullptr, nullptr, nullptr, Ga, 0),
        GS(viNs, viNs + PV, nullptr, nullptr, 64, B_n1Wv2,
           nullptr, uns, uns + PV, nullptr, nullptr, nullptr, Gn, 0),
        M3, 64, n);
    // d pair with fused vn_lrelu -> v
    gemm_vn3<<<dim3(gv, 2), 256>>>(
        VS(uas, uas + PV, B_a1Wd, uas, uas + PV, vas, vas + PV, nullptr, nullptr),
        VS(uns, uns + PV, B_n1Wd, uns, uns + PV, vns, vns + PV, nullptr, nullptr), n);
    // vi2 pair: att -> norms only; net -> vi2n planes + norms
    gemm_vn3<<<dim3(gv, 2), 256>>>(
        VS(vas, vas + PV, B_a2Wv1, nullptr, nullptr, nullptr, nullptr, nA2, nA2 + H64),
        VS(vns, vns + PV, B_n2Wv1, nullptr, nullptr, viAs, viAs + PV, nN2, nN2 + H64), n);
    k_att<<<(n + 7) / 8, 256>>>(nA2, Sas, W[12], att, n);

    // fs = (norms2 | lrelu(Sn)) @ n2Ws  -> Sas reuse
    {
        GSet g = GS(nN2, nN2 + H64, lrS, lrS + H256, 64, B_n2Ws,
                    nullptr, Sas, Sas + H256, nullptr, nullptr, nullptr, nullptr, 0);
        gemm_bf16<256><<<dim3(gv, 1), 512, SM256>>>(g, g, n, 320, n);
    }
    // gate2 -> Ga reuse
    {
        GSet g = GS(Sas, Sas + H256, nullptr, nullptr, 256, B_n2Wg,
                    Ga, nullptr, nullptr, nullptr, nullptr, W[25], nullptr, 1);
        gemm_bf16<64><<<dim3(gv, 1), 256, SM64>>>(g, g, n, 256, n);
    }
    // fv = gate2 * (n2Wv2 @ vi2n) -> vas reuse
    {
        GSet g = GS(viAs, viAs + PV, nullptr, nullptr, 64, B_n2Wv2,
                    nullptr, vas, vas + PV, nullptr, nullptr, nullptr, Ga, 0);
        gemm_bf16<64><<<dim3(g3, 1), 256, SM64>>>(g, g, M3, 64, n);
    }

    k_segstart<<<(B + 1 + 255) / 256, 256>>>(bid, n, B, segs);
    k_softmax<<<B, 256>>>(att, segs, wgt);
    k_reduce<<<B, 256>>>(wgt, Sas, vas, pos, segs, B, n, (float*)d_out);
}

// round 10
// speedup vs baseline: 1.0507x; 1.0507x over previous
#include <cuda_runtime.h>
#include <cuda_bf16.h>
#include <math.h>
#include <stdint.h>

typedef __nv_bfloat16 bf16;
typedef __nv_bfloat162 bf162;

#define MAXN   120000
#define SLOPEF 0.01f
#define EPSF   1e-6f
#define PVMAX  (3*MAXN*64)

// ---------------- static device scratch (bf16 split: [hi | lo]) -------------
__device__ __align__(16) bf16  g_vecS[2*PVMAX];
__device__ __align__(16) bf16  g_viAs[2*PVMAX];
__device__ __align__(16) bf16  g_viNs[2*PVMAX];   // later: vi2n
__device__ __align__(16) bf16  g_uas [2*PVMAX];
__device__ __align__(16) bf16  g_uns [2*PVMAX];
__device__ __align__(16) bf16  g_vas [2*PVMAX];   // later: fv
__device__ __align__(16) bf16  g_vns [2*PVMAX];
__device__ __align__(16) bf16  g_scaX[2*MAXN*256];
__device__ __align__(16) bf16  g_lrS [2*MAXN*256];
__device__ __align__(16) bf16  g_Sas [2*MAXN*256]; // later: fs
__device__ __align__(16) bf16  g_Sns [2*MAXN*256];
__device__ __align__(16) bf16  g_nA1 [2*MAXN*64];
__device__ __align__(16) bf16  g_nN1 [2*MAXN*64];
__device__ __align__(16) bf16  g_nA2 [2*MAXN*64];
__device__ __align__(16) bf16  g_nN2 [2*MAXN*64];
__device__ __align__(16) bf16  g_Baug[1048576];
__device__ float g_Ga  [MAXN*64];
__device__ float g_Gn  [MAXN*64];
__device__ float g_att [MAXN];
__device__ float g_w   [MAXN];
__device__ int   g_seg [4100];

// ---------------- helpers ----------------
__device__ __forceinline__ uint32_t smem_u32(const void* p) {
    return (uint32_t)__cvta_generic_to_shared(p);
}
__device__ __forceinline__ void split2(float x, bf16& h, bf16& l) {
    h = __float2bfloat16(x);
    l = __float2bfloat16(x - __bfloat162float(h));
}
__device__ __forceinline__ float join2(bf16 h, bf16 l) {
    return __bfloat162float(h) + __bfloat162float(l);
}
__device__ __forceinline__ void store_split2(bf16* H, bf16* L, size_t o, float v0, float v1) {
    bf16 h0, l0, h1, l1;
    split2(v0, h0, l0); split2(v1, h1, l1);
    bf162 th; th.x = h0; th.y = h1;
    bf162 tl; tl.x = l0; tl.y = l1;
    *(bf162*)(H + o) = th;
    *(bf162*)(L + o) = tl;
}

#define MMA16816(d, a, b)                                                     \
    asm volatile("mma.sync.aligned.m16n8k16.row.col.f32.bf16.bf16.f32 "      \
        "{%0,%1,%2,%3}, {%4,%5,%6,%7}, {%8,%9}, {%0,%1,%2,%3};"              \
        : "+f"((d)[0]), "+f"((d)[1]), "+f"((d)[2]), "+f"((d)[3])             \
        : "r"((a)[0]), "r"((a)[1]), "r"((a)[2]), "r"((a)[3]),                \
          "r"((b)[0]), "r"((b)[1]))

#define LDSM_X4(r0, r1, r2, r3, addr)                                        \
    asm volatile("ldmatrix.sync.aligned.m8n8.x4.shared.b16 {%0,%1,%2,%3}, [%4];" \
        : "=r"(r0), "=r"(r1), "=r"(r2), "=r"(r3) : "r"(addr))

#define CP_ASYNC16(sa, ga)                                                   \
    asm volatile("cp.async.cg.shared.global [%0], [%1], 16;" :: "r"(sa), "l"(ga))
#define CP_ASYNC16_P(sa, ga, p)                                              \
    asm volatile("cp.async.cg.shared.global [%0], [%1], 16, %2;" :: "r"(sa), "l"(ga), "r"(p))
#define CP_COMMIT() asm volatile("cp.async.commit_group;")
#define CP_WAIT0()  asm volatile("cp.async.wait_group 0;")

// ---------------------------------------------------------------------------
// generic HMMA GEMM with two A regions: cols [0,K1) from A1, [K1,K) from A2
// C[M, NCfull] tile (128 x NC) at column offset blockIdx.z*NC.
// B prepacked [NCfull][hi K | lo K].
// NC=128: 512 thr (16 warps 4x4, warp 32x32), minBlocks 2 -> 32 warps/SM.
// NC=64:  256 thr (8 warps 4x2,  warp 32x32), minBlocks 3 -> 24 warps/SM.
// ---------------------------------------------------------------------------
struct GSet {
    const bf16 *A1h, *A1l, *A2h, *A2l;
    int K1;
    const bf16* B;
    float* Cf; bf16 *Chi, *Clo;
    bf16 *Lhi, *Llo;                 // optional lrelu split side-output
    const float *bias, *gate;
    int act;
};

template <int NC>
__global__ void __launch_bounds__(NC >= 128 ? 512 : 256, NC >= 128 ? 2 : 3)
gemm_bf16(GSet s0, GSet s1, int M, int K, int Nn, int NCfull) {
    constexpr int NTH   = (NC >= 128) ? 512 : 256;
    constexpr int NWN   = (NC >= 128) ? 4 : 2;
    constexpr int WCOLS = NC / NWN;          // 32
    constexpr int NT    = WCOLS / 8;         // 4
    constexpr int A_ST  = 128 * 40;
    constexpr int B_ST  = NC * 40;

    extern __shared__ bf16 sm[];
    bf16* smA = sm;
    bf16* smB = sm + 2 * A_ST;

    const int tid = threadIdx.x;
    const int lane = tid & 31, wid = tid >> 5;
    const int wm = wid / NWN, wn = wid % NWN;
    const GSet S = (blockIdx.y == 0) ? s0 : s1;
    const int m0 = blockIdx.x * 128;
    const int n0 = blockIdx.z * NC;
    const int KC = K >> 5;
    const int ST = 2 * KC;
    const size_t K2 = (size_t)2 * K;
    const int K2w = K - S.K1;

    float acc[2][NT][4];
#pragma unroll
    for (int i = 0; i < 2; i++)
#pragma unroll
        for (int j = 0; j < NT; j++)
#pragma unroll
            for (int k = 0; k < 4; k++) acc[i][j][k] = 0.f;

    auto load_stage = [&](int s, int buf) {
        bool hp = (s < KC);
        int kc = hp ? s : s - KC;
        int kof = kc * 32;
        const bf16* base; int stride, col;
        if (kof < S.K1) { base = hp ? S.A1h : S.A1l; stride = S.K1; col = kof; }
        else            { base = hp ? S.A2h : S.A2l; stride = K2w;  col = kof - S.K1; }
        for (int i = tid; i < 512; i += NTH) {
            int r = i >> 2, sg = i & 3;
            int m = m0 + r;
            uint32_t sa = smem_u32(smA + buf * A_ST + r * 40 + sg * 8);
            const bf16* ga = base + ((m < M) ? ((size_t)m * stride + col + sg * 8) : 0);
            CP_ASYNC16_P(sa, ga, (m < M) ? 16 : 0);
        }
        int c0 = kc * 32;
        for (int i = tid; i < NC * 4; i += NTH) {
            int r = i >> 2, sg = i & 3;
            uint32_t sa = smem_u32(smB + (buf * 2 + 0) * B_ST + r * 40 + sg * 8);
            CP_ASYNC16(sa, S.B + (size_t)(n0 + r) * K2 + c0 + sg * 8);
        }
        if (hp) {
            int c1 = K + kc * 32;
            for (int i = tid; i < NC * 4; i += NTH) {
                int r = i >> 2, sg = i & 3;
                uint32_t sa = smem_u32(smB + (buf * 2 + 1) * B_ST + r * 40 + sg * 8);
                CP_ASYNC16(sa, S.B + (size_t)(n0 + r) * K2 + c1 + sg * 8);
            }
        }
        CP_COMMIT();
    };

    load_stage(0, 0);
    for (int s = 0; s < ST; s++) {
        int buf = s & 1;
        CP_WAIT0();
        __syncthreads();
        if (s + 1 < ST) load_stage(s + 1, buf ^ 1);
        const bool dual = (s < KC);
#pragma unroll
        for (int kk = 0; kk < 2; kk++) {
            const int k16 = kk * 16;
            uint32_t a[2][4];
#pragma unroll
            for (int mt = 0; mt < 2; mt++) {
                uint32_t ad = smem_u32(smA + buf * A_ST
                                       + (wm * 32 + mt * 16 + (lane & 15)) * 40
                                       + k16 + (lane >> 4) * 8);
                LDSM_X4(a[mt][0], a[mt][1], a[mt][2], a[mt][3], ad);
            }
#pragma unroll
            for (int sub = 0; sub < 2; sub++) {
                if (sub == 1 && !dual) break;
                uint32_t b[NT][2];
#pragma unroll
                for (int half = 0; half < NT / 2; half++) {
                    int g = lane >> 3, r = lane & 7;
                    int nt8 = (g >> 1), ko = (g & 1) * 8;
                    uint32_t ad = smem_u32(smB + (buf * 2 + sub) * B_ST
                                           + (wn * WCOLS + half * 16 + nt8 * 8 + r) * 40
                                           + k16 + ko);
                    uint32_t r0, r1, r2, r3;
                    LDSM_X4(r0, r1, r2, r3, ad);
                    b[half * 2 + 0][0] = r0; b[half * 2 + 0][1] = r1;
                    b[half * 2 + 1][0] = r2; b[half * 2 + 1][1] = r3;
                }
#pragma unroll
                for (int mt = 0; mt < 2; mt++)
#pragma unroll
                    for (int nt = 0; nt < NT; nt++)
                        MMA16816(acc[mt][nt], a[mt], b[nt]);
            }
        }
    }

#pragma unroll
    for (int mt = 0; mt < 2; mt++) {
#pragma unroll
        for (int hh = 0; hh < 2; hh++) {
            int m = m0 + wm * 32 + mt * 16 + (lane >> 2) + hh * 8;
            if (m >= M) continue;
            int node = m % Nn;
#pragma unroll
            for (int nt = 0; nt < NT; nt++) {
                int col = n0 + wn * WCOLS + nt * 8 + (lane & 3) * 2;
                float v0 = acc[mt][nt][hh * 2 + 0];
                float v1 = acc[mt][nt][hh * 2 + 1];
                if (S.act) {
                    v0 = 1.f / (1.f + __expf(-(v0 + S.bias[col])));
                    v1 = 1.f / (1.f + __expf(-(v1 + S.bias[col + 1])));
                }
                if (S.gate) {
                    v0 *= S.gate[(size_t)node * 64 + col];
                    v1 *= S.gate[(size_t)node * 64 + col + 1];
                }
                size_t o = (size_t)m * NCfull + col;
                if (S.Cf) *(float2*)(S.Cf + o) = make_float2(v0, v1);
                if (S.Chi) store_split2(S.Chi, S.Clo, o, v0, v1);
                if (S.Lhi) {
                    float l0 = (v0 >= 0.f) ? v0 : SLOPEF * v0;
                    float l1 = (v1 >= 0.f) ? v1 : SLOPEF * v1;
                    store_split2(S.Lhi, S.Llo, o, l0, l1);
                }
            }
        }
    }
}

// ---------------------------------------------------------------------------
// 3-plane VN GEMM (K=64, NC=64): one block = 128 nodes x 64 cols, loops d=0..2
// with B resident in smem. 512 threads, 16 warps (8M x 2N), warp tile 16x32.
// Epilogue holds all 3 components per (node, chan):
//   - optional vn_lrelu against u, optional plane outputs, optional norms.
// ---------------------------------------------------------------------------
struct VSet {
    const bf16 *Ahi, *Alo;      // planes [d][n][64]
    const bf16 *B;              // [64][128]  (hi 64 | lo 64)
    const bf16 *Uhi, *Ulo;      // vn_lrelu input planes (or null)
    bf16 *Chi, *Clo;            // plane outputs (or null)
    bf16 *Nhi, *Nlo;            // norm outputs [n,64] (or null)
};

__global__ void __launch_bounds__(512)
gemm_vn3(VSet s0, VSet s1, int Nn) {
    __shared__ bf16 Bs[64 * 136];
    __shared__ bf16 As[2][128 * 40];
    const int tid = threadIdx.x, lane = tid & 31, wid = tid >> 5;
    const int wm = wid >> 1, wn = wid & 1;       // 8 x 2
    const VSet S = blockIdx.y ? s1 : s0;
    const int m0 = blockIdx.x * 128;
    const size_t P = (size_t)Nn * 64;

    // B resident: 64 rows x 128 bf16 = 16 x 16B per row
    for (int i = tid; i < 1024; i += 512) {
        int r = i >> 4, c8 = i & 15;
        CP_ASYNC16(smem_u32(Bs + r * 136 + c8 * 8), S.B + r * 128 + c8 * 8);
    }
    CP_COMMIT();

    float acc[3][4][4];
#pragma unroll
    for (int d = 0; d < 3; d++)
#pragma unroll
        for (int j = 0; j < 4; j++)
#pragma unroll
            for (int k = 0; k < 4; k++) acc[d][j][k] = 0.f;

    auto loadA = [&](int gs, int buf) {
        int d = gs >> 2, s = gs & 3;
        const bf16* Ab = (s < 2) ? S.Ahi : S.Alo;
        int kof = (s & 1) * 32;
        {
            int i = tid;          // exactly 512 chunks
            int r = i >> 2, sg = i & 3;
            int m = m0 + r;
            uint32_t sa = smem_u32(As[buf] + r * 40 + sg * 8);
            const bf16* ga = Ab + d * P + ((m < Nn) ? ((size_t)m * 64 + kof + sg * 8) : 0);
            CP_ASYNC16_P(sa, ga, (m < Nn) ? 16 : 0);
        }
        CP_COMMIT();
    };

    loadA(0, 0);
    for (int gs = 0; gs < 12; gs++) {
        int buf = gs & 1;
        CP_WAIT0();
        __syncthreads();
        if (gs + 1 < 12) loadA(gs + 1, buf ^ 1);
        int d = gs >> 2, s = gs & 3;
        bool dual = (s < 2);
        int kc = s & 1;
#pragma unroll
        for (int kk = 0; kk < 2; kk++) {
            const int k16 = kk * 16;
            uint32_t a[4];
            {
                uint32_t ad = smem_u32(As[buf] + (wm * 16 + (lane & 15)) * 40
                                       + k16 + (lane >> 4) * 8);
                LDSM_X4(a[0], a[1], a[2], a[3], ad);
            }
#pragma unroll
            for (int sub = 0; sub < 2; sub++) {
                if (sub == 1 && !dual) break;
                int bcol = sub * 64 + kc * 32;
                uint32_t b[4][2];
                {
                    int g = lane >> 3, r = lane & 7;
                    int nt8 = (g >> 1), ko = (g & 1) * 8;
#pragma unroll
                    for (int half = 0; half < 2; half++) {
                        uint32_t ad = smem_u32(Bs + (wn * 32 + half * 16 + nt8 * 8 + r) * 136
                                               + bcol + k16 + ko);
                        uint32_t r0, r1, r2, r3;
                        LDSM_X4(r0, r1, r2, r3, ad);
                        b[half * 2 + 0][0] = r0; b[half * 2 + 0][1] = r1;
                        b[half * 2 + 1][0] = r2; b[half * 2 + 1][1] = r3;
                    }
                }
#pragma unroll
                for (int nt = 0; nt < 4; nt++)
                    MMA16816(acc[d][nt], a, b[nt]);
            }
        }
    }

    // -------- fused epilogue --------
#pragma unroll
    for (int hh = 0; hh < 2; hh++) {
        int m = m0 + wm * 16 + (lane >> 2) + hh * 8;
        if (m >= Nn) continue;
#pragma unroll
        for (int nt = 0; nt < 4; nt++) {
            int col = wn * 32 + nt * 8 + (lane & 3) * 2;
            float v[3][2];
#pragma unroll
            for (int d = 0; d < 3; d++) {
                v[d][0] = acc[d][nt][hh * 2 + 0];
                v[d][1] = acc[d][nt][hh * 2 + 1];
            }
            if (S.Uhi) {
                float u[3][2];
#pragma unroll
                for (int d = 0; d < 3; d++) {
                    size_t q = d * P + (size_t)m * 64 + col;
                    bf162 uh = *(const bf162*)(S.Uhi + q);
                    bf162 ul = *(const bf162*)(S.Ulo + q);
                    u[d][0] = join2(uh.x, ul.x);
                    u[d][1] = join2(uh.y, ul.y);
                }
#pragma unroll
                for (int e = 0; e < 2; e++) {
                    float dot = u[0][e] * v[0][e] + u[1][e] * v[1][e] + u[2][e] * v[2][e];
                    float dsq = v[0][e] * v[0][e] + v[1][e] * v[1][e] + v[2][e] * v[2][e];
                    float sc = dot / (dsq + EPSF);
#pragma unroll
                    for (int d = 0; d < 3; d++) {
                        float x = u[d][e];
                        float r = (dot >= 0.f) ? x
                                 : (SLOPEF * x + (1.f - SLOPEF) * (x - sc * v[d][e]));
                        v[d][e] = r;
                    }
                }
            }
            if (S.Chi) {
#pragma unroll
                for (int d = 0; d < 3; d++)
                    store_split2(S.Chi, S.Clo, d * P + (size_t)m * 64 + col, v[d][0], v[d][1]);
            }
            if (S.Nhi) {
                float n0 = sqrtf(v[0][0] * v[0][0] + v[1][0] * v[1][0] + v[2][0] * v[2][0]);
                float n1 = sqrtf(v[0][1] * v[0][1] + v[1][1] * v[1][1] + v[2][1] * v[2][1]);
                store_split2(S.Nhi, S.Nlo, (size_t)m * 64 + col, n0, n1);
            }
        }
    }
}

// ---------------------------------------------------------------------------
// weight prepack: W(nc,k) fp32 -> Baug(nc,2k) bf16 rows [hi | lo]
// ---------------------------------------------------------------------------
struct PPk { const float* w; bf16* o; int nc; int k; };
struct PPargs { PPk e[15]; };
__global__ void k_prepack(PPargs pa) {
    PPk p = pa.e[blockIdx.y];
    int tot = p.nc * p.k;
    for (int i = blockIdx.x * 256 + threadIdx.x; i < tot; i += gridDim.x * 256) {
        float x = p.w[i];
        bf16 h, l; split2(x, h, l);
        int r = i / p.k, kk = i - r * p.k;
        bf16* row = p.o + (size_t)r * 2 * p.k;
        row[kk] = h; row[p.k + kk] = l;
    }
}

// ---------------------------------------------------------------------------
// prep: vec -> split planes; sca = h_sca + te[t] -> shared split [n,256]
// ---------------------------------------------------------------------------
__global__ void k_prep(const float* __restrict__ h_vec, const float* __restrict__ h_sca,
                       const float* __restrict__ te, const int* __restrict__ tptr,
                       bf16* __restrict__ vhi, bf16* __restrict__ scah, int Nn) {
    size_t PV = (size_t)3 * Nn * 64;
    bf16* vlo = vhi + PV;
    bf16* scal = scah + (size_t)Nn * 256;
    int i = blockIdx.x * 256 + threadIdx.x;
    int half = Nn * 64;
    if (i < half) {
        int node = i >> 6, c = i & 63;
#pragma unroll
        for (int d = 0; d < 3; d++) {
            float x = h_vec[(size_t)node * 192 + c * 3 + d];
            bf16 h, l; split2(x, h, l);
            size_t o = (size_t)d * Nn * 64 + (size_t)node * 64 + c;
            vhi[o] = h; vlo[o] = l;
        }
    } else if (i < 2 * half) {
        int j = i - half;
        int node = j >> 6, q4 = (j & 63) * 4;
        int t = *tptr;
        float4 hs = *(const float4*)(h_sca + (size_t)node * 256 + q4);
        float4 tv = *(const float4*)(te + (size_t)t * 256 + q4);
        size_t o = (size_t)node * 256 + q4;
        store_split2(scah, scal, o,     hs.x + tv.x, hs.y + tv.y);
        store_split2(scah, scal, o + 2, hs.z + tv.z, hs.w + tv.w);
    }
}

// att[n] = Ws[0:64].|vi2a| + Ws[64:320].lrelu(Sa)
__global__ void k_att(const bf16* __restrict__ Nh, const bf16* __restrict__ Sa,
                      const float* __restrict__ Ws, float* __restrict__ att, int Nn) {
    __shared__ float ws[320];
    int tid = threadIdx.x, w = tid >> 5, lane = tid & 31;
    for (int i = tid; i < 320; i += 256) ws[i] = Ws[i];
    __syncthreads();
    int node = blockIdx.x * 8 + w;
    if (node >= Nn) return;
    const bf16* Nl = Nh + (size_t)Nn * 64;
    const bf16* Sal = Sa + (size_t)Nn * 256;
    float p = 0.f;
    for (int c = lane; c < 64; c += 32) {
        size_t q = (size_t)node * 64 + c;
        p = fmaf(ws[c], join2(Nh[q], Nl[q]), p);
    }
    for (int k = lane; k < 256; k += 32) {
        size_t q = (size_t)node * 256 + k;
        float sv = join2(Sa[q], Sal[q]);
        sv = (sv >= 0.f) ? sv : SLOPEF * sv;
        p = fmaf(ws[64 + k], sv, p);
    }
#pragma unroll
    for (int o = 16; o > 0; o >>= 1) p += __shfl_down_sync(0xffffffff, p, o);
    if (lane == 0) att[node] = p;
}

__global__ void k_segstart(const int* __restrict__ bid, int n, int B, int* __restrict__ start) {
    int b = blockIdx.x * blockDim.x + threadIdx.x;
    if (b > B) return;
    int lo = 0, hi = n;
    while (lo < hi) { int mid = (lo + hi) >> 1; if (bid[mid] < b) lo = mid + 1; else hi = mid; }
    start[b] = lo;
}

__global__ void k_softmax(const float* __restrict__ att, const int* __restrict__ start,
                          float* __restrict__ w) {
    int b = blockIdx.x;
    int s = start[b], e = start[b + 1];
    if (s >= e) return;
    __shared__ float red[256];
    int tid = threadIdx.x;
    float m = -INFINITY;
    for (int i = s + tid; i < e; i += 256) m = fmaxf(m, att[i]);
    red[tid] = m; __syncthreads();
    for (int o = 128; o > 0; o >>= 1) { if (tid < o) red[tid] = fmaxf(red[tid], red[tid + o]); __syncthreads(); }
    m = red[0]; __syncthreads();
    float zs = 0.f;
    for (int i = s + tid; i < e; i += 256) zs += __expf(att[i] - m);
    red[tid] = zs; __syncthreads();
    for (int o = 128; o > 0; o >>= 1) { if (tid < o) red[tid] += red[tid + o]; __syncthreads(); }
    float inv = 1.f / red[0];
    for (int i = s + tid; i < e; i += 256) w[i] = __expf(att[i] - m) * inv;
}

__global__ void k_reduce(const float* __restrict__ w, const bf16* __restrict__ fs,
                         const bf16* __restrict__ fv, const float* __restrict__ pos,
                         const int* __restrict__ start, int B, int Nn, float* __restrict__ out) {
    int b = blockIdx.x, j = threadIdx.x;
    int s = start[b], e = start[b + 1];
    size_t P = (size_t)Nn * 64, PV = 3 * P;
    const bf16* fsl = fs + (size_t)Nn * 256;
    int c = j / 3, d = j - c * 3;
    float a256 = 0.f, a192 = 0.f, a3 = 0.f;
    for (int i = s; i < e; i++) {
        float wi = w[i];
        size_t q = (size_t)i * 256 + j;
        a256 = fmaf(wi, join2(fs[q], fsl[q]), a256);
        if (j < 192) {
            size_t qv = (size_t)d * P + (size_t)i * 64 + c;
            a192 = fmaf(wi, join2(fv[qv], fv[PV + qv]), a192);
        }
        if (j < 3) a3 = fmaf(wi, pos[(size_t)i * 3 + j], a3);
    }
    out[(size_t)b * 256 + j] = a256;
    if (j < 192) out[(size_t)B * 256 + (size_t)b * 192 + j] = a192;
    if (j < 3)   out[(size_t)B * 256 + (size_t)B * 192 + (size_t)b * 3 + j] = a3;
}

// ---------------------------------------------------------------------------
extern "C" void kernel_launch(void* const* d_in, const int* in_sizes, int n_in,
                              void* d_out, int out_size) {
    const float* h_sca = (const float*)d_in[0];
    const float* h_vec = (const float*)d_in[1];
    const float* pos   = (const float*)d_in[2];
    const float* te    = (const float*)d_in[3];
    const float* W[26];
    for (int i = 4; i <= 25; i++) W[i] = (const float*)d_in[i];
    const int* tptr = (const int*)d_in[26];
    const int* bid  = (const int*)d_in[27];

    int n = in_sizes[0] / 256;
    int B = out_size / 451;

    bf16 *vecS, *viAs, *viNs, *uas, *uns, *vas, *vns, *scaX, *lrS, *Sas, *Sns;
    bf16 *nA1, *nN1, *nA2, *nN2, *Baug;
    float *Ga, *Gn, *att, *wgt;
    int* segs;
    cudaGetSymbolAddress((void**)&vecS, g_vecS);
    cudaGetSymbolAddress((void**)&viAs, g_viAs);
    cudaGetSymbolAddress((void**)&viNs, g_viNs);
    cudaGetSymbolAddress((void**)&uas,  g_uas);
    cudaGetSymbolAddress((void**)&uns,  g_uns);
    cudaGetSymbolAddress((void**)&vas,  g_vas);
    cudaGetSymbolAddress((void**)&vns,  g_vns);
    cudaGetSymbolAddress((void**)&scaX, g_scaX);
    cudaGetSymbolAddress((void**)&lrS,  g_lrS);
    cudaGetSymbolAddress((void**)&Sas,  g_Sas);
    cudaGetSymbolAddress((void**)&Sns,  g_Sns);
    cudaGetSymbolAddress((void**)&nA1,  g_nA1);
    cudaGetSymbolAddress((void**)&nN1,  g_nN1);
    cudaGetSymbolAddress((void**)&nA2,  g_nA2);
    cudaGetSymbolAddress((void**)&nN2,  g_nN2);
    cudaGetSymbolAddress((void**)&Baug, g_Baug);
    cudaGetSymbolAddress((void**)&Ga,   g_Ga);
    cudaGetSymbolAddress((void**)&Gn,   g_Gn);
    cudaGetSymbolAddress((void**)&att,  g_att);
    cudaGetSymbolAddress((void**)&wgt,  g_w);
    cudaGetSymbolAddress((void**)&segs, g_seg);

    static const int widx[15] = {4,15, 6,17, 7,18, 5,16, 9,20, 10,21, 23,24,22};
    static const int wnc[15]  = {64,64, 256,256, 64,64, 64,64, 64,64, 64,64, 256,64,64};
    static const int wk[15]   = {64,64, 320,320, 256,256, 64,64, 64,64, 64,64, 320,256,64};
    PPargs pa;
    size_t boff[15]; size_t acc = 0;
    for (int i = 0; i < 15; i++) {
        boff[i] = acc;
        pa.e[i] = PPk{W[widx[i]], Baug + acc, wnc[i], wk[i]};
        acc += (size_t)wnc[i] * 2 * wk[i];
    }
    const bf16 *B_a1Wv1 = Baug + boff[0],  *B_n1Wv1 = Baug + boff[1];
    const bf16 *B_a1Ws  = Baug + boff[2],  *B_n1Ws  = Baug + boff[3];
    const bf16 *B_a1Wg  = Baug + boff[4],  *B_n1Wg  = Baug + boff[5];
    const bf16 *B_a1Wv2 = Baug + boff[6],  *B_n1Wv2 = Baug + boff[7];
    const bf16 *B_a1Wd  = Baug + boff[8],  *B_n1Wd  = Baug + boff[9];
    const bf16 *B_a2Wv1 = Baug + boff[10], *B_n2Wv1 = Baug + boff[11];
    const bf16 *B_n2Ws  = Baug + boff[12], *B_n2Wg  = Baug + boff[13];
    const bf16 *B_n2Wv2 = Baug + boff[14];

    size_t PV = (size_t)3 * n * 64;
    size_t H64 = (size_t)n * 64, H256 = (size_t)n * 256;
    int M3 = 3 * n;
    int gv = (n + 127) / 128;
    int g3 = (M3 + 127) / 128;

    constexpr int SM64  = (2 * 128 * 40 + 4 * 64 * 40) * 2;    // 40960 B
    constexpr int SM128 = (2 * 128 * 40 + 4 * 128 * 40) * 2;   // 61440 B
    cudaFuncSetAttribute((const void*)gemm_bf16<64>,
                         cudaFuncAttributeMaxDynamicSharedMemorySize, SM64);
    cudaFuncSetAttribute((const void*)gemm_bf16<128>,
                         cudaFuncAttributeMaxDynamicSharedMemorySize, SM128);

    auto GS = [](const bf16* a1h, const bf16* a1l, const bf16* a2h, const bf16* a2l, int K1,
                 const bf16* b, float* cf, bf16* ch, bf16* cl, bf16* lh, bf16* ll,
                 const float* bias, const float* gate, int act) {
        GSet g; g.A1h = a1h; g.A1l = a1l; g.A2h = a2h; g.A2l = a2l; g.K1 = K1;
        g.B = b; g.Cf = cf; g.Chi = ch; g.Clo = cl; g.Lhi = lh; g.Llo = ll;
        g.bias = bias; g.gate = gate; g.act = act; return g;
    };
    auto VS = [](const bf16* ah, const bf16* al, const bf16* b,
                 const bf16* uh, const bf16* ul, bf16* ch, bf16* cl, bf16* nh, bf16* nl) {
        VSet v; v.Ahi = ah; v.Alo = al; v.B = b; v.Uhi = uh; v.Ulo = ul;
        v.Chi = ch; v.Clo = cl; v.Nhi = nh; v.Nlo = nl; return v;
    };

    k_prepack<<<dim3(64, 15), 256>>>(pa);
    k_prep<<<(n * 128 + 255) / 256, 256>>>(h_vec, h_sca, te, tptr, vecS, scaX, n);

    // vi pair: planes + norms
    gemm_vn3<<<dim3(gv, 2), 512>>>(
        VS(vecS, vecS + PV, B_a1Wv1, nullptr, nullptr, viAs, viAs + PV, nA1, nA1 + H64),
        VS(vecS, vecS + PV, B_n1Wv1, nullptr, nullptr, viNs, viNs + PV, nN1, nN1 + H64), n);
    // S pair: A = (norms | sca shared);  net side also emits lrelu(Sn)
    gemm_bf16<128><<<dim3(gv, 2, 2), 512, SM128>>>(
        GS(nA1, nA1 + H64, scaX, scaX + H256, 64, B_a1Ws,
           nullptr, Sas, Sas + H256, nullptr, nullptr, nullptr, nullptr, 0),
        GS(nN1, nN1 + H64, scaX, scaX + H256, 64, B_n1Ws,
           nullptr, Sns, Sns + H256, lrS, lrS + H256, nullptr, nullptr, 0),
        n, 320, n, 256);
    // gates pair
    gemm_bf16<64><<<dim3(gv, 2, 1), 256, SM64>>>(
        GS(Sas, Sas + H256, nullptr, nullptr, 256, B_a1Wg,
           Ga, nullptr, nullptr, nullptr, nullptr, W[8], nullptr, 1),
        GS(Sns, Sns + H256, nullptr, nullptr, 256, B_n1Wg,
           Gn, nullptr, nullptr, nullptr, nullptr, W[19], nullptr, 1),
        n, 256, n, 64);
    // u pair (per-plane rows M3, gated)
    gemm_bf16<64><<<dim3(g3, 2, 1), 256, SM64>>>(
        GS(viAs, viAs + PV, nullptr, nullptr, 64, B_a1Wv2,
           nullptr, uas, uas + PV, nullptr, nullptr, nullptr, Ga, 0),
        GS(viNs, viNs + PV, nullptr, nullptr, 64, B_n1Wv2,
           nullptr, uns, uns + PV, nullptr, nullptr, nullptr, Gn, 0),
        M3, 64, n, 64);
    // d pair with fused vn_lrelu -> v
    gemm_vn3<<<dim3(gv, 2), 512>>>(
        VS(uas, uas + PV, B_a1Wd, uas, uas + PV, vas, vas + PV, nullptr, nullptr),
        VS(uns, uns + PV, B_n1Wd, uns, uns + PV, vns, vns + PV, nullptr, nullptr), n);
    // vi2 pair: att -> norms only; net -> vi2n planes + norms
    gemm_vn3<<<dim3(gv, 2), 512>>>(
        VS(vas, vas + PV, B_a2Wv1, nullptr, nullptr, nullptr, nullptr, nA2, nA2 + H64),
        VS(vns, vns + PV, B_n2Wv1, nullptr, nullptr, viAs, viAs + PV, nN2, nN2 + H64), n);
    k_att<<<(n + 7) / 8, 256>>>(nA2, Sas, W[12], att, n);

    // fs = (norms2 | lrelu(Sn)) @ n2Ws  -> Sas reuse
    {
        GSet g = GS(nN2, nN2 + H64, lrS, lrS + H256, 64, B_n2Ws,
                    nullptr, Sas, Sas + H256, nullptr, nullptr, nullptr, nullptr, 0);
        gemm_bf16<128><<<dim3(gv, 1, 2), 512, SM128>>>(g, g, n, 320, n, 256);
    }
    // gate2 -> Ga reuse
    {
        GSet g = GS(Sas, Sas + H256, nullptr, nullptr, 256, B_n2Wg,
                    Ga, nullptr, nullptr, nullptr, nullptr, W[25], nullptr, 1);
        gemm_bf16<64><<<dim3(gv, 1, 1), 256, SM64>>>(g, g, n, 256, n, 64);
    }
    // fv = gate2 * (n2Wv2 @ vi2n) -> vas reuse
    {
        GSet g = GS(viAs, viAs + PV, nullptr, nullptr, 64, B_n2Wv2,
                    nullptr, vas, vas + PV, nullptr, nullptr, nullptr, Ga, 0);
        gemm_bf16<64><<<dim3(g3, 1, 1), 256, SM64>>>(g, g, M3, 64, n, 64);
    }

    k_segstart<<<(B + 1 + 255) / 256, 256>>>(bid, n, B, segs);
    k_softmax<<<B, 256>>>(att, segs, wgt);
    k_reduce<<<B, 256>>>(wgt, Sas, vas, pos, segs, B, n, (float*)d_out);
}

// round 11
// speedup vs baseline: 1.9711x; 1.8761x over previous
#include <cuda_runtime.h>
#include <cuda_fp16.h>
#include <math.h>
#include <stdint.h>

typedef __half hf;

#define MAXN   120000
#define SLOPEF 0.01f
#define EPSF   1e-6f
#define PVMAX  (3*MAXN*64)

// ---------------- static device scratch (plain fp16) ------------------------
__device__ __align__(16) hf    g_vecS[PVMAX];
__device__ __align__(16) hf    g_viAs[PVMAX];
__device__ __align__(16) hf    g_viNs[PVMAX];   // later: vi2n
__device__ __align__(16) hf    g_uas [PVMAX];
__device__ __align__(16) hf    g_uns [PVMAX];
__device__ __align__(16) hf    g_vas [PVMAX];   // later: fv
__device__ __align__(16) hf    g_vns [PVMAX];
__device__ __align__(16) hf    g_scaX[MAXN*256];
__device__ __align__(16) hf    g_lrS [MAXN*256];
__device__ __align__(16) hf    g_Sas [MAXN*256]; // later: fs
__device__ __align__(16) hf    g_Sns [MAXN*256];
__device__ __align__(16) hf    g_nA1 [MAXN*64];
__device__ __align__(16) hf    g_nN1 [MAXN*64];
__device__ __align__(16) hf    g_nA2 [MAXN*64];
__device__ __align__(16) hf    g_nN2 [MAXN*64];
__device__ __align__(16) hf    g_Baug[524288];
__device__ float g_Ga  [MAXN*64];
__device__ float g_Gn  [MAXN*64];
__device__ float g_att [MAXN];
__device__ float g_w   [MAXN];
__device__ int   g_seg [4100];

// ---------------- helpers ----------------
__device__ __forceinline__ uint32_t smem_u32(const void* p) {
    return (uint32_t)__cvta_generic_to_shared(p);
}
__device__ __forceinline__ void store_h2(hf* H, size_t o, float v0, float v1) {
    __half2 t; t.x = __float2half(v0); t.y = __float2half(v1);
    *(__half2*)(H + o) = t;
}

#define MMA16816(d, a, b)                                                     \
    asm volatile("mma.sync.aligned.m16n8k16.row.col.f32.f16.f16.f32 "        \
        "{%0,%1,%2,%3}, {%4,%5,%6,%7}, {%8,%9}, {%0,%1,%2,%3};"              \
        : "+f"((d)[0]), "+f"((d)[1]), "+f"((d)[2]), "+f"((d)[3])             \
        : "r"((a)[0]), "r"((a)[1]), "r"((a)[2]), "r"((a)[3]),                \
          "r"((b)[0]), "r"((b)[1]))

#define LDSM_X4(r0, r1, r2, r3, addr)                                        \
    asm volatile("ldmatrix.sync.aligned.m8n8.x4.shared.b16 {%0,%1,%2,%3}, [%4];" \
        : "=r"(r0), "=r"(r1), "=r"(r2), "=r"(r3) : "r"(addr))

#define CP_ASYNC16(sa, ga)                                                   \
    asm volatile("cp.async.cg.shared.global [%0], [%1], 16;" :: "r"(sa), "l"(ga))
#define CP_ASYNC16_P(sa, ga, p)                                              \
    asm volatile("cp.async.cg.shared.global [%0], [%1], 16, %2;" :: "r"(sa), "l"(ga), "r"(p))
#define CP_COMMIT() asm volatile("cp.async.commit_group;")
#define CP_WAIT0()  asm volatile("cp.async.wait_group 0;")

// ---------------------------------------------------------------------------
// fp16 HMMA GEMM with two A regions: cols [0,K1) from A1, [K1,K) from A2
// C[M, NCfull] tile (128 x NC) at column offset blockIdx.z*NC.
// B prepacked [NCfull][K] fp16.
// NC=128: 512 thr (16 warps 4x4, warp 32x32), minBlocks 2.
// NC=64:  256 thr (8 warps 4x2,  warp 32x32), minBlocks 3.
// ---------------------------------------------------------------------------
struct GSet {
    const hf *A1, *A2;
    int K1;
    const hf* B;
    float* Cf; hf* Ch;
    hf* Lh;                          // optional lrelu side-output
    const float *bias, *gate;
    int act;
};

template <int NC>
__global__ void __launch_bounds__(NC >= 128 ? 512 : 256, NC >= 128 ? 2 : 3)
gemm_f16(GSet s0, GSet s1, int M, int K, int Nn, int NCfull) {
    constexpr int NTH   = (NC >= 128) ? 512 : 256;
    constexpr int NWN   = (NC >= 128) ? 4 : 2;
    constexpr int WCOLS = NC / NWN;          // 32
    constexpr int NT    = WCOLS / 8;         // 4
    constexpr int A_ST  = 128 * 40;
    constexpr int B_ST  = NC * 40;

    extern __shared__ hf sm[];
    hf* smA = sm;
    hf* smB = sm + 2 * A_ST;

    const int tid = threadIdx.x;
    const int lane = tid & 31, wid = tid >> 5;
    const int wm = wid / NWN, wn = wid % NWN;
    const GSet S = (blockIdx.y == 0) ? s0 : s1;
    const int m0 = blockIdx.x * 128;
    const int n0 = blockIdx.z * NC;
    const int ST = K >> 5;
    const int K2w = K - S.K1;

    float acc[2][NT][4];
#pragma unroll
    for (int i = 0; i < 2; i++)
#pragma unroll
        for (int j = 0; j < NT; j++)
#pragma unroll
            for (int k = 0; k < 4; k++) acc[i][j][k] = 0.f;

    auto load_stage = [&](int s, int buf) {
        int kof = s * 32;
        const hf* base; int stride, col;
        if (kof < S.K1) { base = S.A1; stride = S.K1; col = kof; }
        else            { base = S.A2; stride = K2w;  col = kof - S.K1; }
        for (int i = tid; i < 512; i += NTH) {
            int r = i >> 2, sg = i & 3;
            int m = m0 + r;
            uint32_t sa = smem_u32(smA + buf * A_ST + r * 40 + sg * 8);
            const hf* ga = base + ((m < M) ? ((size_t)m * stride + col + sg * 8) : 0);
            CP_ASYNC16_P(sa, ga, (m < M) ? 16 : 0);
        }
        for (int i = tid; i < NC * 4; i += NTH) {
            int r = i >> 2, sg = i & 3;
            uint32_t sa = smem_u32(smB + buf * B_ST + r * 40 + sg * 8);
            CP_ASYNC16(sa, S.B + (size_t)(n0 + r) * K + kof + sg * 8);
        }
        CP_COMMIT();
    };

    load_stage(0, 0);
    for (int s = 0; s < ST; s++) {
        int buf = s & 1;
        CP_WAIT0();
        __syncthreads();
        if (s + 1 < ST) load_stage(s + 1, buf ^ 1);
#pragma unroll
        for (int kk = 0; kk < 2; kk++) {
            const int k16 = kk * 16;
            uint32_t a[2][4];
#pragma unroll
            for (int mt = 0; mt < 2; mt++) {
                uint32_t ad = smem_u32(smA + buf * A_ST
                                       + (wm * 32 + mt * 16 + (lane & 15)) * 40
                                       + k16 + (lane >> 4) * 8);
                LDSM_X4(a[mt][0], a[mt][1], a[mt][2], a[mt][3], ad);
            }
            uint32_t b[NT][2];
#pragma unroll
            for (int half = 0; half < NT / 2; half++) {
                int g = lane >> 3, r = lane & 7;
                int nt8 = (g >> 1), ko = (g & 1) * 8;
                uint32_t ad = smem_u32(smB + buf * B_ST
                                       + (wn * WCOLS + half * 16 + nt8 * 8 + r) * 40
                                       + k16 + ko);
                uint32_t r0, r1, r2, r3;
                LDSM_X4(r0, r1, r2, r3, ad);
                b[half * 2 + 0][0] = r0; b[half * 2 + 0][1] = r1;
                b[half * 2 + 1][0] = r2; b[half * 2 + 1][1] = r3;
            }
#pragma unroll
            for (int mt = 0; mt < 2; mt++)
#pragma unroll
                for (int nt = 0; nt < NT; nt++)
                    MMA16816(acc[mt][nt], a[mt], b[nt]);
        }
    }

#pragma unroll
    for (int mt = 0; mt < 2; mt++) {
#pragma unroll
        for (int hh = 0; hh < 2; hh++) {
            int m = m0 + wm * 32 + mt * 16 + (lane >> 2) + hh * 8;
            if (m >= M) continue;
            int node = m % Nn;
#pragma unroll
            for (int nt = 0; nt < NT; nt++) {
                int col = n0 + wn * WCOLS + nt * 8 + (lane & 3) * 2;
                float v0 = acc[mt][nt][hh * 2 + 0];
                float v1 = acc[mt][nt][hh * 2 + 1];
                if (S.act) {
                    v0 = 1.f / (1.f + __expf(-(v0 + S.bias[col])));
                    v1 = 1.f / (1.f + __expf(-(v1 + S.bias[col + 1])));
                }
                if (S.gate) {
                    v0 *= S.gate[(size_t)node * 64 + col];
                    v1 *= S.gate[(size_t)node * 64 + col + 1];
                }
                size_t o = (size_t)m * NCfull + col;
                if (S.Cf) *(float2*)(S.Cf + o) = make_float2(v0, v1);
                if (S.Ch) store_h2(S.Ch, o, v0, v1);
                if (S.Lh) {
                    float l0 = (v0 >= 0.f) ? v0 : SLOPEF * v0;
                    float l1 = (v1 >= 0.f) ? v1 : SLOPEF * v1;
                    store_h2(S.Lh, o, l0, l1);
                }
            }
        }
    }
}

// ---------------------------------------------------------------------------
// 3-plane VN GEMM (K=64, NC=64): one block = 128 nodes x 64 cols, loops d=0..2
// with B resident in smem. 512 threads, 16 warps (8M x 2N), warp tile 16x32.
// Epilogue holds all 3 components per (node, chan):
//   - optional vn_lrelu against u, optional plane outputs, optional norms.
// ---------------------------------------------------------------------------
struct VSet {
    const hf *A;                // planes [d][n][64]
    const hf *B;                // [64][64] fp16
    const hf *U;                // vn_lrelu input planes (or null)
    hf *C;                      // plane outputs (or null)
    hf *Nrm;                    // norm outputs [n,64] (or null)
};

__global__ void __launch_bounds__(512, 2)
gemm_vn3(VSet s0, VSet s1, int Nn) {
    __shared__ hf Bs[64 * 72];
    __shared__ hf As[2][128 * 40];
    const int tid = threadIdx.x, lane = tid & 31, wid = tid >> 5;
    const int wm = wid >> 1, wn = wid & 1;       // 8 x 2
    const VSet S = blockIdx.y ? s1 : s0;
    const int m0 = blockIdx.x * 128;
    const size_t P = (size_t)Nn * 64;

    // B resident: 64 rows x 64 fp16 = 8 x 16B per row
    if (tid < 512) {
        int r = tid >> 3, c8 = tid & 7;
        CP_ASYNC16(smem_u32(Bs + r * 72 + c8 * 8), S.B + r * 64 + c8 * 8);
    }
    CP_COMMIT();

    float acc[3][4][4];
#pragma unroll
    for (int d = 0; d < 3; d++)
#pragma unroll
        for (int j = 0; j < 4; j++)
#pragma unroll
            for (int k = 0; k < 4; k++) acc[d][j][k] = 0.f;

    auto loadA = [&](int gs, int buf) {
        int d = gs >> 1, kc = gs & 1;
        int kof = kc * 32;
        int r = tid >> 2, sg = tid & 3;          // exactly 512 chunks
        int m = m0 + r;
        uint32_t sa = smem_u32(As[buf] + r * 40 + sg * 8);
        const hf* ga = S.A + d * P + ((m < Nn) ? ((size_t)m * 64 + kof + sg * 8) : 0);
        CP_ASYNC16_P(sa, ga, (m < Nn) ? 16 : 0);
        CP_COMMIT();
    };

    loadA(0, 0);
    for (int gs = 0; gs < 6; gs++) {
        int buf = gs & 1;
        CP_WAIT0();
        __syncthreads();
        if (gs + 1 < 6) loadA(gs + 1, buf ^ 1);
        int d = gs >> 1, kc = gs & 1;
#pragma unroll
        for (int kk = 0; kk < 2; kk++) {
            const int k16 = kk * 16;
            uint32_t a[4];
            {
                uint32_t ad = smem_u32(As[buf] + (wm * 16 + (lane & 15)) * 40
                                       + k16 + (lane >> 4) * 8);
                LDSM_X4(a[0], a[1], a[2], a[3], ad);
            }
            int bcol = kc * 32;
            uint32_t b[4][2];
            {
                int g = lane >> 3, r = lane & 7;
                int nt8 = (g >> 1), ko = (g & 1) * 8;
#pragma unroll
                for (int half = 0; half < 2; half++) {
                    uint32_t ad = smem_u32(Bs + (wn * 32 + half * 16 + nt8 * 8 + r) * 72
                                           + bcol + k16 + ko);
                    uint32_t r0, r1, r2, r3;
                    LDSM_X4(r0, r1, r2, r3, ad);
                    b[half * 2 + 0][0] = r0; b[half * 2 + 0][1] = r1;
                    b[half * 2 + 1][0] = r2; b[half * 2 + 1][1] = r3;
                }
            }
#pragma unroll
            for (int nt = 0; nt < 4; nt++)
                MMA16816(acc[d][nt], a, b[nt]);
        }
    }

    // -------- fused epilogue --------
#pragma unroll
    for (int hh = 0; hh < 2; hh++) {
        int m = m0 + wm * 16 + (lane >> 2) + hh * 8;
        if (m >= Nn) continue;
#pragma unroll
        for (int nt = 0; nt < 4; nt++) {
            int col = wn * 32 + nt * 8 + (lane & 3) * 2;
            float v[3][2];
#pragma unroll
            for (int d = 0; d < 3; d++) {
                v[d][0] = acc[d][nt][hh * 2 + 0];
                v[d][1] = acc[d][nt][hh * 2 + 1];
            }
            if (S.U) {
                float u[3][2];
#pragma unroll
                for (int d = 0; d < 3; d++) {
                    __half2 uh = *(const __half2*)(S.U + d * P + (size_t)m * 64 + col);
                    u[d][0] = __half2float(uh.x);
                    u[d][1] = __half2float(uh.y);
                }
#pragma unroll
                for (int e = 0; e < 2; e++) {
                    float dot = u[0][e] * v[0][e] + u[1][e] * v[1][e] + u[2][e] * v[2][e];
                    float dsq = v[0][e] * v[0][e] + v[1][e] * v[1][e] + v[2][e] * v[2][e];
                    float sc = dot / (dsq + EPSF);
#pragma unroll
                    for (int d = 0; d < 3; d++) {
                        float x = u[d][e];
                        float r = (dot >= 0.f) ? x
                                 : (SLOPEF * x + (1.f - SLOPEF) * (x - sc * v[d][e]));
                        v[d][e] = r;
                    }
                }
            }
            if (S.C) {
#pragma unroll
                for (int d = 0; d < 3; d++)
                    store_h2(S.C, d * P + (size_t)m * 64 + col, v[d][0], v[d][1]);
            }
            if (S.Nrm) {
                float n0 = sqrtf(v[0][0] * v[0][0] + v[1][0] * v[1][0] + v[2][0] * v[2][0]);
                float n1 = sqrtf(v[0][1] * v[0][1] + v[1][1] * v[1][1] + v[2][1] * v[2][1]);
                store_h2(S.Nrm, (size_t)m * 64 + col, n0, n1);
            }
        }
    }
}

// ---------------------------------------------------------------------------
// weight prepack: W(nc,k) fp32 -> fp16
// ---------------------------------------------------------------------------
struct PPk { const float* w; hf* o; int nc; int k; };
struct PPargs { PPk e[15]; };
__global__ void k_prepack(PPargs pa) {
    PPk p = pa.e[blockIdx.y];
    int tot = p.nc * p.k;
    for (int i = blockIdx.x * 256 + threadIdx.x; i < tot; i += gridDim.x * 256)
        p.o[i] = __float2half(p.w[i]);
}

// ---------------------------------------------------------------------------
// prep: vec -> fp16 planes; sca = h_sca + te[t] -> fp16 [n,256]
// ---------------------------------------------------------------------------
__global__ void k_prep(const float* __restrict__ h_vec, const float* __restrict__ h_sca,
                       const float* __restrict__ te, const int* __restrict__ tptr,
                       hf* __restrict__ vh, hf* __restrict__ scah, int Nn) {
    int i = blockIdx.x * 256 + threadIdx.x;
    int half = Nn * 64;
    if (i < half) {
        int node = i >> 6, c = i & 63;
#pragma unroll
        for (int d = 0; d < 3; d++) {
            float x = h_vec[(size_t)node * 192 + c * 3 + d];
            vh[(size_t)d * Nn * 64 + (size_t)node * 64 + c] = __float2half(x);
        }
    } else if (i < 2 * half) {
        int j = i - half;
        int node = j >> 6, q4 = (j & 63) * 4;
        int t = *tptr;
        float4 hs = *(const float4*)(h_sca + (size_t)node * 256 + q4);
        float4 tv = *(const float4*)(te + (size_t)t * 256 + q4);
        size_t o = (size_t)node * 256 + q4;
        store_h2(scah, o,     hs.x + tv.x, hs.y + tv.y);
        store_h2(scah, o + 2, hs.z + tv.z, hs.w + tv.w);
    }
}

// att[n] = Ws[0:64].|vi2a| + Ws[64:320].lrelu(Sa)
__global__ void k_att(const hf* __restrict__ Nh, const hf* __restrict__ Sa,
                      const float* __restrict__ Ws, float* __restrict__ att, int Nn) {
    __shared__ float ws[320];
    int tid = threadIdx.x, w = tid >> 5, lane = tid & 31;
    for (int i = tid; i < 320; i += 256) ws[i] = Ws[i];
    __syncthreads();
    int node = blockIdx.x * 8 + w;
    if (node >= Nn) return;
    float p = 0.f;
    for (int c = lane; c < 64; c += 32)
        p = fmaf(ws[c], __half2float(Nh[(size_t)node * 64 + c]), p);
    for (int k = lane; k < 256; k += 32) {
        float sv = __half2float(Sa[(size_t)node * 256 + k]);
        sv = (sv >= 0.f) ? sv : SLOPEF * sv;
        p = fmaf(ws[64 + k], sv, p);
    }
#pragma unroll
    for (int o = 16; o > 0; o >>= 1) p += __shfl_down_sync(0xffffffff, p, o);
    if (lane == 0) att[node] = p;
}

__global__ void k_segstart(const int* __restrict__ bid, int n, int B, int* __restrict__ start) {
    int b = blockIdx.x * blockDim.x + threadIdx.x;
    if (b > B) return;
    int lo = 0, hi = n;
    while (lo < hi) { int mid = (lo + hi) >> 1; if (bid[mid] < b) lo = mid + 1; else hi = mid; }
    start[b] = lo;
}

__global__ void k_softmax(const float* __restrict__ att, const int* __restrict__ start,
                          float* __restrict__ w) {
    int b = blockIdx.x;
    int s = start[b], e = start[b + 1];
    if (s >= e) return;
    __shared__ float red[256];
    int tid = threadIdx.x;
    float m = -INFINITY;
    for (int i = s + tid; i < e; i += 256) m = fmaxf(m, att[i]);
    red[tid] = m; __syncthreads();
    for (int o = 128; o > 0; o >>= 1) { if (tid < o) red[tid] = fmaxf(red[tid], red[tid + o]); __syncthreads(); }
    m = red[0]; __syncthreads();
    float zs = 0.f;
    for (int i = s + tid; i < e; i += 256) zs += __expf(att[i] - m);
    red[tid] = zs; __syncthreads();
    for (int o = 128; o > 0; o >>= 1) { if (tid < o) red[tid] += red[tid + o]; __syncthreads(); }
    float inv = 1.f / red[0];
    for (int i = s + tid; i < e; i += 256) w[i] = __expf(att[i] - m) * inv;
}

__global__ void k_reduce(const float* __restrict__ w, const hf* __restrict__ fs,
                         const hf* __restrict__ fv, const float* __restrict__ pos,
                         const int* __restrict__ start, int B, int Nn, float* __restrict__ out) {
    int b = blockIdx.x, j = threadIdx.x;
    int s = start[b], e = start[b + 1];
    size_t P = (size_t)Nn * 64;
    int c = j / 3, d = j - c * 3;
    float a256 = 0.f, a192 = 0.f, a3 = 0.f;
    for (int i = s; i < e; i++) {
        float wi = w[i];
        a256 = fmaf(wi, __half2float(fs[(size_t)i * 256 + j]), a256);
        if (j < 192)
            a192 = fmaf(wi, __half2float(fv[(size_t)d * P + (size_t)i * 64 + c]), a192);
        if (j < 3) a3 = fmaf(wi, pos[(size_t)i * 3 + j], a3);
    }
    out[(size_t)b * 256 + j] = a256;
    if (j < 192) out[(size_t)B * 256 + (size_t)b * 192 + j] = a192;
    if (j < 3)   out[(size_t)B * 256 + (size_t)B * 192 + (size_t)b * 3 + j] = a3;
}

// ---------------------------------------------------------------------------
extern "C" void kernel_launch(void* const* d_in, const int* in_sizes, int n_in,
                              void* d_out, int out_size) {
    const float* h_sca = (const float*)d_in[0];
    const float* h_vec = (const float*)d_in[1];
    const float* pos   = (const float*)d_in[2];
    const float* te    = (const float*)d_in[3];
    const float* W[26];
    for (int i = 4; i <= 25; i++) W[i] = (const float*)d_in[i];
    const int* tptr = (const int*)d_in[26];
    const int* bid  = (const int*)d_in[27];

    int n = in_sizes[0] / 256;
    int B = out_size / 451;

    hf *vecS, *viAs, *viNs, *uas, *uns, *vas, *vns, *scaX, *lrS, *Sas, *Sns;
    hf *nA1, *nN1, *nA2, *nN2, *Baug;
    float *Ga, *Gn, *att, *wgt;
    int* segs;
    cudaGetSymbolAddress((void**)&vecS, g_vecS);
    cudaGetSymbolAddress((void**)&viAs, g_viAs);
    cudaGetSymbolAddress((void**)&viNs, g_viNs);
    cudaGetSymbolAddress((void**)&uas,  g_uas);
    cudaGetSymbolAddress((void**)&uns,  g_uns);
    cudaGetSymbolAddress((void**)&vas,  g_vas);
    cudaGetSymbolAddress((void**)&vns,  g_vns);
    cudaGetSymbolAddress((void**)&scaX, g_scaX);
    cudaGetSymbolAddress((void**)&lrS,  g_lrS);
    cudaGetSymbolAddress((void**)&Sas,  g_Sas);
    cudaGetSymbolAddress((void**)&Sns,  g_Sns);
    cudaGetSymbolAddress((void**)&nA1,  g_nA1);
    cudaGetSymbolAddress((void**)&nN1,  g_nN1);
    cudaGetSymbolAddress((void**)&nA2,  g_nA2);
    cudaGetSymbolAddress((void**)&nN2,  g_nN2);
    cudaGetSymbolAddress((void**)&Baug, g_Baug);
    cudaGetSymbolAddress((void**)&Ga,   g_Ga);
    cudaGetSymbolAddress((void**)&Gn,   g_Gn);
    cudaGetSymbolAddress((void**)&att,  g_att);
    cudaGetSymbolAddress((void**)&wgt,  g_w);
    cudaGetSymbolAddress((void**)&segs, g_seg);

    static const int widx[15] = {4,15, 6,17, 7,18, 5,16, 9,20, 10,21, 23,24,22};
    static const int wnc[15]  = {64,64, 256,256, 64,64, 64,64, 64,64, 64,64, 256,64,64};
    static const int wk[15]   = {64,64, 320,320, 256,256, 64,64, 64,64, 64,64, 320,256,64};
    PPargs pa;
    size_t boff[15]; size_t acc = 0;
    for (int i = 0; i < 15; i++) {
        boff[i] = acc;
        pa.e[i] = PPk{W[widx[i]], Baug + acc, wnc[i], wk[i]};
        acc += (size_t)wnc[i] * wk[i];
    }
    const hf *B_a1Wv1 = Baug + boff[0],  *B_n1Wv1 = Baug + boff[1];
    const hf *B_a1Ws  = Baug + boff[2],  *B_n1Ws  = Baug + boff[3];
    const hf *B_a1Wg  = Baug + boff[4],  *B_n1Wg  = Baug + boff[5];
    const hf *B_a1Wv2 = Baug + boff[6],  *B_n1Wv2 = Baug + boff[7];
    const hf *B_a1Wd  = Baug + boff[8],  *B_n1Wd  = Baug + boff[9];
    const hf *B_a2Wv1 = Baug + boff[10], *B_n2Wv1 = Baug + boff[11];
    const hf *B_n2Ws  = Baug + boff[12], *B_n2Wg  = Baug + boff[13];
    const hf *B_n2Wv2 = Baug + boff[14];

    size_t H64 = (size_t)n * 64, H256 = (size_t)n * 256;
    int M3 = 3 * n;
    int gv = (n + 127) / 128;
    int g3 = (M3 + 127) / 128;

    constexpr int SM64  = (2 * 128 * 40 + 2 * 64 * 40) * 2;    // 30720 B
    constexpr int SM128 = (2 * 128 * 40 + 2 * 128 * 40) * 2;   // 40960 B
    cudaFuncSetAttribute((const void*)gemm_f16<64>,
                         cudaFuncAttributeMaxDynamicSharedMemorySize, SM64);
    cudaFuncSetAttribute((const void*)gemm_f16<128>,
                         cudaFuncAttributeMaxDynamicSharedMemorySize, SM128);

    auto GS = [](const hf* a1, const hf* a2, int K1, const hf* b,
                 float* cf, hf* ch, hf* lh,
                 const float* bias, const float* gate, int act) {
        GSet g; g.A1 = a1; g.A2 = a2; g.K1 = K1; g.B = b;
        g.Cf = cf; g.Ch = ch; g.Lh = lh;
        g.bias = bias; g.gate = gate; g.act = act; return g;
    };
    auto VS = [](const hf* a, const hf* b, const hf* u, hf* c, hf* nrm) {
        VSet v; v.A = a; v.B = b; v.U = u; v.C = c; v.Nrm = nrm; return v;
    };

    k_prepack<<<dim3(64, 15), 256>>>(pa);
    k_prep<<<(n * 128 + 255) / 256, 256>>>(h_vec, h_sca, te, tptr, vecS, scaX, n);

    // vi pair: planes + norms
    gemm_vn3<<<dim3(gv, 2), 512>>>(
        VS(vecS, B_a1Wv1, nullptr, viAs, nA1),
        VS(vecS, B_n1Wv1, nullptr, viNs, nN1), n);
    // S pair: A = (norms | sca shared); net side also emits lrelu(Sn)
    gemm_f16<128><<<dim3(gv, 2, 2), 512, SM128>>>(
        GS(nA1, scaX, 64, B_a1Ws, nullptr, Sas, nullptr, nullptr, nullptr, 0),
        GS(nN1, scaX, 64, B_n1Ws, nullptr, Sns, lrS,     nullptr, nullptr, 0),
        n, 320, n, 256);
    // gates pair
    gemm_f16<64><<<dim3(gv, 2, 1), 256, SM64>>>(
        GS(Sas, nullptr, 256, B_a1Wg, Ga, nullptr, nullptr, W[8],  nullptr, 1),
        GS(Sns, nullptr, 256, B_n1Wg, Gn, nullptr, nullptr, W[19], nullptr, 1),
        n, 256, n, 64);
    // u pair (per-plane rows M3, gated)
    gemm_f16<64><<<dim3(g3, 2, 1), 256, SM64>>>(
        GS(viAs, nullptr, 64, B_a1Wv2, nullptr, uas, nullptr, nullptr, Ga, 0),
        GS(viNs, nullptr, 64, B_n1Wv2, nullptr, uns, nullptr, nullptr, Gn, 0),
        M3, 64, n, 64);
    // d pair with fused vn_lrelu -> v
    gemm_vn3<<<dim3(gv, 2), 512>>>(
        VS(uas, B_a1Wd, uas, vas, nullptr),
        VS(uns, B_n1Wd, uns, vns, nullptr), n);
    // vi2 pair: att -> norms only; net -> vi2n planes + norms
    gemm_vn3<<<dim3(gv, 2), 512>>>(
        VS(vas, B_a2Wv1, nullptr, nullptr, nA2),
        VS(vns, B_n2Wv1, nullptr, viAs, nN2), n);
    k_att<<<(n + 7) / 8, 256>>>(nA2, Sas, W[12], att, n);

    // fs = (norms2 | lrelu(Sn)) @ n2Ws -> Sas reuse
    {
        GSet g = GS(nN2, lrS, 64, B_n2Ws, nullptr, Sas, nullptr, nullptr, nullptr, 0);
        gemm_f16<128><<<dim3(gv, 1, 2), 512, SM128>>>(g, g, n, 320, n, 256);
    }
    // gate2 -> Ga reuse
    {
        GSet g = GS(Sas, nullptr, 256, B_n2Wg, Ga, nullptr, nullptr, W[25], nullptr, 1);
        gemm_f16<64><<<dim3(gv, 1, 1), 256, SM64>>>(g, g, n, 256, n, 64);
    }
    // fv = gate2 * (n2Wv2 @ vi2n) -> vas reuse
    {
        GSet g = GS(viAs, nullptr, 64, B_n2Wv2, nullptr, vas, nullptr, nullptr, Ga, 0);
        gemm_f16<64><<<dim3(g3, 1, 1), 256, SM64>>>(g, g, M3, 64, n, 64);
    }

    k_segstart<<<(B + 1 + 255) / 256, 256>>>(bid, n, B, segs);
    k_softmax<<<B, 256>>>(att, segs, wgt);
    k_reduce<<<B, 256>>>(wgt, Sas, vas, pos, segs, B, n, (float*)d_out);
}

// round 12
// speedup vs baseline: 1.9785x; 1.0037x over previous
#include <cuda_runtime.h>
#include <cuda_fp16.h>
#include <math.h>
#include <stdint.h>

typedef __half hf;

#define MAXN   120000
#define SLOPEF 0.01f
#define EPSF   1e-6f
#define PVMAX  (3*MAXN*64)

// ---------------- static device scratch (plain fp16) ------------------------
__device__ __align__(16) hf    g_vecS[PVMAX];
__device__ __align__(16) hf    g_viAs[PVMAX];
__device__ __align__(16) hf    g_viNs[PVMAX];   // later: vi2n
__device__ __align__(16) hf    g_uas [PVMAX];
__device__ __align__(16) hf    g_uns [PVMAX];
__device__ __align__(16) hf    g_vas [PVMAX];   // later: fv
__device__ __align__(16) hf    g_vns [PVMAX];
__device__ __align__(16) hf    g_scaX[MAXN*256];
__device__ __align__(16) hf    g_lrS [MAXN*256];
__device__ __align__(16) hf    g_Sas [MAXN*256]; // later: fs
__device__ __align__(16) hf    g_Sns [MAXN*256];
__device__ __align__(16) hf    g_nA1 [MAXN*64];
__device__ __align__(16) hf    g_nN1 [MAXN*64];
__device__ __align__(16) hf    g_nA2 [MAXN*64];
__device__ __align__(16) hf    g_nN2 [MAXN*64];
__device__ __align__(16) hf    g_Baug[524288];
__device__ float g_Ga  [MAXN*64];
__device__ float g_Gn  [MAXN*64];
__device__ float g_att [MAXN];
__device__ float g_w   [MAXN];
__device__ int   g_seg [4100];

// ---------------- helpers ----------------
__device__ __forceinline__ uint32_t smem_u32(const void* p) {
    return (uint32_t)__cvta_generic_to_shared(p);
}
__device__ __forceinline__ void store_h2(hf* H, size_t o, float v0, float v1) {
    __half2 t; t.x = __float2half(v0); t.y = __float2half(v1);
    *(__half2*)(H + o) = t;
}

#define MMA16816(d, a, b)                                                     \
    asm volatile("mma.sync.aligned.m16n8k16.row.col.f32.f16.f16.f32 "        \
        "{%0,%1,%2,%3}, {%4,%5,%6,%7}, {%8,%9}, {%0,%1,%2,%3};"              \
        : "+f"((d)[0]), "+f"((d)[1]), "+f"((d)[2]), "+f"((d)[3])             \
        : "r"((a)[0]), "r"((a)[1]), "r"((a)[2]), "r"((a)[3]),                \
          "r"((b)[0]), "r"((b)[1]))

#define LDSM_X4(r0, r1, r2, r3, addr)                                        \
    asm volatile("ldmatrix.sync.aligned.m8n8.x4.shared.b16 {%0,%1,%2,%3}, [%4];" \
        : "=r"(r0), "=r"(r1), "=r"(r2), "=r"(r3) : "r"(addr))

#define CP_ASYNC16(sa, ga)                                                   \
    asm volatile("cp.async.cg.shared.global [%0], [%1], 16;" :: "r"(sa), "l"(ga))
#define CP_ASYNC16_P(sa, ga, p)                                              \
    asm volatile("cp.async.cg.shared.global [%0], [%1], 16, %2;" :: "r"(sa), "l"(ga), "r"(p))
#define CP_COMMIT() asm volatile("cp.async.commit_group;")
#define CP_WAIT0()  asm volatile("cp.async.wait_group 0;")

// ---------------------------------------------------------------------------
// fp16 HMMA GEMM with two A regions: cols [0,K1) from A1, [K1,K) from A2
// C[M, NCfull] tile (128 x NC) at column offset blockIdx.z*NC.
// B prepacked [NCfull][K] fp16.
// NC=128: 256 thr, 8 warps 2(M)x4(N), warp tile 64x32, minBlocks 2.
// NC=64:  256 thr, 8 warps 4(M)x2(N), warp tile 32x32, minBlocks 3.
// ---------------------------------------------------------------------------
struct GSet {
    const hf *A1, *A2;
    int K1;
    const hf* B;
    float* Cf; hf* Ch;
    hf* Lh;                          // optional lrelu side-output
    const float *bias, *gate;
    int act;
};

template <int NC>
__global__ void __launch_bounds__(256, NC >= 128 ? 2 : 3)
gemm_f16(GSet s0, GSet s1, int M, int K, int Nn, int NCfull) {
    constexpr int NWM   = (NC >= 128) ? 2 : 4;
    constexpr int NWN   = (NC >= 128) ? 4 : 2;
    constexpr int MT    = 128 / (NWM * 16);  // 4 or 2
    constexpr int WCOLS = NC / NWN;          // 32
    constexpr int NT    = WCOLS / 8;         // 4
    constexpr int A_ST  = 128 * 40;
    constexpr int B_ST  = NC * 40;

    extern __shared__ hf sm[];
    hf* smA = sm;
    hf* smB = sm + 2 * A_ST;

    const int tid = threadIdx.x;
    const int lane = tid & 31, wid = tid >> 5;
    const int wm = wid / NWN, wn = wid % NWN;
    const GSet S = (blockIdx.y == 0) ? s0 : s1;
    const int m0 = blockIdx.x * 128;
    const int n0 = blockIdx.z * NC;
    const int ST = K >> 5;
    const int K2w = K - S.K1;

    float acc[MT][NT][4];
#pragma unroll
    for (int i = 0; i < MT; i++)
#pragma unroll
        for (int j = 0; j < NT; j++)
#pragma unroll
            for (int k = 0; k < 4; k++) acc[i][j][k] = 0.f;

    auto load_stage = [&](int s, int buf) {
        int kof = s * 32;
        const hf* base; int stride, col;
        if (kof < S.K1) { base = S.A1; stride = S.K1; col = kof; }
        else            { base = S.A2; stride = K2w;  col = kof - S.K1; }
#pragma unroll
        for (int i = tid; i < 512; i += 256) {
            int r = i >> 2, sg = i & 3;
            int m = m0 + r;
            uint32_t sa = smem_u32(smA + buf * A_ST + r * 40 + sg * 8);
            const hf* ga = base + ((m < M) ? ((size_t)m * stride + col + sg * 8) : 0);
            CP_ASYNC16_P(sa, ga, (m < M) ? 16 : 0);
        }
#pragma unroll
        for (int i = tid; i < NC * 4; i += 256) {
            int r = i >> 2, sg = i & 3;
            uint32_t sa = smem_u32(smB + buf * B_ST + r * 40 + sg * 8);
            CP_ASYNC16(sa, S.B + (size_t)(n0 + r) * K + kof + sg * 8);
        }
        CP_COMMIT();
    };

    // hoisted per-warp LDSM base offsets (element units, within one buffer)
    uint32_t aBase = smem_u32(smA);
    uint32_t bBase = smem_u32(smB);
    int aOff[MT];
#pragma unroll
    for (int mt = 0; mt < MT; mt++)
        aOff[mt] = (wm * (MT * 16) + mt * 16 + (lane & 15)) * 40 + (lane >> 4) * 8;
    int bOff;
    {
        int g = lane >> 3, r = lane & 7;
        int nt8 = (g >> 1), ko = (g & 1) * 8;
        bOff = (wn * WCOLS + nt8 * 8 + r) * 40 + ko;
    }

    load_stage(0, 0);
    for (int s = 0; s < ST; s++) {
        int buf = s & 1;
        CP_WAIT0();
        __syncthreads();
        if (s + 1 < ST) load_stage(s + 1, buf ^ 1);
        uint32_t aB = aBase + buf * (A_ST * 2);
        uint32_t bB = bBase + buf * (B_ST * 2);
#pragma unroll
        for (int kk = 0; kk < 2; kk++) {
            const int k16 = kk * 16;
            uint32_t a[MT][4];
#pragma unroll
            for (int mt = 0; mt < MT; mt++)
                LDSM_X4(a[mt][0], a[mt][1], a[mt][2], a[mt][3],
                        aB + (aOff[mt] + k16) * 2);
            uint32_t b[NT][2];
#pragma unroll
            for (int half = 0; half < NT / 2; half++) {
                uint32_t r0, r1, r2, r3;
                LDSM_X4(r0, r1, r2, r3, bB + (bOff + half * 16 * 40 + k16) * 2);
                b[half * 2 + 0][0] = r0; b[half * 2 + 0][1] = r1;
                b[half * 2 + 1][0] = r2; b[half * 2 + 1][1] = r3;
            }
#pragma unroll
            for (int mt = 0; mt < MT; mt++)
#pragma unroll
                for (int nt = 0; nt < NT; nt++)
                    MMA16816(acc[mt][nt], a[mt], b[nt]);
        }
    }

#pragma unroll
    for (int mt = 0; mt < MT; mt++) {
#pragma unroll
        for (int hh = 0; hh < 2; hh++) {
            int m = m0 + wm * (MT * 16) + mt * 16 + (lane >> 2) + hh * 8;
            if (m >= M) continue;
            int node = m % Nn;
#pragma unroll
            for (int nt = 0; nt < NT; nt++) {
                int col = n0 + wn * WCOLS + nt * 8 + (lane & 3) * 2;
                float v0 = acc[mt][nt][hh * 2 + 0];
                float v1 = acc[mt][nt][hh * 2 + 1];
                if (S.act) {
                    v0 = 1.f / (1.f + __expf(-(v0 + S.bias[col])));
                    v1 = 1.f / (1.f + __expf(-(v1 + S.bias[col + 1])));
                }
                if (S.gate) {
                    v0 *= S.gate[(size_t)node * 64 + col];
                    v1 *= S.gate[(size_t)node * 64 + col + 1];
                }
                size_t o = (size_t)m * NCfull + col;
                if (S.Cf) *(float2*)(S.Cf + o) = make_float2(v0, v1);
                if (S.Ch) store_h2(S.Ch, o, v0, v1);
                if (S.Lh) {
                    float l0 = (v0 >= 0.f) ? v0 : SLOPEF * v0;
                    float l1 = (v1 >= 0.f) ? v1 : SLOPEF * v1;
                    store_h2(S.Lh, o, l0, l1);
                }
            }
        }
    }
}

// ---------------------------------------------------------------------------
// 3-plane VN GEMM (K=64, NC=64): one block = 128 nodes x 64 cols, loops d=0..2
// with B resident in smem. 512 threads, 16 warps (8M x 2N), warp tile 16x32.
// ---------------------------------------------------------------------------
struct VSet {
    const hf *A;                // planes [d][n][64]
    const hf *B;                // [64][64] fp16
    const hf *U;                // vn_lrelu input planes (or null)
    hf *C;                      // plane outputs (or null)
    hf *Nrm;                    // norm outputs [n,64] (or null)
};

__global__ void __launch_bounds__(512, 2)
gemm_vn3(VSet s0, VSet s1, int Nn) {
    __shared__ hf Bs[64 * 72];
    __shared__ hf As[2][128 * 40];
    const int tid = threadIdx.x, lane = tid & 31, wid = tid >> 5;
    const int wm = wid >> 1, wn = wid & 1;       // 8 x 2
    const VSet S = blockIdx.y ? s1 : s0;
    const int m0 = blockIdx.x * 128;
    const size_t P = (size_t)Nn * 64;

    // B resident: 64 rows x 64 fp16 = 8 x 16B per row
    {
        int r = tid >> 3, c8 = tid & 7;
        CP_ASYNC16(smem_u32(Bs + r * 72 + c8 * 8), S.B + r * 64 + c8 * 8);
    }
    CP_COMMIT();

    float acc[3][4][4];
#pragma unroll
    for (int d = 0; d < 3; d++)
#pragma unroll
        for (int j = 0; j < 4; j++)
#pragma unroll
            for (int k = 0; k < 4; k++) acc[d][j][k] = 0.f;

    auto loadA = [&](int gs, int buf) {
        int d = gs >> 1, kc = gs & 1;
        int kof = kc * 32;
        int r = tid >> 2, sg = tid & 3;          // exactly 512 chunks
        int m = m0 + r;
        uint32_t sa = smem_u32(As[buf] + r * 40 + sg * 8);
        const hf* ga = S.A + d * P + ((m < Nn) ? ((size_t)m * 64 + kof + sg * 8) : 0);
        CP_ASYNC16_P(sa, ga, (m < Nn) ? 16 : 0);
        CP_COMMIT();
    };

    loadA(0, 0);
    for (int gs = 0; gs < 6; gs++) {
        int buf = gs & 1;
        CP_WAIT0();
        __syncthreads();
        if (gs + 1 < 6) loadA(gs + 1, buf ^ 1);
        int d = gs >> 1, kc = gs & 1;
#pragma unroll
        for (int kk = 0; kk < 2; kk++) {
            const int k16 = kk * 16;
            uint32_t a[4];
            {
                uint32_t ad = smem_u32(As[buf] + (wm * 16 + (lane & 15)) * 40
                                       + k16 + (lane >> 4) * 8);
                LDSM_X4(a[0], a[1], a[2], a[3], ad);
            }
            int bcol = kc * 32;
            uint32_t b[4][2];
            {
                int g = lane >> 3, r = lane & 7;
                int nt8 = (g >> 1), ko = (g & 1) * 8;
#pragma unroll
                for (int half = 0; half < 2; half++) {
                    uint32_t ad = smem_u32(Bs + (wn * 32 + half * 16 + nt8 * 8 + r) * 72
                                           + bcol + k16 + ko);
                    uint32_t r0, r1, r2, r3;
                    LDSM_X4(r0, r1, r2, r3, ad);
                    b[half * 2 + 0][0] = r0; b[half * 2 + 0][1] = r1;
                    b[half * 2 + 1][0] = r2; b[half * 2 + 1][1] = r3;
                }
            }
#pragma unroll
            for (int nt = 0; nt < 4; nt++)
                MMA16816(acc[d][nt], a, b[nt]);
        }
    }

    // -------- fused epilogue --------
#pragma unroll
    for (int hh = 0; hh < 2; hh++) {
        int m = m0 + wm * 16 + (lane >> 2) + hh * 8;
        if (m >= Nn) continue;
#pragma unroll
        for (int nt = 0; nt < 4; nt++) {
            int col = wn * 32 + nt * 8 + (lane & 3) * 2;
            float v[3][2];
#pragma unroll
            for (int d = 0; d < 3; d++) {
                v[d][0] = acc[d][nt][hh * 2 + 0];
                v[d][1] = acc[d][nt][hh * 2 + 1];
            }
            if (S.U) {
                float u[3][2];
#pragma unroll
                for (int d = 0; d < 3; d++) {
                    __half2 uh = *(const __half2*)(S.U + d * P + (size_t)m * 64 + col);
                    u[d][0] = __half2float(uh.x);
                    u[d][1] = __half2float(uh.y);
                }
#pragma unroll
                for (int e = 0; e < 2; e++) {
                    float dot = u[0][e] * v[0][e] + u[1][e] * v[1][e] + u[2][e] * v[2][e];
                    float dsq = v[0][e] * v[0][e] + v[1][e] * v[1][e] + v[2][e] * v[2][e];
                    float sc = dot / (dsq + EPSF);
#pragma unroll
                    for (int d = 0; d < 3; d++) {
                        float x = u[d][e];
                        float r = (dot >= 0.f) ? x
                                 : (SLOPEF * x + (1.f - SLOPEF) * (x - sc * v[d][e]));
                        v[d][e] = r;
                    }
                }
            }
            if (S.C) {
#pragma unroll
                for (int d = 0; d < 3; d++)
                    store_h2(S.C, d * P + (size_t)m * 64 + col, v[d][0], v[d][1]);
            }
            if (S.Nrm) {
                float n0 = sqrtf(v[0][0] * v[0][0] + v[1][0] * v[1][0] + v[2][0] * v[2][0]);
                float n1 = sqrtf(v[0][1] * v[0][1] + v[1][1] * v[1][1] + v[2][1] * v[2][1]);
                store_h2(S.Nrm, (size_t)m * 64 + col, n0, n1);
            }
        }
    }
}

// ---------------------------------------------------------------------------
// weight prepack: W(nc,k) fp32 -> fp16
// ---------------------------------------------------------------------------
struct PPk { const float* w; hf* o; int nc; int k; };
struct PPargs { PPk e[15]; };
__global__ void k_prepack(PPargs pa) {
    PPk p = pa.e[blockIdx.y];
    int tot = p.nc * p.k;
    for (int i = blockIdx.x * 256 + threadIdx.x; i < tot; i += gridDim.x * 256)
        p.o[i] = __float2half(p.w[i]);
}

// ---------------------------------------------------------------------------
// prep: vec -> fp16 planes; sca = h_sca + te[t] -> fp16 [n,256]
// ---------------------------------------------------------------------------
__global__ void k_prep(const float* __restrict__ h_vec, const float* __restrict__ h_sca,
                       const float* __restrict__ te, const int* __restrict__ tptr,
                       hf* __restrict__ vh, hf* __restrict__ scah, int Nn) {
    int i = blockIdx.x * 256 + threadIdx.x;
    int half = Nn * 64;
    if (i < half) {
        int node = i >> 6, c = i & 63;
#pragma unroll
        for (int d = 0; d < 3; d++) {
            float x = h_vec[(size_t)node * 192 + c * 3 + d];
            vh[(size_t)d * Nn * 64 + (size_t)node * 64 + c] = __float2half(x);
        }
    } else if (i < 2 * half) {
        int j = i - half;
        int node = j >> 6, q4 = (j & 63) * 4;
        int t = *tptr;
        float4 hs = *(const float4*)(h_sca + (size_t)node * 256 + q4);
        float4 tv = *(const float4*)(te + (size_t)t * 256 + q4);
        size_t o = (size_t)node * 256 + q4;
        store_h2(scah, o,     hs.x + tv.x, hs.y + tv.y);
        store_h2(scah, o + 2, hs.z + tv.z, hs.w + tv.w);
    }
}

// att[n] = Ws[0:64].|vi2a| + Ws[64:320].lrelu(Sa)
__global__ void k_att(const hf* __restrict__ Nh, const hf* __restrict__ Sa,
                      const float* __restrict__ Ws, float* __restrict__ att, int Nn) {
    __shared__ float ws[320];
    int tid = threadIdx.x, w = tid >> 5, lane = tid & 31;
    for (int i = tid; i < 320; i += 256) ws[i] = Ws[i];
    __syncthreads();
    int node = blockIdx.x * 8 + w;
    if (node >= Nn) return;
    float p = 0.f;
    for (int c = lane; c < 64; c += 32)
        p = fmaf(ws[c], __half2float(Nh[(size_t)node * 64 + c]), p);
    for (int k = lane; k < 256; k += 32) {
        float sv = __half2float(Sa[(size_t)node * 256 + k]);
        sv = (sv >= 0.f) ? sv : SLOPEF * sv;
        p = fmaf(ws[64 + k], sv, p);
    }
#pragma unroll
    for (int o = 16; o > 0; o >>= 1) p += __shfl_down_sync(0xffffffff, p, o);
    if (lane == 0) att[node] = p;
}

__global__ void k_segstart(const int* __restrict__ bid, int n, int B, int* __restrict__ start) {
    int b = blockIdx.x * blockDim.x + threadIdx.x;
    if (b > B) return;
    int lo = 0, hi = n;
    while (lo < hi) { int mid = (lo + hi) >> 1; if (bid[mid] < b) lo = mid + 1; else hi = mid; }
    start[b] = lo;
}

__global__ void k_softmax(const float* __restrict__ att, const int* __restrict__ start,
                          float* __restrict__ w) {
    int b = blockIdx.x;
    int s = start[b], e = start[b + 1];
    if (s >= e) return;
    __shared__ float red[256];
    int tid = threadIdx.x;
    float m = -INFINITY;
    for (int i = s + tid; i < e; i += 256) m = fmaxf(m, att[i]);
    red[tid] = m; __syncthreads();
    for (int o = 128; o > 0; o >>= 1) { if (tid < o) red[tid] = fmaxf(red[tid], red[tid + o]); __syncthreads(); }
    m = red[0]; __syncthreads();
    float zs = 0.f;
    for (int i = s + tid; i < e; i += 256) zs += __expf(att[i] - m);
    red[tid] = zs; __syncthreads();
    for (int o = 128; o > 0; o >>= 1) { if (tid < o) red[tid] += red[tid + o]; __syncthreads(); }
    float inv = 1.f / red[0];
    for (int i = s + tid; i < e; i += 256) w[i] = __expf(att[i] - m) * inv;
}

__global__ void k_reduce(const float* __restrict__ w, const hf* __restrict__ fs,
                         const hf* __restrict__ fv, const float* __restrict__ pos,
                         const int* __restrict__ start, int B, int Nn, float* __restrict__ out) {
    int b = blockIdx.x, j = threadIdx.x;
    int s = start[b], e = start[b + 1];
    size_t P = (size_t)Nn * 64;
    int c = j / 3, d = j - c * 3;
    float a256 = 0.f, a192 = 0.f, a3 = 0.f;
    for (int i = s; i < e; i++) {
        float wi = w[i];
        a256 = fmaf(wi, __half2float(fs[(size_t)i * 256 + j]), a256);
        if (j < 192)
            a192 = fmaf(wi, __half2float(fv[(size_t)d * P + (size_t)i * 64 + c]), a192);
        if (j < 3) a3 = fmaf(wi, pos[(size_t)i * 3 + j], a3);
    }
    out[(size_t)b * 256 + j] = a256;
    if (j < 192) out[(size_t)B * 256 + (size_t)b * 192 + j] = a192;
    if (j < 3)   out[(size_t)B * 256 + (size_t)B * 192 + (size_t)b * 3 + j] = a3;
}

// ---------------------------------------------------------------------------
extern "C" void kernel_launch(void* const* d_in, const int* in_sizes, int n_in,
                              void* d_out, int out_size) {
    const float* h_sca = (const float*)d_in[0];
    const float* h_vec = (const float*)d_in[1];
    const float* pos   = (const float*)d_in[2];
    const float* te    = (const float*)d_in[3];
    const float* W[26];
    for (int i = 4; i <= 25; i++) W[i] = (const float*)d_in[i];
    const int* tptr = (const int*)d_in[26];
    const int* bid  = (const int*)d_in[27];

    int n = in_sizes[0] / 256;
    int B = out_size / 451;

    hf *vecS, *viAs, *viNs, *uas, *uns, *vas, *vns, *scaX, *lrS, *Sas, *Sns;
    hf *nA1, *nN1, *nA2, *nN2, *Baug;
    float *Ga, *Gn, *att, *wgt;
    int* segs;
    cudaGetSymbolAddress((void**)&vecS, g_vecS);
    cudaGetSymbolAddress((void**)&viAs, g_viAs);
    cudaGetSymbolAddress((void**)&viNs, g_viNs);
    cudaGetSymbolAddress((void**)&uas,  g_uas);
    cudaGetSymbolAddress((void**)&uns,  g_uns);
    cudaGetSymbolAddress((void**)&vas,  g_vas);
    cudaGetSymbolAddress((void**)&vns,  g_vns);
    cudaGetSymbolAddress((void**)&scaX, g_scaX);
    cudaGetSymbolAddress((void**)&lrS,  g_lrS);
    cudaGetSymbolAddress((void**)&Sas,  g_Sas);
    cudaGetSymbolAddress((void**)&Sns,  g_Sns);
    cudaGetSymbolAddress((void**)&nA1,  g_nA1);
    cudaGetSymbolAddress((void**)&nN1,  g_nN1);
    cudaGetSymbolAddress((void**)&nA2,  g_nA2);
    cudaGetSymbolAddress((void**)&nN2,  g_nN2);
    cudaGetSymbolAddress((void**)&Baug, g_Baug);
    cudaGetSymbolAddress((void**)&Ga,   g_Ga);
    cudaGetSymbolAddress((void**)&Gn,   g_Gn);
    cudaGetSymbolAddress((void**)&att,  g_att);
    cudaGetSymbolAddress((void**)&wgt,  g_w);
    cudaGetSymbolAddress((void**)&segs, g_seg);

    static const int widx[15] = {4,15, 6,17, 7,18, 5,16, 9,20, 10,21, 23,24,22};
    static const int wnc[15]  = {64,64, 256,256, 64,64, 64,64, 64,64, 64,64, 256,64,64};
    static const int wk[15]   = {64,64, 320,320, 256,256, 64,64, 64,64, 64,64, 320,256,64};
    PPargs pa;
    size_t boff[15]; size_t acc = 0;
    for (int i = 0; i < 15; i++) {
        boff[i] = acc;
        pa.e[i] = PPk{W[widx[i]], Baug + acc, wnc[i], wk[i]};
        acc += (size_t)wnc[i] * wk[i];
    }
    const hf *B_a1Wv1 = Baug + boff[0],  *B_n1Wv1 = Baug + boff[1];
    const hf *B_a1Ws  = Baug + boff[2],  *B_n1Ws  = Baug + boff[3];
    const hf *B_a1Wg  = Baug + boff[4],  *B_n1Wg  = Baug + boff[5];
    const hf *B_a1Wv2 = Baug + boff[6],  *B_n1Wv2 = Baug + boff[7];
    const hf *B_a1Wd  = Baug + boff[8],  *B_n1Wd  = Baug + boff[9];
    const hf *B_a2Wv1 = Baug + boff[10], *B_n2Wv1 = Baug + boff[11];
    const hf *B_n2Ws  = Baug + boff[12], *B_n2Wg  = Baug + boff[13];
    const hf *B_n2Wv2 = Baug + boff[14];

    int M3 = 3 * n;
    int gv = (n + 127) / 128;
    int g3 = (M3 + 127) / 128;

    constexpr int SM64  = (2 * 128 * 40 + 2 * 64 * 40) * 2;    // 30720 B
    constexpr int SM128 = (2 * 128 * 40 + 2 * 128 * 40) * 2;   // 40960 B
    cudaFuncSetAttribute((const void*)gemm_f16<64>,
                         cudaFuncAttributeMaxDynamicSharedMemorySize, SM64);
    cudaFuncSetAttribute((const void*)gemm_f16<128>,
                         cudaFuncAttributeMaxDynamicSharedMemorySize, SM128);

    auto GS = [](const hf* a1, const hf* a2, int K1, const hf* b,
                 float* cf, hf* ch, hf* lh,
                 const float* bias, const float* gate, int act) {
        GSet g; g.A1 = a1; g.A2 = a2; g.K1 = K1; g.B = b;
        g.Cf = cf; g.Ch = ch; g.Lh = lh;
        g.bias = bias; g.gate = gate; g.act = act; return g;
    };
    auto VS = [](const hf* a, const hf* b, const hf* u, hf* c, hf* nrm) {
        VSet v; v.A = a; v.B = b; v.U = u; v.C = c; v.Nrm = nrm; return v;
    };

    k_prepack<<<dim3(64, 15), 256>>>(pa);
    k_prep<<<(n * 128 + 255) / 256, 256>>>(h_vec, h_sca, te, tptr, vecS, scaX, n);

    // vi pair: planes + norms
    gemm_vn3<<<dim3(gv, 2), 512>>>(
        VS(vecS, B_a1Wv1, nullptr, viAs, nA1),
        VS(vecS, B_n1Wv1, nullptr, viNs, nN1), n);
    // S pair: A = (norms | sca shared); net side also emits lrelu(Sn)
    gemm_f16<128><<<dim3(gv, 2, 2), 256, SM128>>>(
        GS(nA1, scaX, 64, B_a1Ws, nullptr, Sas, nullptr, nullptr, nullptr, 0),
        GS(nN1, scaX, 64, B_n1Ws, nullptr, Sns, lrS,     nullptr, nullptr, 0),
        n, 320, n, 256);
    // gates pair
    gemm_f16<64><<<dim3(gv, 2, 1), 256, SM64>>>(
        GS(Sas, nullptr, 256, B_a1Wg, Ga, nullptr, nullptr, W[8],  nullptr, 1),
        GS(Sns, nullptr, 256, B_n1Wg, Gn, nullptr, nullptr, W[19], nullptr, 1),
        n, 256, n, 64);
    // u pair (per-plane rows M3, gated)
    gemm_f16<64><<<dim3(g3, 2, 1), 256, SM64>>>(
        GS(viAs, nullptr, 64, B_a1Wv2, nullptr, uas, nullptr, nullptr, Ga, 0),
        GS(viNs, nullptr, 64, B_n1Wv2, nullptr, uns, nullptr, nullptr, Gn, 0),
        M3, 64, n, 64);
    // d pair with fused vn_lrelu -> v
    gemm_vn3<<<dim3(gv, 2), 512>>>(
        VS(uas, B_a1Wd, uas, vas, nullptr),
        VS(uns, B_n1Wd, uns, vns, nullptr), n);
    // vi2 pair: att -> norms only; net -> vi2n planes + norms
    gemm_vn3<<<dim3(gv, 2), 512>>>(
        VS(vas, B_a2Wv1, nullptr, nullptr, nA2),
        VS(vns, B_n2Wv1, nullptr, viAs, nN2), n);
    k_att<<<(n + 7) / 8, 256>>>(nA2, Sas, W[12], att, n);

    // fs = (norms2 | lrelu(Sn)) @ n2Ws -> Sas reuse
    {
        GSet g = GS(nN2, lrS, 64, B_n2Ws, nullptr, Sas, nullptr, nullptr, nullptr, 0);
        gemm_f16<128><<<dim3(gv, 1, 2), 256, SM128>>>(g, g, n, 320, n, 256);
    }
    // gate2 -> Ga reuse
    {
        GSet g = GS(Sas, nullptr, 256, B_n2Wg, Ga, nullptr, nullptr, W[25], nullptr, 1);
        gemm_f16<64><<<dim3(gv, 1, 1), 256, SM64>>>(g, g, n, 256, n, 64);
    }
    // fv = gate2 * (n2Wv2 @ vi2n) -> vas reuse
    {
        GSet g = GS(viAs, nullptr, 64, B_n2Wv2, nullptr, vas, nullptr, nullptr, Ga, 0);
        gemm_f16<64><<<dim3(g3, 1, 1), 256, SM64>>>(g, g, M3, 64, n, 64);
    }

    k_segstart<<<(B + 1 + 255) / 256, 256>>>(bid, n, B, segs);
    k_softmax<<<B, 256>>>(att, segs, wgt);
    k_reduce<<<B, 256>>>(wgt, Sas, vas, pos, segs, B, n, (float*)d_out);
}

// round 13
// speedup vs baseline: 2.1018x; 1.0623x over previous
#include <cuda_runtime.h>
#include <cuda_fp16.h>
#include <math.h>
#include <stdint.h>

typedef __half hf;

#define MAXN   120000
#define SLOPEF 0.01f
#define EPSF   1e-6f
#define PVMAX  (3*MAXN*64)

// ---------------- static device scratch (plain fp16) ------------------------
__device__ __align__(16) hf    g_vecS[PVMAX];
__device__ __align__(16) hf    g_viAs[PVMAX];
__device__ __align__(16) hf    g_viNs[PVMAX];   // later: vi2n
__device__ __align__(16) hf    g_uas [PVMAX];
__device__ __align__(16) hf    g_uns [PVMAX];
__device__ __align__(16) hf    g_vas [PVMAX];   // later: fv
__device__ __align__(16) hf    g_vns [PVMAX];
__device__ __align__(16) hf    g_scaX[MAXN*256];
__device__ __align__(16) hf    g_lrS [MAXN*256];
__device__ __align__(16) hf    g_Sas [MAXN*256]; // later: fs
__device__ __align__(16) hf    g_Sns [MAXN*256];
__device__ __align__(16) hf    g_nA1 [MAXN*64];
__device__ __align__(16) hf    g_nN1 [MAXN*64];
__device__ __align__(16) hf    g_nA2 [MAXN*64];
__device__ __align__(16) hf    g_nN2 [MAXN*64];
__device__ __align__(16) hf    g_Baug[524288];
__device__ float g_Ga  [MAXN*64];
__device__ float g_Gn  [MAXN*64];
__device__ float g_att [MAXN];
__device__ float g_w   [MAXN];
__device__ int   g_seg [4100];

// ---------------- helpers ----------------
__device__ __forceinline__ uint32_t smem_u32(const void* p) {
    return (uint32_t)__cvta_generic_to_shared(p);
}
__device__ __forceinline__ void store_h2(hf* H, size_t o, float v0, float v1) {
    __half2 t; t.x = __float2half(v0); t.y = __float2half(v1);
    *(__half2*)(H + o) = t;
}

#define MMA16816(d, a, b)                                                     \
    asm volatile("mma.sync.aligned.m16n8k16.row.col.f32.f16.f16.f32 "        \
        "{%0,%1,%2,%3}, {%4,%5,%6,%7}, {%8,%9}, {%0,%1,%2,%3};"              \
        : "+f"((d)[0]), "+f"((d)[1]), "+f"((d)[2]), "+f"((d)[3])             \
        : "r"((a)[0]), "r"((a)[1]), "r"((a)[2]), "r"((a)[3]),                \
          "r"((b)[0]), "r"((b)[1]))

#define LDSM_X4(r0, r1, r2, r3, addr)                                        \
    asm volatile("ldmatrix.sync.aligned.m8n8.x4.shared.b16 {%0,%1,%2,%3}, [%4];" \
        : "=r"(r0), "=r"(r1), "=r"(r2), "=r"(r3) : "r"(addr))

#define CP_ASYNC16(sa, ga)                                                   \
    asm volatile("cp.async.cg.shared.global [%0], [%1], 16;" :: "r"(sa), "l"(ga))
#define CP_ASYNC16_P(sa, ga, p)                                              \
    asm volatile("cp.async.cg.shared.global [%0], [%1], 16, %2;" :: "r"(sa), "l"(ga), "r"(p))
#define CP_COMMIT() asm volatile("cp.async.commit_group;")
#define CP_WAIT0()  asm volatile("cp.async.wait_group 0;")

// ---------------------------------------------------------------------------
// fp16 HMMA GEMM with two A regions: cols [0,K1) from A1, [K1,K) from A2.
// C[M, NCfull] tile (128 x NC) at column offset blockIdx.z*NC.
// K stages of 64 columns (K, K1 multiples of 64). Smem rows pitch 72 (144B,
// conflict-free for ldmatrix).
// NC=128: 512 thr, 16 warps 4(M)x4(N), warp tile 32x32, minBlocks 2.
// NC=64:  256 thr,  8 warps 4(M)x2(N), warp tile 32x32, minBlocks 3.
// ---------------------------------------------------------------------------
struct GSet {
    const hf *A1, *A2;
    int K1;
    const hf* B;
    float* Cf; hf* Ch;
    hf* Lh;                          // optional lrelu side-output
    const float *bias, *gate;
    int act;
};

template <int NC>
__global__ void __launch_bounds__(NC >= 128 ? 512 : 256, NC >= 128 ? 2 : 3)
gemm_f16(GSet s0, GSet s1, int M, int K, int Nn, int NCfull) {
    constexpr int NTH   = (NC >= 128) ? 512 : 256;
    constexpr int NWN   = (NC >= 128) ? 4 : 2;
    constexpr int WCOLS = NC / NWN;          // 32
    constexpr int NT    = WCOLS / 8;         // 4
    constexpr int A_ST  = 128 * 72;
    constexpr int B_ST  = NC * 72;

    extern __shared__ hf sm[];
    hf* smA = sm;
    hf* smB = sm + 2 * A_ST;

    const int tid = threadIdx.x;
    const int lane = tid & 31, wid = tid >> 5;
    const int wm = wid / NWN, wn = wid % NWN;
    const GSet S = (blockIdx.y == 0) ? s0 : s1;
    const int m0 = blockIdx.x * 128;
    const int n0 = blockIdx.z * NC;
    const int ST = K >> 6;
    const int K2w = K - S.K1;

    float acc[2][NT][4];
#pragma unroll
    for (int i = 0; i < 2; i++)
#pragma unroll
        for (int j = 0; j < NT; j++)
#pragma unroll
            for (int k = 0; k < 4; k++) acc[i][j][k] = 0.f;

    auto load_stage = [&](int s, int buf) {
        int kof = s * 64;
        const hf* base; int stride, col;
        if (kof < S.K1) { base = S.A1; stride = S.K1; col = kof; }
        else            { base = S.A2; stride = K2w;  col = kof - S.K1; }
        for (int i = tid; i < 1024; i += NTH) {      // A: 128 rows x 8 chunks
            int r = i >> 3, sg = i & 7;
            int m = m0 + r;
            uint32_t sa = smem_u32(smA + buf * A_ST + r * 72 + sg * 8);
            const hf* ga = base + ((m < M) ? ((size_t)m * stride + col + sg * 8) : 0);
            CP_ASYNC16_P(sa, ga, (m < M) ? 16 : 0);
        }
        for (int i = tid; i < NC * 8; i += NTH) {    // B: NC rows x 8 chunks
            int r = i >> 3, sg = i & 7;
            uint32_t sa = smem_u32(smB + buf * B_ST + r * 72 + sg * 8);
            CP_ASYNC16(sa, S.B + (size_t)(n0 + r) * K + kof + sg * 8);
        }
        CP_COMMIT();
    };

    // hoisted per-warp LDSM base offsets (element units)
    uint32_t aBase = smem_u32(smA);
    uint32_t bBase = smem_u32(smB);
    int aOff[2];
#pragma unroll
    for (int mt = 0; mt < 2; mt++)
        aOff[mt] = (wm * 32 + mt * 16 + (lane & 15)) * 72 + (lane >> 4) * 8;
    int bOff;
    {
        int g = lane >> 3, r = lane & 7;
        int nt8 = (g >> 1), ko = (g & 1) * 8;
        bOff = (wn * WCOLS + nt8 * 8 + r) * 72 + ko;
    }

    load_stage(0, 0);
    for (int s = 0; s < ST; s++) {
        int buf = s & 1;
        CP_WAIT0();
        __syncthreads();
        if (s + 1 < ST) load_stage(s + 1, buf ^ 1);
        uint32_t aB = aBase + buf * (A_ST * 2);
        uint32_t bB = bBase + buf * (B_ST * 2);
#pragma unroll
        for (int kk = 0; kk < 4; kk++) {
            const int k16 = kk * 16;
            uint32_t a[2][4];
#pragma unroll
            for (int mt = 0; mt < 2; mt++)
                LDSM_X4(a[mt][0], a[mt][1], a[mt][2], a[mt][3],
                        aB + (aOff[mt] + k16) * 2);
            uint32_t b[NT][2];
#pragma unroll
            for (int half = 0; half < NT / 2; half++) {
                uint32_t r0, r1, r2, r3;
                LDSM_X4(r0, r1, r2, r3, bB + (bOff + half * 16 * 72 + k16) * 2);
                b[half * 2 + 0][0] = r0; b[half * 2 + 0][1] = r1;
                b[half * 2 + 1][0] = r2; b[half * 2 + 1][1] = r3;
            }
#pragma unroll
            for (int mt = 0; mt < 2; mt++)
#pragma unroll
                for (int nt = 0; nt < NT; nt++)
                    MMA16816(acc[mt][nt], a[mt], b[nt]);
        }
    }

#pragma unroll
    for (int mt = 0; mt < 2; mt++) {
#pragma unroll
        for (int hh = 0; hh < 2; hh++) {
            int m = m0 + wm * 32 + mt * 16 + (lane >> 2) + hh * 8;
            if (m >= M) continue;
            int node = m % Nn;
#pragma unroll
            for (int nt = 0; nt < NT; nt++) {
                int col = n0 + wn * WCOLS + nt * 8 + (lane & 3) * 2;
                float v0 = acc[mt][nt][hh * 2 + 0];
                float v1 = acc[mt][nt][hh * 2 + 1];
                if (S.act) {
                    v0 = 1.f / (1.f + __expf(-(v0 + S.bias[col])));
                    v1 = 1.f / (1.f + __expf(-(v1 + S.bias[col + 1])));
                }
                if (S.gate) {
                    v0 *= S.gate[(size_t)node * 64 + col];
                    v1 *= S.gate[(size_t)node * 64 + col + 1];
                }
                size_t o = (size_t)m * NCfull + col;
                if (S.Cf) *(float2*)(S.Cf + o) = make_float2(v0, v1);
                if (S.Ch) store_h2(S.Ch, o, v0, v1);
                if (S.Lh) {
                    float l0 = (v0 >= 0.f) ? v0 : SLOPEF * v0;
                    float l1 = (v1 >= 0.f) ? v1 : SLOPEF * v1;
                    store_h2(S.Lh, o, l0, l1);
                }
            }
        }
    }
}

// ---------------------------------------------------------------------------
// 3-plane VN GEMM (K=64, NC=64): one block = 128 nodes x 64 cols, ONE stage
// per plane (3 stages). B resident in smem. 512 threads, 16 warps (8M x 2N),
// warp tile 16x32. Fused vn_lrelu / plane / norm epilogue.
// ---------------------------------------------------------------------------
struct VSet {
    const hf *A;                // planes [d][n][64]
    const hf *B;                // [64][64] fp16
    const hf *U;                // vn_lrelu input planes (or null)
    hf *C;                      // plane outputs (or null)
    hf *Nrm;                    // norm outputs [n,64] (or null)
};

__global__ void __launch_bounds__(512, 2)
gemm_vn3(VSet s0, VSet s1, int Nn) {
    __shared__ hf Bs[64 * 72];
    __shared__ hf As[2][128 * 72];
    const int tid = threadIdx.x, lane = tid & 31, wid = tid >> 5;
    const int wm = wid >> 1, wn = wid & 1;       // 8 x 2
    const VSet S = blockIdx.y ? s1 : s0;
    const int m0 = blockIdx.x * 128;
    const size_t P = (size_t)Nn * 64;

    // B resident: 64 rows x 64 fp16 = 8 x 16B per row (512 chunks)
    {
        int r = tid >> 3, c8 = tid & 7;
        CP_ASYNC16(smem_u32(Bs + r * 72 + c8 * 8), S.B + r * 64 + c8 * 8);
    }
    CP_COMMIT();

    float acc[3][4][4];
#pragma unroll
    for (int d = 0; d < 3; d++)
#pragma unroll
        for (int j = 0; j < 4; j++)
#pragma unroll
            for (int k = 0; k < 4; k++) acc[d][j][k] = 0.f;

    auto loadA = [&](int d, int buf) {
        for (int i = tid; i < 1024; i += 512) {
            int r = i >> 3, sg = i & 7;
            int m = m0 + r;
            uint32_t sa = smem_u32(As[buf] + r * 72 + sg * 8);
            const hf* ga = S.A + d * P + ((m < Nn) ? ((size_t)m * 64 + sg * 8) : 0);
            CP_ASYNC16_P(sa, ga, (m < Nn) ? 16 : 0);
        }
        CP_COMMIT();
    };

    int aOff = (wm * 16 + (lane & 15)) * 72 + (lane >> 4) * 8;
    int bOff;
    {
        int g = lane >> 3, r = lane & 7;
        int nt8 = (g >> 1), ko = (g & 1) * 8;
        bOff = (wn * 32 + nt8 * 8 + r) * 72 + ko;
    }
    uint32_t aBase = smem_u32(As[0]);
    uint32_t bBase = smem_u32(Bs);

    loadA(0, 0);
    for (int d = 0; d < 3; d++) {
        int buf = d & 1;
        CP_WAIT0();
        __syncthreads();
        if (d + 1 < 3) loadA(d + 1, buf ^ 1);
        uint32_t aB = aBase + buf * (128 * 72 * 2);
#pragma unroll
        for (int kk = 0; kk < 4; kk++) {
            const int k16 = kk * 16;
            uint32_t a[4];
            LDSM_X4(a[0], a[1], a[2], a[3], aB + (aOff + k16) * 2);
            uint32_t b[4][2];
#pragma unroll
            for (int half = 0; half < 2; half++) {
                uint32_t r0, r1, r2, r3;
                LDSM_X4(r0, r1, r2, r3, bBase + (bOff + half * 16 * 72 + k16) * 2);
                b[half * 2 + 0][0] = r0; b[half * 2 + 0][1] = r1;
                b[half * 2 + 1][0] = r2; b[half * 2 + 1][1] = r3;
            }
#pragma unroll
            for (int nt = 0; nt < 4; nt++)
                MMA16816(acc[d][nt], a, b[nt]);
        }
    }

    // -------- fused epilogue --------
#pragma unroll
    for (int hh = 0; hh < 2; hh++) {
        int m = m0 + wm * 16 + (lane >> 2) + hh * 8;
        if (m >= Nn) continue;
#pragma unroll
        for (int nt = 0; nt < 4; nt++) {
            int col = wn * 32 + nt * 8 + (lane & 3) * 2;
            float v[3][2];
#pragma unroll
            for (int d = 0; d < 3; d++) {
                v[d][0] = acc[d][nt][hh * 2 + 0];
                v[d][1] = acc[d][nt][hh * 2 + 1];
            }
            if (S.U) {
                float u[3][2];
#pragma unroll
                for (int d = 0; d < 3; d++) {
                    __half2 uh = *(const __half2*)(S.U + d * P + (size_t)m * 64 + col);
                    u[d][0] = __half2float(uh.x);
                    u[d][1] = __half2float(uh.y);
                }
#pragma unroll
                for (int e = 0; e < 2; e++) {
                    float dot = u[0][e] * v[0][e] + u[1][e] * v[1][e] + u[2][e] * v[2][e];
                    float dsq = v[0][e] * v[0][e] + v[1][e] * v[1][e] + v[2][e] * v[2][e];
                    float sc = dot / (dsq + EPSF);
#pragma unroll
                    for (int d = 0; d < 3; d++) {
                        float x = u[d][e];
                        float r = (dot >= 0.f) ? x
                                 : (SLOPEF * x + (1.f - SLOPEF) * (x - sc * v[d][e]));
                        v[d][e] = r;
                    }
                }
            }
            if (S.C) {
#pragma unroll
                for (int d = 0; d < 3; d++)
                    store_h2(S.C, d * P + (size_t)m * 64 + col, v[d][0], v[d][1]);
            }
            if (S.Nrm) {
                float n0 = sqrtf(v[0][0] * v[0][0] + v[1][0] * v[1][0] + v[2][0] * v[2][0]);
                float n1 = sqrtf(v[0][1] * v[0][1] + v[1][1] * v[1][1] + v[2][1] * v[2][1]);
                store_h2(S.Nrm, (size_t)m * 64 + col, n0, n1);
            }
        }
    }
}

// ---------------------------------------------------------------------------
// weight prepack: W(nc,k) fp32 -> fp16
// ---------------------------------------------------------------------------
struct PPk { const float* w; hf* o; int nc; int k; };
struct PPargs { PPk e[15]; };
__global__ void k_prepack(PPargs pa) {
    PPk p = pa.e[blockIdx.y];
    int tot = p.nc * p.k;
    for (int i = blockIdx.x * 256 + threadIdx.x; i < tot; i += gridDim.x * 256)
        p.o[i] = __float2half(p.w[i]);
}

// ---------------------------------------------------------------------------
// prep: vec -> fp16 planes; sca = h_sca + te[t] -> fp16 [n,256]
// ---------------------------------------------------------------------------
__global__ void k_prep(const float* __restrict__ h_vec, const float* __restrict__ h_sca,
                       const float* __restrict__ te, const int* __restrict__ tptr,
                       hf* __restrict__ vh, hf* __restrict__ scah, int Nn) {
    int i = blockIdx.x * 256 + threadIdx.x;
    int half = Nn * 64;
    if (i < half) {
        int node = i >> 6, c = i & 63;
#pragma unroll
        for (int d = 0; d < 3; d++) {
            float x = h_vec[(size_t)node * 192 + c * 3 + d];
            vh[(size_t)d * Nn * 64 + (size_t)node * 64 + c] = __float2half(x);
        }
    } else if (i < 2 * half) {
        int j = i - half;
        int node = j >> 6, q4 = (j & 63) * 4;
        int t = *tptr;
        float4 hs = *(const float4*)(h_sca + (size_t)node * 256 + q4);
        float4 tv = *(const float4*)(te + (size_t)t * 256 + q4);
        size_t o = (size_t)node * 256 + q4;
        store_h2(scah, o,     hs.x + tv.x, hs.y + tv.y);
        store_h2(scah, o + 2, hs.z + tv.z, hs.w + tv.w);
    }
}

// att[n] = Ws[0:64].|vi2a| + Ws[64:320].lrelu(Sa)
__global__ void k_att(const hf* __restrict__ Nh, const hf* __restrict__ Sa,
                      const float* __restrict__ Ws, float* __restrict__ att, int Nn) {
    __shared__ float ws[320];
    int tid = threadIdx.x, w = tid >> 5, lane = tid & 31;
    for (int i = tid; i < 320; i += 256) ws[i] = Ws[i];
    __syncthreads();
    int node = blockIdx.x * 8 + w;
    if (node >= Nn) return;
    float p = 0.f;
    for (int c = lane; c < 64; c += 32)
        p = fmaf(ws[c], __half2float(Nh[(size_t)node * 64 + c]), p);
    for (int k = lane; k < 256; k += 32) {
        float sv = __half2float(Sa[(size_t)node * 256 + k]);
        sv = (sv >= 0.f) ? sv : SLOPEF * sv;
        p = fmaf(ws[64 + k], sv, p);
    }
#pragma unroll
    for (int o = 16; o > 0; o >>= 1) p += __shfl_down_sync(0xffffffff, p, o);
    if (lane == 0) att[node] = p;
}

__global__ void k_segstart(const int* __restrict__ bid, int n, int B, int* __restrict__ start) {
    int b = blockIdx.x * blockDim.x + threadIdx.x;
    if (b > B) return;
    int lo = 0, hi = n;
    while (lo < hi) { int mid = (lo + hi) >> 1; if (bid[mid] < b) lo = mid + 1; else hi = mid; }
    start[b] = lo;
}

__global__ void k_softmax(const float* __restrict__ att, const int* __restrict__ start,
                          float* __restrict__ w) {
    int b = blockIdx.x;
    int s = start[b], e = start[b + 1];
    if (s >= e) return;
    __shared__ float red[256];
    int tid = threadIdx.x;
    float m = -INFINITY;
    for (int i = s + tid; i < e; i += 256) m = fmaxf(m, att[i]);
    red[tid] = m; __syncthreads();
    for (int o = 128; o > 0; o >>= 1) { if (tid < o) red[tid] = fmaxf(red[tid], red[tid + o]); __syncthreads(); }
    m = red[0]; __syncthreads();
    float zs = 0.f;
    for (int i = s + tid; i < e; i += 256) zs += __expf(att[i] - m);
    red[tid] = zs; __syncthreads();
    for (int o = 128; o > 0; o >>= 1) { if (tid < o) red[tid] += red[tid + o]; __syncthreads(); }
    float inv = 1.f / red[0];
    for (int i = s + tid; i < e; i += 256) w[i] = __expf(att[i] - m) * inv;
}

__global__ void k_reduce(const float* __restrict__ w, const hf* __restrict__ fs,
                         const hf* __restrict__ fv, const float* __restrict__ pos,
                         const int* __restrict__ start, int B, int Nn, float* __restrict__ out) {
    int b = blockIdx.x, j = threadIdx.x;
    int s = start[b], e = start[b + 1];
    size_t P = (size_t)Nn * 64;
    int c = j / 3, d = j - c * 3;
    float a256 = 0.f, a192 = 0.f, a3 = 0.f;
    for (int i = s; i < e; i++) {
        float wi = w[i];
        a256 = fmaf(wi, __half2float(fs[(size_t)i * 256 + j]), a256);
        if (j < 192)
            a192 = fmaf(wi, __half2float(fv[(size_t)d * P + (size_t)i * 64 + c]), a192);
        if (j < 3) a3 = fmaf(wi, pos[(size_t)i * 3 + j], a3);
    }
    out[(size_t)b * 256 + j] = a256;
    if (j < 192) out[(size_t)B * 256 + (size_t)b * 192 + j] = a192;
    if (j < 3)   out[(size_t)B * 256 + (size_t)B * 192 + (size_t)b * 3 + j] = a3;
}

// ---------------------------------------------------------------------------
extern "C" void kernel_launch(void* const* d_in, const int* in_sizes, int n_in,
                              void* d_out, int out_size) {
    const float* h_sca = (const float*)d_in[0];
    const float* h_vec = (const float*)d_in[1];
    const float* pos   = (const float*)d_in[2];
    const float* te    = (const float*)d_in[3];
    const float* W[26];
    for (int i = 4; i <= 25; i++) W[i] = (const float*)d_in[i];
    const int* tptr = (const int*)d_in[26];
    const int* bid  = (const int*)d_in[27];

    int n = in_sizes[0] / 256;
    int B = out_size / 451;

    hf *vecS, *viAs, *viNs, *uas, *uns, *vas, *vns, *scaX, *lrS, *Sas, *Sns;
    hf *nA1, *nN1, *nA2, *nN2, *Baug;
    float *Ga, *Gn, *att, *wgt;
    int* segs;
    cudaGetSymbolAddress((void**)&vecS, g_vecS);
    cudaGetSymbolAddress((void**)&viAs, g_viAs);
    cudaGetSymbolAddress((void**)&viNs, g_viNs);
    cudaGetSymbolAddress((void**)&uas,  g_uas);
    cudaGetSymbolAddress((void**)&uns,  g_uns);
    cudaGetSymbolAddress((void**)&vas,  g_vas);
    cudaGetSymbolAddress((void**)&vns,  g_vns);
    cudaGetSymbolAddress((void**)&scaX, g_scaX);
    cudaGetSymbolAddress((void**)&lrS,  g_lrS);
    cudaGetSymbolAddress((void**)&Sas,  g_Sas);
    cudaGetSymbolAddress((void**)&Sns,  g_Sns);
    cudaGetSymbolAddress((void**)&nA1,  g_nA1);
    cudaGetSymbolAddress((void**)&nN1,  g_nN1);
    cudaGetSymbolAddress((void**)&nA2,  g_nA2);
    cudaGetSymbolAddress((void**)&nN2,  g_nN2);
    cudaGetSymbolAddress((void**)&Baug, g_Baug);
    cudaGetSymbolAddress((void**)&Ga,   g_Ga);
    cudaGetSymbolAddress((void**)&Gn,   g_Gn);
    cudaGetSymbolAddress((void**)&att,  g_att);
    cudaGetSymbolAddress((void**)&wgt,  g_w);
    cudaGetSymbolAddress((void**)&segs, g_seg);

    static const int widx[15] = {4,15, 6,17, 7,18, 5,16, 9,20, 10,21, 23,24,22};
    static const int wnc[15]  = {64,64, 256,256, 64,64, 64,64, 64,64, 64,64, 256,64,64};
    static const int wk[15]   = {64,64, 320,320, 256,256, 64,64, 64,64, 64,64, 320,256,64};
    PPargs pa;
    size_t boff[15]; size_t acc = 0;
    for (int i = 0; i < 15; i++) {
        boff[i] = acc;
        pa.e[i] = PPk{W[widx[i]], Baug + acc, wnc[i], wk[i]};
        acc += (size_t)wnc[i] * wk[i];
    }
    const hf *B_a1Wv1 = Baug + boff[0],  *B_n1Wv1 = Baug + boff[1];
    const hf *B_a1Ws  = Baug + boff[2],  *B_n1Ws  = Baug + boff[3];
    const hf *B_a1Wg  = Baug + boff[4],  *B_n1Wg  = Baug + boff[5];
    const hf *B_a1Wv2 = Baug + boff[6],  *B_n1Wv2 = Baug + boff[7];
    const hf *B_a1Wd  = Baug + boff[8],  *B_n1Wd  = Baug + boff[9];
    const hf *B_a2Wv1 = Baug + boff[10], *B_n2Wv1 = Baug + boff[11];
    const hf *B_n2Ws  = Baug + boff[12], *B_n2Wg  = Baug + boff[13];
    const hf *B_n2Wv2 = Baug + boff[14];

    int M3 = 3 * n;
    int gv = (n + 127) / 128;
    int g3 = (M3 + 127) / 128;

    constexpr int SM64  = (2 * 128 * 72 + 2 * 64 * 72) * 2;    // 55296 B
    constexpr int SM128 = (2 * 128 * 72 + 2 * 128 * 72) * 2;   // 73728 B
    cudaFuncSetAttribute((const void*)gemm_f16<64>,
                         cudaFuncAttributeMaxDynamicSharedMemorySize, SM64);
    cudaFuncSetAttribute((const void*)gemm_f16<128>,
                         cudaFuncAttributeMaxDynamicSharedMemorySize, SM128);

    auto GS = [](const hf* a1, const hf* a2, int K1, const hf* b,
                 float* cf, hf* ch, hf* lh,
                 const float* bias, const float* gate, int act) {
        GSet g; g.A1 = a1; g.A2 = a2; g.K1 = K1; g.B = b;
        g.Cf = cf; g.Ch = ch; g.Lh = lh;
        g.bias = bias; g.gate = gate; g.act = act; return g;
    };
    auto VS = [](const hf* a, const hf* b, const hf* u, hf* c, hf* nrm) {
        VSet v; v.A = a; v.B = b; v.U = u; v.C = c; v.Nrm = nrm; return v;
    };

    k_prepack<<<dim3(64, 15), 256>>>(pa);
    k_prep<<<(n * 128 + 255) / 256, 256>>>(h_vec, h_sca, te, tptr, vecS, scaX, n);

    // vi pair: planes + norms
    gemm_vn3<<<dim3(gv, 2), 512>>>(
        VS(vecS, B_a1Wv1, nullptr, viAs, nA1),
        VS(vecS, B_n1Wv1, nullptr, viNs, nN1), n);
    // S pair: A = (norms | sca shared); net side also emits lrelu(Sn)
    gemm_f16<128><<<dim3(gv, 2, 2), 512, SM128>>>(
        GS(nA1, scaX, 64, B_a1Ws, nullptr, Sas, nullptr, nullptr, nullptr, 0),
        GS(nN1, scaX, 64, B_n1Ws, nullptr, Sns, lrS,     nullptr, nullptr, 0),
        n, 320, n, 256);
    // gates pair
    gemm_f16<64><<<dim3(gv, 2, 1), 256, SM64>>>(
        GS(Sas, nullptr, 256, B_a1Wg, Ga, nullptr, nullptr, W[8],  nullptr, 1),
        GS(Sns, nullptr, 256, B_n1Wg, Gn, nullptr, nullptr, W[19], nullptr, 1),
        n, 256, n, 64);
    // u pair (per-plane rows M3, gated)
    gemm_f16<64><<<dim3(g3, 2, 1), 256, SM64>>>(
        GS(viAs, nullptr, 64, B_a1Wv2, nullptr, uas, nullptr, nullptr, Ga, 0),
        GS(viNs, nullptr, 64, B_n1Wv2, nullptr, uns, nullptr, nullptr, Gn, 0),
        M3, 64, n, 64);
    // d pair with fused vn_lrelu -> v
    gemm_vn3<<<dim3(gv, 2), 512>>>(
        VS(uas, B_a1Wd, uas, vas, nullptr),
        VS(uns, B_n1Wd, uns, vns, nullptr), n);
    // vi2 pair: att -> norms only; net -> vi2n planes + norms
    gemm_vn3<<<dim3(gv, 2), 512>>>(
        VS(vas, B_a2Wv1, nullptr, nullptr, nA2),
        VS(vns, B_n2Wv1, nullptr, viAs, nN2), n);
    k_att<<<(n + 7) / 8, 256>>>(nA2, Sas, W[12], att, n);

    // fs = (norms2 | lrelu(Sn)) @ n2Ws -> Sas reuse
    {
        GSet g = GS(nN2, lrS, 64, B_n2Ws, nullptr, Sas, nullptr, nullptr, nullptr, 0);
        gemm_f16<128><<<dim3(gv, 1, 2), 512, SM128>>>(g, g, n, 320, n, 256);
    }
    // gate2 -> Ga reuse
    {
        GSet g = GS(Sas, nullptr, 256, B_n2Wg, Ga, nullptr, nullptr, W[25], nullptr, 1);
        gemm_f16<64><<<dim3(gv, 1, 1), 256, SM64>>>(g, g, n, 256, n, 64);
    }
    // fv = gate2 * (n2Wv2 @ vi2n) -> vas reuse
    {
        GSet g = GS(viAs, nullptr, 64, B_n2Wv2, nullptr, vas, nullptr, nullptr, Ga, 0);
        gemm_f16<64><<<dim3(g3, 1, 1), 256, SM64>>>(g, g, M3, 64, n, 64);
    }

    k_segstart<<<(B + 1 + 255) / 256, 256>>>(bid, n, B, segs);
    k_softmax<<<B, 256>>>(att, segs, wgt);
    k_reduce<<<B, 256>>>(wgt, Sas, vas, pos, segs, B, n, (float*)d_out);
}

// round 14
// speedup vs baseline: 2.1474x; 1.0217x over previous
#include <cuda_runtime.h>
#include <cuda_fp16.h>
#include <math.h>
#include <stdint.h>

typedef __half hf;

#define MAXN   120000
#define SLOPEF 0.01f
#define EPSF   1e-6f
#define PVMAX  (3*MAXN*64)

// ---------------- static device scratch (plain fp16) ------------------------
__device__ __align__(16) hf    g_vecS[PVMAX];
__device__ __align__(16) hf    g_viAs[PVMAX];
__device__ __align__(16) hf    g_viNs[PVMAX];   // later: vi2n
__device__ __align__(16) hf    g_uas [PVMAX];
__device__ __align__(16) hf    g_uns [PVMAX];
__device__ __align__(16) hf    g_vas [PVMAX];   // later: fv
__device__ __align__(16) hf    g_vns [PVMAX];
__device__ __align__(16) hf    g_scaX[MAXN*256];
__device__ __align__(16) hf    g_lrS [MAXN*256];
__device__ __align__(16) hf    g_Sas [MAXN*256]; // later: fs
__device__ __align__(16) hf    g_Sns [MAXN*256];
__device__ __align__(16) hf    g_nA1 [MAXN*64];
__device__ __align__(16) hf    g_nN1 [MAXN*64];
__device__ __align__(16) hf    g_nA2 [MAXN*64];
__device__ __align__(16) hf    g_nN2 [MAXN*64];
__device__ __align__(16) hf    g_Baug[524288];
__device__ float g_Ga  [MAXN*64];
__device__ float g_Gn  [MAXN*64];
__device__ float g_att [MAXN];
__device__ float g_w   [MAXN];
__device__ int   g_seg [4100];

// ---------------- helpers ----------------
__device__ __forceinline__ uint32_t smem_u32(const void* p) {
    return (uint32_t)__cvta_generic_to_shared(p);
}
__device__ __forceinline__ void store_h2(hf* H, size_t o, float v0, float v1) {
    __half2 t; t.x = __float2half(v0); t.y = __float2half(v1);
    *(__half2*)(H + o) = t;
}

#define MMA16816(d, a, b)                                                     \
    asm volatile("mma.sync.aligned.m16n8k16.row.col.f32.f16.f16.f32 "        \
        "{%0,%1,%2,%3}, {%4,%5,%6,%7}, {%8,%9}, {%0,%1,%2,%3};"              \
        : "+f"((d)[0]), "+f"((d)[1]), "+f"((d)[2]), "+f"((d)[3])             \
        : "r"((a)[0]), "r"((a)[1]), "r"((a)[2]), "r"((a)[3]),                \
          "r"((b)[0]), "r"((b)[1]))

#define LDSM_X4(r0, r1, r2, r3, addr)                                        \
    asm volatile("ldmatrix.sync.aligned.m8n8.x4.shared.b16 {%0,%1,%2,%3}, [%4];" \
        : "=r"(r0), "=r"(r1), "=r"(r2), "=r"(r3) : "r"(addr))

#define CP_ASYNC16(sa, ga)                                                   \
    asm volatile("cp.async.cg.shared.global [%0], [%1], 16;" :: "r"(sa), "l"(ga))
#define CP_ASYNC16_P(sa, ga, p)                                              \
    asm volatile("cp.async.cg.shared.global [%0], [%1], 16, %2;" :: "r"(sa), "l"(ga), "r"(p))
#define CP_COMMIT() asm volatile("cp.async.commit_group;")
#define CP_WAIT0()  asm volatile("cp.async.wait_group 0;")
#define CP_WAIT1()  asm volatile("cp.async.wait_group 1;")
#define CP_WAIT2()  asm volatile("cp.async.wait_group 2;")

// ---------------------------------------------------------------------------
// fp16 HMMA GEMM with two A regions: cols [0,K1) from A1, [K1,K) from A2.
// C[M, NCfull] tile (128 x NC) at column offset blockIdx.z*NC.
// K stages of 64 columns. Smem rows pitch 72 (conflict-free ldmatrix).
// NC=128: 512 thr, 16 warps 4x4, warp 32x32, 3-stage pipeline, minBlocks 2.
// NC=64:  256 thr,  8 warps 4x2, warp 32x32, 2-stage pipeline, minBlocks 3.
// ---------------------------------------------------------------------------
struct GSet {
    const hf *A1, *A2;
    int K1;
    const hf* B;
    float* Cf; hf* Ch;
    hf* Lh;                          // optional lrelu side-output
    const float *bias, *gate;
    int act;
};

template <int NC>
__global__ void __launch_bounds__(NC >= 128 ? 512 : 256, NC >= 128 ? 2 : 3)
gemm_f16(GSet s0, GSet s1, int M, int K, int Nn, int NCfull) {
    constexpr int NTH   = (NC >= 128) ? 512 : 256;
    constexpr int NST   = (NC >= 128) ? 3 : 2;
    constexpr int NWN   = (NC >= 128) ? 4 : 2;
    constexpr int WCOLS = NC / NWN;          // 32
    constexpr int NT    = WCOLS / 8;         // 4
    constexpr int A_ST  = 128 * 72;
    constexpr int B_ST  = NC * 72;

    extern __shared__ hf sm[];
    hf* smA = sm;
    hf* smB = sm + NST * A_ST;

    const int tid = threadIdx.x;
    const int lane = tid & 31, wid = tid >> 5;
    const int wm = wid / NWN, wn = wid % NWN;
    const GSet S = (blockIdx.y == 0) ? s0 : s1;
    const int m0 = blockIdx.x * 128;
    const int n0 = blockIdx.z * NC;
    const int ST = K >> 6;
    const int K2w = K - S.K1;

    float acc[2][NT][4];
#pragma unroll
    for (int i = 0; i < 2; i++)
#pragma unroll
        for (int j = 0; j < NT; j++)
#pragma unroll
            for (int k = 0; k < 4; k++) acc[i][j][k] = 0.f;

    auto load_stage = [&](int s, int buf) {
        int kof = s * 64;
        const hf* base; int stride, col;
        if (kof < S.K1) { base = S.A1; stride = S.K1; col = kof; }
        else            { base = S.A2; stride = K2w;  col = kof - S.K1; }
        for (int i = tid; i < 1024; i += NTH) {      // A: 128 rows x 8 chunks
            int r = i >> 3, sg = i & 7;
            int m = m0 + r;
            uint32_t sa = smem_u32(smA + buf * A_ST + r * 72 + sg * 8);
            const hf* ga = base + ((m < M) ? ((size_t)m * stride + col + sg * 8) : 0);
            CP_ASYNC16_P(sa, ga, (m < M) ? 16 : 0);
        }
        for (int i = tid; i < NC * 8; i += NTH) {    // B: NC rows x 8 chunks
            int r = i >> 3, sg = i & 7;
            uint32_t sa = smem_u32(smB + buf * B_ST + r * 72 + sg * 8);
            CP_ASYNC16(sa, S.B + (size_t)(n0 + r) * K + kof + sg * 8);
        }
        CP_COMMIT();
    };

    // hoisted per-warp LDSM base offsets (element units)
    uint32_t aBase = smem_u32(smA);
    uint32_t bBase = smem_u32(smB);
    int aOff[2];
#pragma unroll
    for (int mt = 0; mt < 2; mt++)
        aOff[mt] = (wm * 32 + mt * 16 + (lane & 15)) * 72 + (lane >> 4) * 8;
    int bOff;
    {
        int g = lane >> 3, r = lane & 7;
        int nt8 = (g >> 1), ko = (g & 1) * 8;
        bOff = (wn * WCOLS + nt8 * 8 + r) * 72 + ko;
    }

    // prologue: fill NST-1 stages
#pragma unroll
    for (int p = 0; p < NST - 1; p++) {
        if (p < ST) load_stage(p, p);
        else        CP_COMMIT();
    }
    for (int s = 0; s < ST; s++) {
        int buf = (NST == 2) ? (s & 1) : (s % 3);
        if (NST == 3 && s + 1 < ST) CP_WAIT1();
        else                        CP_WAIT0();
        __syncthreads();
        if (s + NST - 1 < ST)
            load_stage(s + NST - 1, (NST == 2) ? ((s + 1) & 1) : ((s + NST - 1) % 3));
        uint32_t aB = aBase + buf * (A_ST * 2);
        uint32_t bB = bBase + buf * (B_ST * 2);
#pragma unroll
        for (int kk = 0; kk < 4; kk++) {
            const int k16 = kk * 16;
            uint32_t a[2][4];
#pragma unroll
            for (int mt = 0; mt < 2; mt++)
                LDSM_X4(a[mt][0], a[mt][1], a[mt][2], a[mt][3],
                        aB + (aOff[mt] + k16) * 2);
            uint32_t b[NT][2];
#pragma unroll
            for (int half = 0; half < NT / 2; half++) {
                uint32_t r0, r1, r2, r3;
                LDSM_X4(r0, r1, r2, r3, bB + (bOff + half * 16 * 72 + k16) * 2);
                b[half * 2 + 0][0] = r0; b[half * 2 + 0][1] = r1;
                b[half * 2 + 1][0] = r2; b[half * 2 + 1][1] = r3;
            }
#pragma unroll
            for (int mt = 0; mt < 2; mt++)
#pragma unroll
                for (int nt = 0; nt < NT; nt++)
                    MMA16816(acc[mt][nt], a[mt], b[nt]);
        }
    }

#pragma unroll
    for (int mt = 0; mt < 2; mt++) {
#pragma unroll
        for (int hh = 0; hh < 2; hh++) {
            int m = m0 + wm * 32 + mt * 16 + (lane >> 2) + hh * 8;
            if (m >= M) continue;
            int node = m % Nn;
#pragma unroll
            for (int nt = 0; nt < NT; nt++) {
                int col = n0 + wn * WCOLS + nt * 8 + (lane & 3) * 2;
                float v0 = acc[mt][nt][hh * 2 + 0];
                float v1 = acc[mt][nt][hh * 2 + 1];
                if (S.act) {
                    v0 = 1.f / (1.f + __expf(-(v0 + S.bias[col])));
                    v1 = 1.f / (1.f + __expf(-(v1 + S.bias[col + 1])));
                }
                if (S.gate) {
                    v0 *= S.gate[(size_t)node * 64 + col];
                    v1 *= S.gate[(size_t)node * 64 + col + 1];
                }
                size_t o = (size_t)m * NCfull + col;
                if (S.Cf) *(float2*)(S.Cf + o) = make_float2(v0, v1);
                if (S.Ch) store_h2(S.Ch, o, v0, v1);
                if (S.Lh) {
                    float l0 = (v0 >= 0.f) ? v0 : SLOPEF * v0;
                    float l1 = (v1 >= 0.f) ? v1 : SLOPEF * v1;
                    store_h2(S.Lh, o, l0, l1);
                }
            }
        }
    }
}

// ---------------------------------------------------------------------------
// 3-plane VN GEMM (K=64, NC=64): one block = 128 nodes x 64 cols.
// ALL THREE plane buffers preloaded up front (separate commit groups), drained
// with wait_group 2/1/0 — later planes load behind earlier planes' MMAs.
// 512 threads, 16 warps (8M x 2N), warp tile 16x32. Dynamic smem.
// ---------------------------------------------------------------------------
struct VSet {
    const hf *A;                // planes [d][n][64]
    const hf *B;                // [64][64] fp16
    const hf *U;                // vn_lrelu input planes (or null)
    hf *C;                      // plane outputs (or null)
    hf *Nrm;                    // norm outputs [n,64] (or null)
};

__global__ void __launch_bounds__(512, 2)
gemm_vn3(VSet s0, VSet s1, int Nn) {
    extern __shared__ hf vsm[];
    hf* Bs = vsm;                         // 64*72
    hf* As = vsm + 64 * 72;               // 3 planes of 128*72
    const int tid = threadIdx.x, lane = tid & 31, wid = tid >> 5;
    const int wm = wid >> 1, wn = wid & 1;       // 8 x 2
    const VSet S = blockIdx.y ? s1 : s0;
    const int m0 = blockIdx.x * 128;
    const size_t P = (size_t)Nn * 64;

    auto loadA = [&](int d) {
        for (int i = tid; i < 1024; i += 512) {
            int r = i >> 3, sg = i & 7;
            int m = m0 + r;
            uint32_t sa = smem_u32(As + d * (128 * 72) + r * 72 + sg * 8);
            const hf* ga = S.A + d * P + ((m < Nn) ? ((size_t)m * 64 + sg * 8) : 0);
            CP_ASYNC16_P(sa, ga, (m < Nn) ? 16 : 0);
        }
        CP_COMMIT();
    };

    // group 0: B + plane 0; group 1: plane 1; group 2: plane 2
    {
        int r = tid >> 3, c8 = tid & 7;
        CP_ASYNC16(smem_u32(Bs + r * 72 + c8 * 8), S.B + r * 64 + c8 * 8);
    }
    loadA(0);
    loadA(1);
    loadA(2);

    float acc[3][4][4];
#pragma unroll
    for (int d = 0; d < 3; d++)
#pragma unroll
        for (int j = 0; j < 4; j++)
#pragma unroll
            for (int k = 0; k < 4; k++) acc[d][j][k] = 0.f;

    int aOff = (wm * 16 + (lane & 15)) * 72 + (lane >> 4) * 8;
    int bOff;
    {
        int g = lane >> 3, r = lane & 7;
        int nt8 = (g >> 1), ko = (g & 1) * 8;
        bOff = (wn * 32 + nt8 * 8 + r) * 72 + ko;
    }
    uint32_t aBase = smem_u32(As);
    uint32_t bBase = smem_u32(Bs);

#pragma unroll
    for (int d = 0; d < 3; d++) {
        if (d == 0) CP_WAIT2();
        else if (d == 1) CP_WAIT1();
        else CP_WAIT0();
        __syncthreads();
        uint32_t aB = aBase + d * (128 * 72 * 2);
#pragma unroll
        for (int kk = 0; kk < 4; kk++) {
            const int k16 = kk * 16;
            uint32_t a[4];
            LDSM_X4(a[0], a[1], a[2], a[3], aB + (aOff + k16) * 2);
            uint32_t b[4][2];
#pragma unroll
            for (int half = 0; half < 2; half++) {
                uint32_t r0, r1, r2, r3;
                LDSM_X4(r0, r1, r2, r3, bBase + (bOff + half * 16 * 72 + k16) * 2);
                b[half * 2 + 0][0] = r0; b[half * 2 + 0][1] = r1;
                b[half * 2 + 1][0] = r2; b[half * 2 + 1][1] = r3;
            }
#pragma unroll
            for (int nt = 0; nt < 4; nt++)
                MMA16816(acc[d][nt], a, b[nt]);
        }
    }

    // -------- fused epilogue --------
#pragma unroll
    for (int hh = 0; hh < 2; hh++) {
        int m = m0 + wm * 16 + (lane >> 2) + hh * 8;
        if (m >= Nn) continue;
#pragma unroll
        for (int nt = 0; nt < 4; nt++) {
            int col = wn * 32 + nt * 8 + (lane & 3) * 2;
            float v[3][2];
#pragma unroll
            for (int d = 0; d < 3; d++) {
                v[d][0] = acc[d][nt][hh * 2 + 0];
                v[d][1] = acc[d][nt][hh * 2 + 1];
            }
            if (S.U) {
                float u[3][2];
#pragma unroll
                for (int d = 0; d < 3; d++) {
                    __half2 uh = *(const __half2*)(S.U + d * P + (size_t)m * 64 + col);
                    u[d][0] = __half2float(uh.x);
                    u[d][1] = __half2float(uh.y);
                }
#pragma unroll
                for (int e = 0; e < 2; e++) {
                    float dot = u[0][e] * v[0][e] + u[1][e] * v[1][e] + u[2][e] * v[2][e];
                    float dsq = v[0][e] * v[0][e] + v[1][e] * v[1][e] + v[2][e] * v[2][e];
                    float sc = dot / (dsq + EPSF);
#pragma unroll
                    for (int d = 0; d < 3; d++) {
                        float x = u[d][e];
                        float r = (dot >= 0.f) ? x
                                 : (SLOPEF * x + (1.f - SLOPEF) * (x - sc * v[d][e]));
                        v[d][e] = r;
                    }
                }
            }
            if (S.C) {
#pragma unroll
                for (int d = 0; d < 3; d++)
                    store_h2(S.C, d * P + (size_t)m * 64 + col, v[d][0], v[d][1]);
            }
            if (S.Nrm) {
                float n0 = sqrtf(v[0][0] * v[0][0] + v[1][0] * v[1][0] + v[2][0] * v[2][0]);
                float n1 = sqrtf(v[0][1] * v[0][1] + v[1][1] * v[1][1] + v[2][1] * v[2][1]);
                store_h2(S.Nrm, (size_t)m * 64 + col, n0, n1);
            }
        }
    }
}

// ---------------------------------------------------------------------------
// weight prepack: W(nc,k) fp32 -> fp16
// ---------------------------------------------------------------------------
struct PPk { const float* w; hf* o; int nc; int k; };
struct PPargs { PPk e[15]; };
__global__ void k_prepack(PPargs pa) {
    PPk p = pa.e[blockIdx.y];
    int tot = p.nc * p.k;
    for (int i = blockIdx.x * 256 + threadIdx.x; i < tot; i += gridDim.x * 256)
        p.o[i] = __float2half(p.w[i]);
}

// ---------------------------------------------------------------------------
// prep: vec -> fp16 planes; sca = h_sca + te[t] -> fp16 [n,256]
// ---------------------------------------------------------------------------
__global__ void k_prep(const float* __restrict__ h_vec, const float* __restrict__ h_sca,
                       const float* __restrict__ te, const int* __restrict__ tptr,
                       hf* __restrict__ vh, hf* __restrict__ scah, int Nn) {
    int i = blockIdx.x * 256 + threadIdx.x;
    int half = Nn * 64;
    if (i < half) {
        int node = i >> 6, c = i & 63;
#pragma unroll
        for (int d = 0; d < 3; d++) {
            float x = h_vec[(size_t)node * 192 + c * 3 + d];
            vh[(size_t)d * Nn * 64 + (size_t)node * 64 + c] = __float2half(x);
        }
    } else if (i < 2 * half) {
        int j = i - half;
        int node = j >> 6, q4 = (j & 63) * 4;
        int t = *tptr;
        float4 hs = *(const float4*)(h_sca + (size_t)node * 256 + q4);
        float4 tv = *(const float4*)(te + (size_t)t * 256 + q4);
        size_t o = (size_t)node * 256 + q4;
        store_h2(scah, o,     hs.x + tv.x, hs.y + tv.y);
        store_h2(scah, o + 2, hs.z + tv.z, hs.w + tv.w);
    }
}

// att[n] = Ws[0:64].|vi2a| + Ws[64:320].lrelu(Sa)
__global__ void k_att(const hf* __restrict__ Nh, const hf* __restrict__ Sa,
                      const float* __restrict__ Ws, float* __restrict__ att, int Nn) {
    __shared__ float ws[320];
    int tid = threadIdx.x, w = tid >> 5, lane = tid & 31;
    for (int i = tid; i < 320; i += 256) ws[i] = Ws[i];
    __syncthreads();
    int node = blockIdx.x * 8 + w;
    if (node >= Nn) return;
    float p = 0.f;
    for (int c = lane; c < 64; c += 32)
        p = fmaf(ws[c], __half2float(Nh[(size_t)node * 64 + c]), p);
    for (int k = lane; k < 256; k += 32) {
        float sv = __half2float(Sa[(size_t)node * 256 + k]);
        sv = (sv >= 0.f) ? sv : SLOPEF * sv;
        p = fmaf(ws[64 + k], sv, p);
    }
#pragma unroll
    for (int o = 16; o > 0; o >>= 1) p += __shfl_down_sync(0xffffffff, p, o);
    if (lane == 0) att[node] = p;
}

__global__ void k_segstart(const int* __restrict__ bid, int n, int B, int* __restrict__ start) {
    int b = blockIdx.x * blockDim.x + threadIdx.x;
    if (b > B) return;
    int lo = 0, hi = n;
    while (lo < hi) { int mid = (lo + hi) >> 1; if (bid[mid] < b) lo = mid + 1; else hi = mid; }
    start[b] = lo;
}

__global__ void k_softmax(const float* __restrict__ att, const int* __restrict__ start,
                          float* __restrict__ w) {
    int b = blockIdx.x;
    int s = start[b], e = start[b + 1];
    if (s >= e) return;
    __shared__ float red[256];
    int tid = threadIdx.x;
    float m = -INFINITY;
    for (int i = s + tid; i < e; i += 256) m = fmaxf(m, att[i]);
    red[tid] = m; __syncthreads();
    for (int o = 128; o > 0; o >>= 1) { if (tid < o) red[tid] = fmaxf(red[tid], red[tid + o]); __syncthreads(); }
    m = red[0]; __syncthreads();
    float zs = 0.f;
    for (int i = s + tid; i < e; i += 256) zs += __expf(att[i] - m);
    red[tid] = zs; __syncthreads();
    for (int o = 128; o > 0; o >>= 1) { if (tid < o) red[tid] += red[tid + o]; __syncthreads(); }
    float inv = 1.f / red[0];
    for (int i = s + tid; i < e; i += 256) w[i] = __expf(att[i] - m) * inv;
}

__global__ void k_reduce(const float* __restrict__ w, const hf* __restrict__ fs,
                         const hf* __restrict__ fv, const float* __restrict__ pos,
                         const int* __restrict__ start, int B, int Nn, float* __restrict__ out) {
    int b = blockIdx.x, j = threadIdx.x;
    int s = start[b], e = start[b + 1];
    size_t P = (size_t)Nn * 64;
    int c = j / 3, d = j - c * 3;
    float a256 = 0.f, a192 = 0.f, a3 = 0.f;
    for (int i = s; i < e; i++) {
        float wi = w[i];
        a256 = fmaf(wi, __half2float(fs[(size_t)i * 256 + j]), a256);
        if (j < 192)
            a192 = fmaf(wi, __half2float(fv[(size_t)d * P + (size_t)i * 64 + c]), a192);
        if (j < 3) a3 = fmaf(wi, pos[(size_t)i * 3 + j], a3);
    }
    out[(size_t)b * 256 + j] = a256;
    if (j < 192) out[(size_t)B * 256 + (size_t)b * 192 + j] = a192;
    if (j < 3)   out[(size_t)B * 256 + (size_t)B * 192 + (size_t)b * 3 + j] = a3;
}

// ---------------------------------------------------------------------------
extern "C" void kernel_launch(void* const* d_in, const int* in_sizes, int n_in,
                              void* d_out, int out_size) {
    const float* h_sca = (const float*)d_in[0];
    const float* h_vec = (const float*)d_in[1];
    const float* pos   = (const float*)d_in[2];
    const float* te    = (const float*)d_in[3];
    const float* W[26];
    for (int i = 4; i <= 25; i++) W[i] = (const float*)d_in[i];
    const int* tptr = (const int*)d_in[26];
    const int* bid  = (const int*)d_in[27];

    int n = in_sizes[0] / 256;
    int B = out_size / 451;

    hf *vecS, *viAs, *viNs, *uas, *uns, *vas, *vns, *scaX, *lrS, *Sas, *Sns;
    hf *nA1, *nN1, *nA2, *nN2, *Baug;
    float *Ga, *Gn, *att, *wgt;
    int* segs;
    cudaGetSymbolAddress((void**)&vecS, g_vecS);
    cudaGetSymbolAddress((void**)&viAs, g_viAs);
    cudaGetSymbolAddress((void**)&viNs, g_viNs);
    cudaGetSymbolAddress((void**)&uas,  g_uas);
    cudaGetSymbolAddress((void**)&uns,  g_uns);
    cudaGetSymbolAddress((void**)&vas,  g_vas);
    cudaGetSymbolAddress((void**)&vns,  g_vns);
    cudaGetSymbolAddress((void**)&scaX, g_scaX);
    cudaGetSymbolAddress((void**)&lrS,  g_lrS);
    cudaGetSymbolAddress((void**)&Sas,  g_Sas);
    cudaGetSymbolAddress((void**)&Sns,  g_Sns);
    cudaGetSymbolAddress((void**)&nA1,  g_nA1);
    cudaGetSymbolAddress((void**)&nN1,  g_nN1);
    cudaGetSymbolAddress((void**)&nA2,  g_nA2);
    cudaGetSymbolAddress((void**)&nN2,  g_nN2);
    cudaGetSymbolAddress((void**)&Baug, g_Baug);
    cudaGetSymbolAddress((void**)&Ga,   g_Ga);
    cudaGetSymbolAddress((void**)&Gn,   g_Gn);
    cudaGetSymbolAddress((void**)&att,  g_att);
    cudaGetSymbolAddress((void**)&wgt,  g_w);
    cudaGetSymbolAddress((void**)&segs, g_seg);

    static const int widx[15] = {4,15, 6,17, 7,18, 5,16, 9,20, 10,21, 23,24,22};
    static const int wnc[15]  = {64,64, 256,256, 64,64, 64,64, 64,64, 64,64, 256,64,64};
    static const int wk[15]   = {64,64, 320,320, 256,256, 64,64, 64,64, 64,64, 320,256,64};
    PPargs pa;
    size_t boff[15]; size_t acc = 0;
    for (int i = 0; i < 15; i++) {
        boff[i] = acc;
        pa.e[i] = PPk{W[widx[i]], Baug + acc, wnc[i], wk[i]};
        acc += (size_t)wnc[i] * wk[i];
    }
    const hf *B_a1Wv1 = Baug + boff[0],  *B_n1Wv1 = Baug + boff[1];
    const hf *B_a1Ws  = Baug + boff[2],  *B_n1Ws  = Baug + boff[3];
    const hf *B_a1Wg  = Baug + boff[4],  *B_n1Wg  = Baug + boff[5];
    const hf *B_a1Wv2 = Baug + boff[6],  *B_n1Wv2 = Baug + boff[7];
    const hf *B_a1Wd  = Baug + boff[8],  *B_n1Wd  = Baug + boff[9];
    const hf *B_a2Wv1 = Baug + boff[10], *B_n2Wv1 = Baug + boff[11];
    const hf *B_n2Ws  = Baug + boff[12], *B_n2Wg  = Baug + boff[13];
    const hf *B_n2Wv2 = Baug + boff[14];

    int M3 = 3 * n;
    int gv = (n + 127) / 128;
    int g3 = (M3 + 127) / 128;

    constexpr int SM64  = 2 * (128 + 64) * 72 * 2;     // 55296 B
    constexpr int SM128 = 3 * (128 + 128) * 72 * 2;    // 110592 B
    constexpr int SMV   = (64 * 72 + 3 * 128 * 72) * 2; // 64512 B
    cudaFuncSetAttribute((const void*)gemm_f16<64>,
                         cudaFuncAttributeMaxDynamicSharedMemorySize, SM64);
    cudaFuncSetAttribute((const void*)gemm_f16<128>,
                         cudaFuncAttributeMaxDynamicSharedMemorySize, SM128);
    cudaFuncSetAttribute((const void*)gemm_vn3,
                         cudaFuncAttributeMaxDynamicSharedMemorySize, SMV);

    auto GS = [](const hf* a1, const hf* a2, int K1, const hf* b,
                 float* cf, hf* ch, hf* lh,
                 const float* bias, const float* gate, int act) {
        GSet g; g.A1 = a1; g.A2 = a2; g.K1 = K1; g.B = b;
        g.Cf = cf; g.Ch = ch; g.Lh = lh;
        g.bias = bias; g.gate = gate; g.act = act; return g;
    };
    auto VS = [](const hf* a, const hf* b, const hf* u, hf* c, hf* nrm) {
        VSet v; v.A = a; v.B = b; v.U = u; v.C = c; v.Nrm = nrm; return v;
    };

    k_prepack<<<dim3(64, 15), 256>>>(pa);
    k_prep<<<(n * 128 + 255) / 256, 256>>>(h_vec, h_sca, te, tptr, vecS, scaX, n);

    // vi pair: planes + norms
    gemm_vn3<<<dim3(gv, 2), 512, SMV>>>(
        VS(vecS, B_a1Wv1, nullptr, viAs, nA1),
        VS(vecS, B_n1Wv1, nullptr, viNs, nN1), n);
    // S pair: A = (norms | sca shared); net side also emits lrelu(Sn)
    gemm_f16<128><<<dim3(gv, 2, 2), 512, SM128>>>(
        GS(nA1, scaX, 64, B_a1Ws, nullptr, Sas, nullptr, nullptr, nullptr, 0),
        GS(nN1, scaX, 64, B_n1Ws, nullptr, Sns, lrS,     nullptr, nullptr, 0),
        n, 320, n, 256);
    // gates pair
    gemm_f16<64><<<dim3(gv, 2, 1), 256, SM64>>>(
        GS(Sas, nullptr, 256, B_a1Wg, Ga, nullptr, nullptr, W[8],  nullptr, 1),
        GS(Sns, nullptr, 256, B_n1Wg, Gn, nullptr, nullptr, W[19], nullptr, 1),
        n, 256, n, 64);
    // u pair (per-plane rows M3, gated)
    gemm_f16<64><<<dim3(g3, 2, 1), 256, SM64>>>(
        GS(viAs, nullptr, 64, B_a1Wv2, nullptr, uas, nullptr, nullptr, Ga, 0),
        GS(viNs, nullptr, 64, B_n1Wv2, nullptr, uns, nullptr, nullptr, Gn, 0),
        M3, 64, n, 64);
    // d pair with fused vn_lrelu -> v
    gemm_vn3<<<dim3(gv, 2), 512, SMV>>>(
        VS(uas, B_a1Wd, uas, vas, nullptr),
        VS(uns, B_n1Wd, uns, vns, nullptr), n);
    // vi2 pair: att -> norms only; net -> vi2n planes + norms
    gemm_vn3<<<dim3(gv, 2), 512, SMV>>>(
        VS(vas, B_a2Wv1, nullptr, nullptr, nA2),
        VS(vns, B_n2Wv1, nullptr, viAs, nN2), n);
    k_att<<<(n + 7) / 8, 256>>>(nA2, Sas, W[12], att, n);

    // fs = (norms2 | lrelu(Sn)) @ n2Ws -> Sas reuse
    {
        GSet g = GS(nN2, lrS, 64, B_n2Ws, nullptr, Sas, nullptr, nullptr, nullptr, 0);
        gemm_f16<128><<<dim3(gv, 1, 2), 512, SM128>>>(g, g, n, 320, n, 256);
    }
    // gate2 -> Ga reuse
    {
        GSet g = GS(Sas, nullptr, 256, B_n2Wg, Ga, nullptr, nullptr, W[25], nullptr, 1);
        gemm_f16<64><<<dim3(gv, 1, 1), 256, SM64>>>(g, g, n, 256, n, 64);
    }
    // fv = gate2 * (n2Wv2 @ vi2n) -> vas reuse
    {
        GSet g = GS(viAs, nullptr, 64, B_n2Wv2, nullptr, vas, nullptr, nullptr, Ga, 0);
        gemm_f16<64><<<dim3(g3, 1, 1), 256, SM64>>>(g, g, M3, 64, n, 64);
    }

    k_segstart<<<(B + 1 + 255) / 256, 256>>>(bid, n, B, segs);
    k_softmax<<<B, 256>>>(att, segs, wgt);
    k_reduce<<<B, 256>>>(wgt, Sas, vas, pos, segs, B, n, (float*)d_out);
}

// round 15
// speedup vs baseline: 2.3661x; 1.1019x over previous
#include <cuda_runtime.h>
#include <cuda_fp16.h>
#include <math.h>
#include <stdint.h>

typedef __half hf;

#define MAXN   120000
#define SLOPEF 0.01f
#define EPSF   1e-6f
#define PVMAX  (3*MAXN*64)

// ---------------- static device scratch (plain fp16) ------------------------
__device__ __align__(16) hf    g_vecS[PVMAX];
__device__ __align__(16) hf    g_viAs[PVMAX];
__device__ __align__(16) hf    g_viNs[PVMAX];
__device__ __align__(16) hf    g_uns [PVMAX];   // vi2n planes (chain output)
__device__ __align__(16) hf    g_vas [PVMAX];   // fv
__device__ __align__(16) hf    g_scaX[MAXN*256];
__device__ __align__(16) hf    g_lrS [MAXN*256];
__device__ __align__(16) hf    g_Sas [MAXN*256]; // later: fs
__device__ __align__(16) hf    g_Sns [MAXN*256];
__device__ __align__(16) hf    g_nA1 [MAXN*64];
__device__ __align__(16) hf    g_nN1 [MAXN*64];
__device__ __align__(16) hf    g_nA2 [MAXN*64];
__device__ __align__(16) hf    g_nN2 [MAXN*64];
__device__ __align__(16) hf    g_Baug[524288];
__device__ float g_Ga  [MAXN*64];
__device__ float g_Gn  [MAXN*64];
__device__ float g_att [MAXN];
__device__ float g_w   [MAXN];
__device__ int   g_seg [4100];

// ---------------- helpers ----------------
__device__ __forceinline__ uint32_t smem_u32(const void* p) {
    return (uint32_t)__cvta_generic_to_shared(p);
}
__device__ __forceinline__ void store_h2(hf* H, size_t o, float v0, float v1) {
    __half2 t; t.x = __float2half(v0); t.y = __float2half(v1);
    *(__half2*)(H + o) = t;
}

#define MMA16816(d, a, b)                                                     \
    asm volatile("mma.sync.aligned.m16n8k16.row.col.f32.f16.f16.f32 "        \
        "{%0,%1,%2,%3}, {%4,%5,%6,%7}, {%8,%9}, {%0,%1,%2,%3};"              \
        : "+f"((d)[0]), "+f"((d)[1]), "+f"((d)[2]), "+f"((d)[3])             \
        : "r"((a)[0]), "r"((a)[1]), "r"((a)[2]), "r"((a)[3]),                \
          "r"((b)[0]), "r"((b)[1]))

#define LDSM_X4(r0, r1, r2, r3, addr)                                        \
    asm volatile("ldmatrix.sync.aligned.m8n8.x4.shared.b16 {%0,%1,%2,%3}, [%4];" \
        : "=r"(r0), "=r"(r1), "=r"(r2), "=r"(r3) : "r"(addr))

#define CP_ASYNC16(sa, ga)                                                   \
    asm volatile("cp.async.cg.shared.global [%0], [%1], 16;" :: "r"(sa), "l"(ga))
#define CP_ASYNC16_P(sa, ga, p)                                              \
    asm volatile("cp.async.cg.shared.global [%0], [%1], 16, %2;" :: "r"(sa), "l"(ga), "r"(p))
#define CP_COMMIT() asm volatile("cp.async.commit_group;")
#define CP_WAIT0()  asm volatile("cp.async.wait_group 0;")
#define CP_WAIT1()  asm volatile("cp.async.wait_group 1;")
#define CP_WAIT2()  asm volatile("cp.async.wait_group 2;")

// ---------------------------------------------------------------------------
// fp16 HMMA GEMM with two A regions (unchanged from round 14)
// ---------------------------------------------------------------------------
struct GSet {
    const hf *A1, *A2;
    int K1;
    const hf* B;
    float* Cf; hf* Ch;
    hf* Lh;
    const float *bias, *gate;
    int act;
};

template <int NC>
__global__ void __launch_bounds__(NC >= 128 ? 512 : 256, NC >= 128 ? 2 : 3)
gemm_f16(GSet s0, GSet s1, int M, int K, int Nn, int NCfull) {
    constexpr int NTH   = (NC >= 128) ? 512 : 256;
    constexpr int NST   = (NC >= 128) ? 3 : 2;
    constexpr int NWN   = (NC >= 128) ? 4 : 2;
    constexpr int WCOLS = NC / NWN;
    constexpr int NT    = WCOLS / 8;
    constexpr int A_ST  = 128 * 72;
    constexpr int B_ST  = NC * 72;

    extern __shared__ hf sm[];
    hf* smA = sm;
    hf* smB = sm + NST * A_ST;

    const int tid = threadIdx.x;
    const int lane = tid & 31, wid = tid >> 5;
    const int wm = wid / NWN, wn = wid % NWN;
    const GSet S = (blockIdx.y == 0) ? s0 : s1;
    const int m0 = blockIdx.x * 128;
    const int n0 = blockIdx.z * NC;
    const int ST = K >> 6;
    const int K2w = K - S.K1;

    float acc[2][NT][4];
#pragma unroll
    for (int i = 0; i < 2; i++)
#pragma unroll
        for (int j = 0; j < NT; j++)
#pragma unroll
            for (int k = 0; k < 4; k++) acc[i][j][k] = 0.f;

    auto load_stage = [&](int s, int buf) {
        int kof = s * 64;
        const hf* base; int stride, col;
        if (kof < S.K1) { base = S.A1; stride = S.K1; col = kof; }
        else            { base = S.A2; stride = K2w;  col = kof - S.K1; }
        for (int i = tid; i < 1024; i += NTH) {
            int r = i >> 3, sg = i & 7;
            int m = m0 + r;
            uint32_t sa = smem_u32(smA + buf * A_ST + r * 72 + sg * 8);
            const hf* ga = base + ((m < M) ? ((size_t)m * stride + col + sg * 8) : 0);
            CP_ASYNC16_P(sa, ga, (m < M) ? 16 : 0);
        }
        for (int i = tid; i < NC * 8; i += NTH) {
            int r = i >> 3, sg = i & 7;
            uint32_t sa = smem_u32(smB + buf * B_ST + r * 72 + sg * 8);
            CP_ASYNC16(sa, S.B + (size_t)(n0 + r) * K + kof + sg * 8);
        }
        CP_COMMIT();
    };

    uint32_t aBase = smem_u32(smA);
    uint32_t bBase = smem_u32(smB);
    int aOff[2];
#pragma unroll
    for (int mt = 0; mt < 2; mt++)
        aOff[mt] = (wm * 32 + mt * 16 + (lane & 15)) * 72 + (lane >> 4) * 8;
    int bOff;
    {
        int g = lane >> 3, r = lane & 7;
        int nt8 = (g >> 1), ko = (g & 1) * 8;
        bOff = (wn * WCOLS + nt8 * 8 + r) * 72 + ko;
    }

#pragma unroll
    for (int p = 0; p < NST - 1; p++) {
        if (p < ST) load_stage(p, p);
        else        CP_COMMIT();
    }
    for (int s = 0; s < ST; s++) {
        int buf = (NST == 2) ? (s & 1) : (s % 3);
        if (NST == 3 && s + 1 < ST) CP_WAIT1();
        else                        CP_WAIT0();
        __syncthreads();
        if (s + NST - 1 < ST)
            load_stage(s + NST - 1, (NST == 2) ? ((s + 1) & 1) : ((s + NST - 1) % 3));
        uint32_t aB = aBase + buf * (A_ST * 2);
        uint32_t bB = bBase + buf * (B_ST * 2);
#pragma unroll
        for (int kk = 0; kk < 4; kk++) {
            const int k16 = kk * 16;
            uint32_t a[2][4];
#pragma unroll
            for (int mt = 0; mt < 2; mt++)
                LDSM_X4(a[mt][0], a[mt][1], a[mt][2], a[mt][3],
                        aB + (aOff[mt] + k16) * 2);
            uint32_t b[NT][2];
#pragma unroll
            for (int half = 0; half < NT / 2; half++) {
                uint32_t r0, r1, r2, r3;
                LDSM_X4(r0, r1, r2, r3, bB + (bOff + half * 16 * 72 + k16) * 2);
                b[half * 2 + 0][0] = r0; b[half * 2 + 0][1] = r1;
                b[half * 2 + 1][0] = r2; b[half * 2 + 1][1] = r3;
            }
#pragma unroll
            for (int mt = 0; mt < 2; mt++)
#pragma unroll
                for (int nt = 0; nt < NT; nt++)
                    MMA16816(acc[mt][nt], a[mt], b[nt]);
        }
    }

#pragma unroll
    for (int mt = 0; mt < 2; mt++) {
#pragma unroll
        for (int hh = 0; hh < 2; hh++) {
            int m = m0 + wm * 32 + mt * 16 + (lane >> 2) + hh * 8;
            if (m >= M) continue;
            int node = m % Nn;
#pragma unroll
            for (int nt = 0; nt < NT; nt++) {
                int col = n0 + wn * WCOLS + nt * 8 + (lane & 3) * 2;
                float v0 = acc[mt][nt][hh * 2 + 0];
                float v1 = acc[mt][nt][hh * 2 + 1];
                if (S.act) {
                    v0 = 1.f / (1.f + __expf(-(v0 + S.bias[col])));
                    v1 = 1.f / (1.f + __expf(-(v1 + S.bias[col + 1])));
                }
                if (S.gate) {
                    v0 *= S.gate[(size_t)node * 64 + col];
                    v1 *= S.gate[(size_t)node * 64 + col + 1];
                }
                size_t o = (size_t)m * NCfull + col;
                if (S.Cf) *(float2*)(S.Cf + o) = make_float2(v0, v1);
                if (S.Ch) store_h2(S.Ch, o, v0, v1);
                if (S.Lh) {
                    float l0 = (v0 >= 0.f) ? v0 : SLOPEF * v0;
                    float l1 = (v1 >= 0.f) ? v1 : SLOPEF * v1;
                    store_h2(S.Lh, o, l0, l1);
                }
            }
        }
    }
}

// ---------------------------------------------------------------------------
// 3-plane VN GEMM (vi pair only): preloaded planes, fused norm epilogue.
// ---------------------------------------------------------------------------
struct VSet {
    const hf *A;
    const hf *B;
    hf *C;
    hf *Nrm;
};

__global__ void __launch_bounds__(512, 2)
gemm_vn3(VSet s0, VSet s1, int Nn) {
    extern __shared__ hf vsm[];
    hf* Bs = vsm;
    hf* As = vsm + 64 * 72;
    const int tid = threadIdx.x, lane = tid & 31, wid = tid >> 5;
    const int wm = wid >> 1, wn = wid & 1;
    const VSet S = blockIdx.y ? s1 : s0;
    const int m0 = blockIdx.x * 128;
    const size_t P = (size_t)Nn * 64;

    auto loadA = [&](int d) {
        for (int i = tid; i < 1024; i += 512) {
            int r = i >> 3, sg = i & 7;
            int m = m0 + r;
            uint32_t sa = smem_u32(As + d * (128 * 72) + r * 72 + sg * 8);
            const hf* ga = S.A + d * P + ((m < Nn) ? ((size_t)m * 64 + sg * 8) : 0);
            CP_ASYNC16_P(sa, ga, (m < Nn) ? 16 : 0);
        }
        CP_COMMIT();
    };

    {
        int r = tid >> 3, c8 = tid & 7;
        CP_ASYNC16(smem_u32(Bs + r * 72 + c8 * 8), S.B + r * 64 + c8 * 8);
    }
    loadA(0);
    loadA(1);
    loadA(2);

    float acc[3][4][4];
#pragma unroll
    for (int d = 0; d < 3; d++)
#pragma unroll
        for (int j = 0; j < 4; j++)
#pragma unroll
            for (int k = 0; k < 4; k++) acc[d][j][k] = 0.f;

    int aOff = (wm * 16 + (lane & 15)) * 72 + (lane >> 4) * 8;
    int bOff;
    {
        int g = lane >> 3, r = lane & 7;
        int nt8 = (g >> 1), ko = (g & 1) * 8;
        bOff = (wn * 32 + nt8 * 8 + r) * 72 + ko;
    }
    uint32_t aBase = smem_u32(As);
    uint32_t bBase = smem_u32(Bs);

#pragma unroll
    for (int d = 0; d < 3; d++) {
        if (d == 0) CP_WAIT2();
        else if (d == 1) CP_WAIT1();
        else CP_WAIT0();
        __syncthreads();
        uint32_t aB = aBase + d * (128 * 72 * 2);
#pragma unroll
        for (int kk = 0; kk < 4; kk++) {
            const int k16 = kk * 16;
            uint32_t a[4];
            LDSM_X4(a[0], a[1], a[2], a[3], aB + (aOff + k16) * 2);
            uint32_t b[4][2];
#pragma unroll
            for (int half = 0; half < 2; half++) {
                uint32_t r0, r1, r2, r3;
                LDSM_X4(r0, r1, r2, r3, bBase + (bOff + half * 16 * 72 + k16) * 2);
                b[half * 2 + 0][0] = r0; b[half * 2 + 0][1] = r1;
                b[half * 2 + 1][0] = r2; b[half * 2 + 1][1] = r3;
            }
#pragma unroll
            for (int nt = 0; nt < 4; nt++)
                MMA16816(acc[d][nt], a, b[nt]);
        }
    }

#pragma unroll
    for (int hh = 0; hh < 2; hh++) {
        int m = m0 + wm * 16 + (lane >> 2) + hh * 8;
        if (m >= Nn) continue;
#pragma unroll
        for (int nt = 0; nt < 4; nt++) {
            int col = wn * 32 + nt * 8 + (lane & 3) * 2;
            float v[3][2];
#pragma unroll
            for (int d = 0; d < 3; d++) {
                v[d][0] = acc[d][nt][hh * 2 + 0];
                v[d][1] = acc[d][nt][hh * 2 + 1];
            }
            if (S.C) {
#pragma unroll
                for (int d = 0; d < 3; d++)
                    store_h2(S.C, d * P + (size_t)m * 64 + col, v[d][0], v[d][1]);
            }
            if (S.Nrm) {
                float n0 = sqrtf(v[0][0] * v[0][0] + v[1][0] * v[1][0] + v[2][0] * v[2][0]);
                float n1 = sqrtf(v[0][1] * v[0][1] + v[1][1] * v[1][1] + v[2][1] * v[2][1]);
                store_h2(S.Nrm, (size_t)m * 64 + col, n0, n1);
            }
        }
    }
}

// ---------------------------------------------------------------------------
// CHAIN kernel: per block of 128 nodes, entirely in smem:
//   u = gate ⊙ (vi @ W2ᵀ)          (u -> smem U)
//   d = u @ Wdᵀ ; v = vnlrelu(u,d) (v -> smem X, overwriting vi)
//   vi2 = v @ W1pᵀ                 (epilogue: norms -> Nrm, planes -> Pout)
// 512 threads, 16 warps (8M x 2N), warp tile 16x32 per plane.
// ---------------------------------------------------------------------------
struct CSet {
    const hf* Vin;       // planes [d][n][64]
    const float* gate;   // [n][64] fp32
    const hf *W2, *Wd, *W1p;
    hf* Pout;            // vi2 planes out (or null)
    hf* Nrm;             // norms out [n][64]
};

__global__ void __launch_bounds__(512, 1)
k_chain(CSet s0, CSet s1, int Nn) {
    constexpr int WP = 64 * 72;     // weight tile elems
    constexpr int XP = 128 * 72;    // plane tile elems
    extern __shared__ hf csm[];
    hf* Wsm = csm;                  // [3][64*72]  W2 | Wd | W1p
    hf* X   = csm + 3 * WP;         // [3][128*72] vi -> later v
    hf* U   = X + 3 * XP;           // [3][128*72] u

    const int tid = threadIdx.x, lane = tid & 31, wid = tid >> 5;
    const int wm = wid >> 1, wn = wid & 1;
    const CSet S = blockIdx.y ? s1 : s0;
    const int m0 = blockIdx.x * 128;
    const size_t P = (size_t)Nn * 64;

    // ---- load weights + vi planes ----
    for (int i = tid; i < 1536; i += 512) {
        int w = i >> 9, j = i & 511;
        int r = j >> 3, c8 = j & 7;
        const hf* src = (w == 0) ? S.W2 : ((w == 1) ? S.Wd : S.W1p);
        CP_ASYNC16(smem_u32(Wsm + w * WP + r * 72 + c8 * 8), src + r * 64 + c8 * 8);
    }
    for (int i = tid; i < 3072; i += 512) {
        int d = i >> 10, j = i & 1023;
        int r = j >> 3, sg = j & 7;
        int m = m0 + r;
        uint32_t sa = smem_u32(X + d * XP + r * 72 + sg * 8);
        const hf* ga = S.Vin + d * P + ((m < Nn) ? ((size_t)m * 64 + sg * 8) : 0);
        CP_ASYNC16_P(sa, ga, (m < Nn) ? 16 : 0);
    }
    CP_COMMIT();

    const int aOff = (wm * 16 + (lane & 15)) * 72 + (lane >> 4) * 8;
    int bOff;
    {
        int g = lane >> 3, r = lane & 7;
        int nt8 = (g >> 1), ko = (g & 1) * 8;
        bOff = (wn * 32 + nt8 * 8 + r) * 72 + ko;
    }
    const int mlBase = wm * 16 + (lane >> 2);
    const int colBase = wn * 32 + (lane & 3) * 2;

    auto gemm64 = [&](uint32_t aTile, uint32_t bTile, float acc[4][4]) {
#pragma unroll
        for (int j = 0; j < 4; j++)
#pragma unroll
            for (int k = 0; k < 4; k++) acc[j][k] = 0.f;
#pragma unroll
        for (int kk = 0; kk < 4; kk++) {
            const int k16 = kk * 16;
            uint32_t a[4];
            LDSM_X4(a[0], a[1], a[2], a[3], aTile + (aOff + k16) * 2);
            uint32_t b[4][2];
#pragma unroll
            for (int half = 0; half < 2; half++) {
                uint32_t r0, r1, r2, r3;
                LDSM_X4(r0, r1, r2, r3, bTile + (bOff + half * 16 * 72 + k16) * 2);
                b[half * 2 + 0][0] = r0; b[half * 2 + 0][1] = r1;
                b[half * 2 + 1][0] = r2; b[half * 2 + 1][1] = r3;
            }
#pragma unroll
            for (int nt = 0; nt < 4; nt++)
                MMA16816(acc[nt], a, b[nt]);
        }
    };

    uint32_t xB = smem_u32(X);
    uint32_t uB = smem_u32(U);
    uint32_t wB = smem_u32(Wsm);

    CP_WAIT0();
    __syncthreads();

    // ---- phase 1: u = gate * (vi @ W2^T), store to U ----
#pragma unroll
    for (int d = 0; d < 3; d++) {
        float acc[4][4];
        gemm64(xB + d * (XP * 2), wB, acc);
#pragma unroll
        for (int hh = 0; hh < 2; hh++) {
            int ml = mlBase + hh * 8;
            int node = m0 + ml;
            if (node >= Nn) continue;
#pragma unroll
            for (int nt = 0; nt < 4; nt++) {
                int col = colBase + nt * 8;
                float2 gg = *(const float2*)(S.gate + (size_t)node * 64 + col);
                float v0 = acc[nt][hh * 2 + 0] * gg.x;
                float v1 = acc[nt][hh * 2 + 1] * gg.y;
                store_h2(U + d * XP, (size_t)ml * 72 + col, v0, v1);
            }
        }
    }
    __syncthreads();

    // ---- phase 2: d = u @ Wd^T ; v = vnlrelu(u, d) -> X ----
    {
        float acc3[3][4][4];
#pragma unroll
        for (int d = 0; d < 3; d++)
            gemm64(uB + d * (XP * 2), wB + WP * 2, acc3[d]);
#pragma unroll
        for (int hh = 0; hh < 2; hh++) {
            int ml = mlBase + hh * 8;
#pragma unroll
            for (int nt = 0; nt < 4; nt++) {
                int col = colBase + nt * 8;
                float dd[3][2], uu[3][2];
#pragma unroll
                for (int d = 0; d < 3; d++) {
                    dd[d][0] = acc3[d][nt][hh * 2 + 0];
                    dd[d][1] = acc3[d][nt][hh * 2 + 1];
                    __half2 uh = *(const __half2*)(U + d * XP + (size_t)ml * 72 + col);
                    uu[d][0] = __half2float(uh.x);
                    uu[d][1] = __half2float(uh.y);
                }
#pragma unroll
                for (int e = 0; e < 2; e++) {
                    float dot = uu[0][e] * dd[0][e] + uu[1][e] * dd[1][e] + uu[2][e] * dd[2][e];
                    float dsq = dd[0][e] * dd[0][e] + dd[1][e] * dd[1][e] + dd[2][e] * dd[2][e];
                    float sc = dot / (dsq + EPSF);
#pragma unroll
                    for (int d = 0; d < 3; d++) {
                        float x = uu[d][e];
                        dd[d][e] = (dot >= 0.f) ? x
                                 : (SLOPEF * x + (1.f - SLOPEF) * (x - sc * dd[d][e]));
                    }
                }
#pragma unroll
                for (int d = 0; d < 3; d++)
                    store_h2(X + d * XP, (size_t)ml * 72 + col, dd[d][0], dd[d][1]);
            }
        }
    }
    __syncthreads();

    // ---- phase 3: vi2 = v @ W1p^T ; norms + optional planes out ----
    {
        float acc3[3][4][4];
#pragma unroll
        for (int d = 0; d < 3; d++)
            gemm64(xB + d * (XP * 2), wB + 2 * WP * 2, acc3[d]);
#pragma unroll
        for (int hh = 0; hh < 2; hh++) {
            int ml = mlBase + hh * 8;
            int m = m0 + ml;
            if (m >= Nn) continue;
#pragma unroll
            for (int nt = 0; nt < 4; nt++) {
                int col = colBase + nt * 8;
                float v[3][2];
#pragma unroll
                for (int d = 0; d < 3; d++) {
                    v[d][0] = acc3[d][nt][hh * 2 + 0];
                    v[d][1] = acc3[d][nt][hh * 2 + 1];
                }
                if (S.Pout) {
#pragma unroll
                    for (int d = 0; d < 3; d++)
                        store_h2(S.Pout, d * P + (size_t)m * 64 + col, v[d][0], v[d][1]);
                }
                float n0 = sqrtf(v[0][0] * v[0][0] + v[1][0] * v[1][0] + v[2][0] * v[2][0]);
                float n1 = sqrtf(v[0][1] * v[0][1] + v[1][1] * v[1][1] + v[2][1] * v[2][1]);
                store_h2(S.Nrm, (size_t)m * 64 + col, n0, n1);
            }
        }
    }
}

// ---------------------------------------------------------------------------
struct PPk { const float* w; hf* o; int nc; int k; };
struct PPargs { PPk e[15]; };
__global__ void k_prepack(PPargs pa) {
    PPk p = pa.e[blockIdx.y];
    int tot = p.nc * p.k;
    for (int i = blockIdx.x * 256 + threadIdx.x; i < tot; i += gridDim.x * 256)
        p.o[i] = __float2half(p.w[i]);
}

__global__ void k_prep(const float* __restrict__ h_vec, const float* __restrict__ h_sca,
                       const float* __restrict__ te, const int* __restrict__ tptr,
                       hf* __restrict__ vh, hf* __restrict__ scah, int Nn) {
    int i = blockIdx.x * 256 + threadIdx.x;
    int half = Nn * 64;
    if (i < half) {
        int node = i >> 6, c = i & 63;
#pragma unroll
        for (int d = 0; d < 3; d++) {
            float x = h_vec[(size_t)node * 192 + c * 3 + d];
            vh[(size_t)d * Nn * 64 + (size_t)node * 64 + c] = __float2half(x);
        }
    } else if (i < 2 * half) {
        int j = i - half;
        int node = j >> 6, q4 = (j & 63) * 4;
        int t = *tptr;
        float4 hs = *(const float4*)(h_sca + (size_t)node * 256 + q4);
        float4 tv = *(const float4*)(te + (size_t)t * 256 + q4);
        size_t o = (size_t)node * 256 + q4;
        store_h2(scah, o,     hs.x + tv.x, hs.y + tv.y);
        store_h2(scah, o + 2, hs.z + tv.z, hs.w + tv.w);
    }
}

__global__ void k_att(const hf* __restrict__ Nh, const hf* __restrict__ Sa,
                      const float* __restrict__ Ws, float* __restrict__ att, int Nn) {
    __shared__ float ws[320];
    int tid = threadIdx.x, w = tid >> 5, lane = tid & 31;
    for (int i = tid; i < 320; i += 256) ws[i] = Ws[i];
    __syncthreads();
    int node = blockIdx.x * 8 + w;
    if (node >= Nn) return;
    float p = 0.f;
    for (int c = lane; c < 64; c += 32)
        p = fmaf(ws[c], __half2float(Nh[(size_t)node * 64 + c]), p);
    for (int k = lane; k < 256; k += 32) {
        float sv = __half2float(Sa[(size_t)node * 256 + k]);
        sv = (sv >= 0.f) ? sv : SLOPEF * sv;
        p = fmaf(ws[64 + k], sv, p);
    }
#pragma unroll
    for (int o = 16; o > 0; o >>= 1) p += __shfl_down_sync(0xffffffff, p, o);
    if (lane == 0) att[node] = p;
}

__global__ void k_segstart(const int* __restrict__ bid, int n, int B, int* __restrict__ start) {
    int b = blockIdx.x * blockDim.x + threadIdx.x;
    if (b > B) return;
    int lo = 0, hi = n;
    while (lo < hi) { int mid = (lo + hi) >> 1; if (bid[mid] < b) lo = mid + 1; else hi = mid; }
    start[b] = lo;
}

__global__ void k_softmax(const float* __restrict__ att, const int* __restrict__ start,
                          float* __restrict__ w) {
    int b = blockIdx.x;
    int s = start[b], e = start[b + 1];
    if (s >= e) return;
    __shared__ float red[256];
    int tid = threadIdx.x;
    float m = -INFINITY;
    for (int i = s + tid; i < e; i += 256) m = fmaxf(m, att[i]);
    red[tid] = m; __syncthreads();
    for (int o = 128; o > 0; o >>= 1) { if (tid < o) red[tid] = fmaxf(red[tid], red[tid + o]); __syncthreads(); }
    m = red[0]; __syncthreads();
    float zs = 0.f;
    for (int i = s + tid; i < e; i += 256) zs += __expf(att[i] - m);
    red[tid] = zs; __syncthreads();
    for (int o = 128; o > 0; o >>= 1) { if (tid < o) red[tid] += red[tid + o]; __syncthreads(); }
    float inv = 1.f / red[0];
    for (int i = s + tid; i < e; i += 256) w[i] = __expf(att[i] - m) * inv;
}

__global__ void k_reduce(const float* __restrict__ w, const hf* __restrict__ fs,
                         const hf* __restrict__ fv, const float* __restrict__ pos,
                         const int* __restrict__ start, int B, int Nn, float* __restrict__ out) {
    int b = blockIdx.x, j = threadIdx.x;
    int s = start[b], e = start[b + 1];
    size_t P = (size_t)Nn * 64;
    int c = j / 3, d = j - c * 3;
    float a256 = 0.f, a192 = 0.f, a3 = 0.f;
    for (int i = s; i < e; i++) {
        float wi = w[i];
        a256 = fmaf(wi, __half2float(fs[(size_t)i * 256 + j]), a256);
        if (j < 192)
            a192 = fmaf(wi, __half2float(fv[(size_t)d * P + (size_t)i * 64 + c]), a192);
        if (j < 3) a3 = fmaf(wi, pos[(size_t)i * 3 + j], a3);
    }
    out[(size_t)b * 256 + j] = a256;
    if (j < 192) out[(size_t)B * 256 + (size_t)b * 192 + j] = a192;
    if (j < 3)   out[(size_t)B * 256 + (size_t)B * 192 + (size_t)b * 3 + j] = a3;
}

// ---------------------------------------------------------------------------
extern "C" void kernel_launch(void* const* d_in, const int* in_sizes, int n_in,
                              void* d_out, int out_size) {
    const float* h_sca = (const float*)d_in[0];
    const float* h_vec = (const float*)d_in[1];
    const float* pos   = (const float*)d_in[2];
    const float* te    = (const float*)d_in[3];
    const float* W[26];
    for (int i = 4; i <= 25; i++) W[i] = (const float*)d_in[i];
    const int* tptr = (const int*)d_in[26];
    const int* bid  = (const int*)d_in[27];

    int n = in_sizes[0] / 256;
    int B = out_size / 451;

    hf *vecS, *viAs, *viNs, *uns, *vas, *scaX, *lrS, *Sas, *Sns;
    hf *nA1, *nN1, *nA2, *nN2, *Baug;
    float *Ga, *Gn, *att, *wgt;
    int* segs;
    cudaGetSymbolAddress((void**)&vecS, g_vecS);
    cudaGetSymbolAddress((void**)&viAs, g_viAs);
    cudaGetSymbolAddress((void**)&viNs, g_viNs);
    cudaGetSymbolAddress((void**)&uns,  g_uns);
    cudaGetSymbolAddress((void**)&vas,  g_vas);
    cudaGetSymbolAddress((void**)&scaX, g_scaX);
    cudaGetSymbolAddress((void**)&lrS,  g_lrS);
    cudaGetSymbolAddress((void**)&Sas,  g_Sas);
    cudaGetSymbolAddress((void**)&Sns,  g_Sns);
    cudaGetSymbolAddress((void**)&nA1,  g_nA1);
    cudaGetSymbolAddress((void**)&nN1,  g_nN1);
    cudaGetSymbolAddress((void**)&nA2,  g_nA2);
    cudaGetSymbolAddress((void**)&nN2,  g_nN2);
    cudaGetSymbolAddress((void**)&Baug, g_Baug);
    cudaGetSymbolAddress((void**)&Ga,   g_Ga);
    cudaGetSymbolAddress((void**)&Gn,   g_Gn);
    cudaGetSymbolAddress((void**)&att,  g_att);
    cudaGetSymbolAddress((void**)&wgt,  g_w);
    cudaGetSymbolAddress((void**)&segs, g_seg);

    static const int widx[15] = {4,15, 6,17, 7,18, 5,16, 9,20, 10,21, 23,24,22};
    static const int wnc[15]  = {64,64, 256,256, 64,64, 64,64, 64,64, 64,64, 256,64,64};
    static const int wk[15]   = {64,64, 320,320, 256,256, 64,64, 64,64, 64,64, 320,256,64};
    PPargs pa;
    size_t boff[15]; size_t acc = 0;
    for (int i = 0; i < 15; i++) {
        boff[i] = acc;
        pa.e[i] = PPk{W[widx[i]], Baug + acc, wnc[i], wk[i]};
        acc += (size_t)wnc[i] * wk[i];
    }
    const hf *B_a1Wv1 = Baug + boff[0],  *B_n1Wv1 = Baug + boff[1];
    const hf *B_a1Ws  = Baug + boff[2],  *B_n1Ws  = Baug + boff[3];
    const hf *B_a1Wg  = Baug + boff[4],  *B_n1Wg  = Baug + boff[5];
    const hf *B_a1Wv2 = Baug + boff[6],  *B_n1Wv2 = Baug + boff[7];
    const hf *B_a1Wd  = Baug + boff[8],  *B_n1Wd  = Baug + boff[9];
    const hf *B_a2Wv1 = Baug + boff[10], *B_n2Wv1 = Baug + boff[11];
    const hf *B_n2Ws  = Baug + boff[12], *B_n2Wg  = Baug + boff[13];
    const hf *B_n2Wv2 = Baug + boff[14];

    int M3 = 3 * n;
    int gv = (n + 127) / 128;
    int g3 = (M3 + 127) / 128;

    constexpr int SM64  = 2 * (128 + 64) * 72 * 2;      // 55296 B
    constexpr int SM128 = 3 * (128 + 128) * 72 * 2;     // 110592 B
    constexpr int SMV   = (64 * 72 + 3 * 128 * 72) * 2; // 64512 B
    constexpr int SMC   = (3 * 64 * 72 + 6 * 128 * 72) * 2; // 138240 B
    cudaFuncSetAttribute((const void*)gemm_f16<64>,
                         cudaFuncAttributeMaxDynamicSharedMemorySize, SM64);
    cudaFuncSetAttribute((const void*)gemm_f16<128>,
                         cudaFuncAttributeMaxDynamicSharedMemorySize, SM128);
    cudaFuncSetAttribute((const void*)gemm_vn3,
                         cudaFuncAttributeMaxDynamicSharedMemorySize, SMV);
    cudaFuncSetAttribute((const void*)k_chain,
                         cudaFuncAttributeMaxDynamicSharedMemorySize, SMC);

    auto GS = [](const hf* a1, const hf* a2, int K1, const hf* b,
                 float* cf, hf* ch, hf* lh,
                 const float* bias, const float* gate, int act) {
        GSet g; g.A1 = a1; g.A2 = a2; g.K1 = K1; g.B = b;
        g.Cf = cf; g.Ch = ch; g.Lh = lh;
        g.bias = bias; g.gate = gate; g.act = act; return g;
    };

    k_prepack<<<dim3(64, 15), 256>>>(pa);
    k_prep<<<(n * 128 + 255) / 256, 256>>>(h_vec, h_sca, te, tptr, vecS, scaX, n);

    // vi pair: planes + norms
    {
        VSet a; a.A = vecS; a.B = B_a1Wv1; a.C = viAs; a.Nrm = nA1;
        VSet b; b.A = vecS; b.B = B_n1Wv1; b.C = viNs; b.Nrm = nN1;
        gemm_vn3<<<dim3(gv, 2), 512, SMV>>>(a, b, n);
    }
    // S pair
    gemm_f16<128><<<dim3(gv, 2, 2), 512, SM128>>>(
        GS(nA1, scaX, 64, B_a1Ws, nullptr, Sas, nullptr, nullptr, nullptr, 0),
        GS(nN1, scaX, 64, B_n1Ws, nullptr, Sns, lrS,     nullptr, nullptr, 0),
        n, 320, n, 256);
    // gates pair
    gemm_f16<64><<<dim3(gv, 2, 1), 256, SM64>>>(
        GS(Sas, nullptr, 256, B_a1Wg, Ga, nullptr, nullptr, W[8],  nullptr, 1),
        GS(Sns, nullptr, 256, B_n1Wg, Gn, nullptr, nullptr, W[19], nullptr, 1),
        n, 256, n, 64);
    // fused chain: u -> d -> vnlrelu -> vi2 (att: norms only; net: planes + norms)
    {
        CSet a; a.Vin = viAs; a.gate = Ga; a.W2 = B_a1Wv2; a.Wd = B_a1Wd;
        a.W1p = B_a2Wv1; a.Pout = nullptr; a.Nrm = nA2;
        CSet b; b.Vin = viNs; b.gate = Gn; b.W2 = B_n1Wv2; b.Wd = B_n1Wd;
        b.W1p = B_n2Wv1; b.Pout = uns; b.Nrm = nN2;
        k_chain<<<dim3(gv, 2), 512, SMC>>>(a, b, n);
    }
    k_att<<<(n + 7) / 8, 256>>>(nA2, Sas, W[12], att, n);

    // fs = (norms2 | lrelu(Sn)) @ n2Ws -> Sas reuse
    {
        GSet g = GS(nN2, lrS, 64, B_n2Ws, nullptr, Sas, nullptr, nullptr, nullptr, 0);
        gemm_f16<128><<<dim3(gv, 1, 2), 512, SM128>>>(g, g, n, 320, n, 256);
    }
    // gate2 -> Ga reuse
    {
        GSet g = GS(Sas, nullptr, 256, B_n2Wg, Ga, nullptr, nullptr, W[25], nullptr, 1);
        gemm_f16<64><<<dim3(gv, 1, 1), 256, SM64>>>(g, g, n, 256, n, 64);
    }
    // fv = gate2 * (n2Wv2 @ vi2n) -> vas
    {
        GSet g = GS(uns, nullptr, 64, B_n2Wv2, nullptr, vas, nullptr, nullptr, Ga, 0);
        gemm_f16<64><<<dim3(g3, 1, 1), 256, SM64>>>(g, g, M3, 64, n, 64);
    }

    k_segstart<<<(B + 1 + 255) / 256, 256>>>(bid, n, B, segs);
    k_softmax<<<B, 256>>>(att, segs, wgt);
    k_reduce<<<B, 256>>>(wgt, Sas, vas, pos, segs, B, n, (float*)d_out);
}

// round 16
// speedup vs baseline: 2.4672x; 1.0427x over previous
#include <cuda_runtime.h>
#include <cuda_fp16.h>
#include <math.h>
#include <stdint.h>

typedef __half hf;

#define MAXN   120000
#define SLOPEF 0.01f
#define EPSF   1e-6f
#define PVMAX  (3*MAXN*64)

// ---------------- static device scratch (plain fp16) ------------------------
__device__ __align__(16) hf    g_vecS[PVMAX];
__device__ __align__(16) hf    g_viAs[PVMAX];
__device__ __align__(16) hf    g_viNs[PVMAX];
__device__ __align__(16) hf    g_uns [PVMAX];   // vi2n planes (chain output)
__device__ __align__(16) hf    g_vas [PVMAX];   // fv
__device__ __align__(16) hf    g_scaX[MAXN*256];
__device__ __align__(16) hf    g_lrS [MAXN*256];
__device__ __align__(16) hf    g_Sas [MAXN*256]; // later: fs
__device__ __align__(16) hf    g_Sns [MAXN*256];
__device__ __align__(16) hf    g_nA1 [MAXN*64];
__device__ __align__(16) hf    g_nN1 [MAXN*64];
__device__ __align__(16) hf    g_nA2 [MAXN*64];
__device__ __align__(16) hf    g_nN2 [MAXN*64];
__device__ __align__(16) hf    g_Baug[524288];
__device__ float g_Ga  [MAXN*64];
__device__ float g_Gn  [MAXN*64];
__device__ float g_att [MAXN];
__device__ float g_w   [MAXN];
__device__ int   g_seg [4100];

// ---------------- helpers ----------------
__device__ __forceinline__ uint32_t smem_u32(const void* p) {
    return (uint32_t)__cvta_generic_to_shared(p);
}
__device__ __forceinline__ void store_h2(hf* H, size_t o, float v0, float v1) {
    __half2 t; t.x = __float2half(v0); t.y = __float2half(v1);
    *(__half2*)(H + o) = t;
}

#define MMA16816(d, a, b)                                                     \
    asm volatile("mma.sync.aligned.m16n8k16.row.col.f32.f16.f16.f32 "        \
        "{%0,%1,%2,%3}, {%4,%5,%6,%7}, {%8,%9}, {%0,%1,%2,%3};"              \
        : "+f"((d)[0]), "+f"((d)[1]), "+f"((d)[2]), "+f"((d)[3])             \
        : "r"((a)[0]), "r"((a)[1]), "r"((a)[2]), "r"((a)[3]),                \
          "r"((b)[0]), "r"((b)[1]))

#define LDSM_X4(r0, r1, r2, r3, addr)                                        \
    asm volatile("ldmatrix.sync.aligned.m8n8.x4.shared.b16 {%0,%1,%2,%3}, [%4];" \
        : "=r"(r0), "=r"(r1), "=r"(r2), "=r"(r3) : "r"(addr))

#define CP_ASYNC16(sa, ga)                                                   \
    asm volatile("cp.async.cg.shared.global [%0], [%1], 16;" :: "r"(sa), "l"(ga))
#define CP_ASYNC16_P(sa, ga, p)                                              \
    asm volatile("cp.async.cg.shared.global [%0], [%1], 16, %2;" :: "r"(sa), "l"(ga), "r"(p))
#define CP_COMMIT() asm volatile("cp.async.commit_group;")
#define CP_WAIT0()  asm volatile("cp.async.wait_group 0;")
#define CP_WAIT1()  asm volatile("cp.async.wait_group 1;")
#define CP_WAIT2()  asm volatile("cp.async.wait_group 2;")

// ---------------------------------------------------------------------------
// fp16 HMMA GEMM, compile-time K and K1 (two A regions: [0,K1) A1, [K1,K) A2).
// C[M, NCfull] tile (128 x NC) at column offset blockIdx.z*NC.
// Fully unrolled stage loop -> loader addresses fold to pointer+immediate.
// NC=128: 512 thr, 16 warps 4x4, 3-stage pipeline, minBlocks 2.
// NC=64:  256 thr,  8 warps 4x2, 2-stage pipeline, minBlocks 3.
// ---------------------------------------------------------------------------
struct GSet {
    const hf *A1, *A2;
    const hf* B;
    float* Cf; hf* Ch;
    hf* Lh;
    const float *bias, *gate;
    int act;
};

template <int NC, int K, int K1>
__global__ void __launch_bounds__(NC >= 128 ? 512 : 256, NC >= 128 ? 2 : 3)
gemm_f16(GSet s0, GSet s1, int M, int Nn, int NCfull) {
    constexpr int NTH   = (NC >= 128) ? 512 : 256;
    constexpr int NST   = (NC >= 128) ? 3 : 2;
    constexpr int NWN   = (NC >= 128) ? 4 : 2;
    constexpr int WCOLS = NC / NWN;
    constexpr int NT    = WCOLS / 8;
    constexpr int A_ST  = 128 * 72;
    constexpr int B_ST  = NC * 72;
    constexpr int ST    = K / 64;
    constexpr int K2w   = K - K1;

    extern __shared__ hf sm[];
    hf* smA = sm;
    hf* smB = sm + NST * A_ST;

    const int tid = threadIdx.x;
    const int lane = tid & 31, wid = tid >> 5;
    const int wm = wid / NWN, wn = wid % NWN;
    const GSet S = (blockIdx.y == 0) ? s0 : s1;
    const int m0 = blockIdx.x * 128;
    const int n0 = blockIdx.z * NC;

    float acc[2][NT][4];
#pragma unroll
    for (int i = 0; i < 2; i++)
#pragma unroll
        for (int j = 0; j < NT; j++)
#pragma unroll
            for (int k = 0; k < 4; k++) acc[i][j][k] = 0.f;

    auto load_stage = [&](int s, int buf) {
        const int kof = s * 64;
#pragma unroll
        for (int it = 0; it < 1024 / NTH; it++) {
            int i = tid + it * NTH;
            int r = i >> 3, sg = i & 7;
            int m = m0 + r;
            uint32_t sa = smem_u32(smA + buf * A_ST + r * 72 + sg * 8);
            const hf* ga;
            if (kof < K1) ga = S.A1 + ((m < M) ? ((size_t)m * K1 + kof + sg * 8) : 0);
            else          ga = S.A2 + ((m < M) ? ((size_t)m * K2w + (kof - K1) + sg * 8) : 0);
            CP_ASYNC16_P(sa, ga, (m < M) ? 16 : 0);
        }
#pragma unroll
        for (int it = 0; it < NC * 8 / NTH; it++) {
            int i = tid + it * NTH;
            int r = i >> 3, sg = i & 7;
            uint32_t sa = smem_u32(smB + buf * B_ST + r * 72 + sg * 8);
            CP_ASYNC16(sa, S.B + (size_t)(n0 + r) * K + kof + sg * 8);
        }
        CP_COMMIT();
    };

    uint32_t aBase = smem_u32(smA);
    uint32_t bBase = smem_u32(smB);
    int aOff[2];
#pragma unroll
    for (int mt = 0; mt < 2; mt++)
        aOff[mt] = (wm * 32 + mt * 16 + (lane & 15)) * 72 + (lane >> 4) * 8;
    int bOff;
    {
        int g = lane >> 3, r = lane & 7;
        int nt8 = (g >> 1), ko = (g & 1) * 8;
        bOff = (wn * WCOLS + nt8 * 8 + r) * 72 + ko;
    }

    // prologue: fill NST-1 stages
#pragma unroll
    for (int p = 0; p < NST - 1; p++) {
        if (p < ST) load_stage(p, p);
        else        CP_COMMIT();
    }
#pragma unroll
    for (int s = 0; s < ST; s++) {
        const int buf = s % NST;
        if (NST == 3 && s + 1 < ST) CP_WAIT1();
        else                        CP_WAIT0();
        __syncthreads();
        if (s + NST - 1 < ST)
            load_stage(s + NST - 1, (s + NST - 1) % NST);
        uint32_t aB = aBase + buf * (A_ST * 2);
        uint32_t bB = bBase + buf * (B_ST * 2);
#pragma unroll
        for (int kk = 0; kk < 4; kk++) {
            const int k16 = kk * 16;
            uint32_t a[2][4];
#pragma unroll
            for (int mt = 0; mt < 2; mt++)
                LDSM_X4(a[mt][0], a[mt][1], a[mt][2], a[mt][3],
                        aB + (aOff[mt] + k16) * 2);
            uint32_t b[NT][2];
#pragma unroll
            for (int half = 0; half < NT / 2; half++) {
                uint32_t r0, r1, r2, r3;
                LDSM_X4(r0, r1, r2, r3, bB + (bOff + half * 16 * 72 + k16) * 2);
                b[half * 2 + 0][0] = r0; b[half * 2 + 0][1] = r1;
                b[half * 2 + 1][0] = r2; b[half * 2 + 1][1] = r3;
            }
#pragma unroll
            for (int mt = 0; mt < 2; mt++)
#pragma unroll
                for (int nt = 0; nt < NT; nt++)
                    MMA16816(acc[mt][nt], a[mt], b[nt]);
        }
    }

#pragma unroll
    for (int mt = 0; mt < 2; mt++) {
#pragma unroll
        for (int hh = 0; hh < 2; hh++) {
            int m = m0 + wm * 32 + mt * 16 + (lane >> 2) + hh * 8;
            if (m >= M) continue;
            int node = m % Nn;
#pragma unroll
            for (int nt = 0; nt < NT; nt++) {
                int col = n0 + wn * WCOLS + nt * 8 + (lane & 3) * 2;
                float v0 = acc[mt][nt][hh * 2 + 0];
                float v1 = acc[mt][nt][hh * 2 + 1];
                if (S.act) {
                    v0 = 1.f / (1.f + __expf(-(v0 + S.bias[col])));
                    v1 = 1.f / (1.f + __expf(-(v1 + S.bias[col + 1])));
                }
                if (S.gate) {
                    v0 *= S.gate[(size_t)node * 64 + col];
                    v1 *= S.gate[(size_t)node * 64 + col + 1];
                }
                size_t o = (size_t)m * NCfull + col;
                if (S.Cf) *(float2*)(S.Cf + o) = make_float2(v0, v1);
                if (S.Ch) store_h2(S.Ch, o, v0, v1);
                if (S.Lh) {
                    float l0 = (v0 >= 0.f) ? v0 : SLOPEF * v0;
                    float l1 = (v1 >= 0.f) ? v1 : SLOPEF * v1;
                    store_h2(S.Lh, o, l0, l1);
                }
            }
        }
    }
}

// ---------------------------------------------------------------------------
// 3-plane VN GEMM (vi pair only): preloaded planes, fused norm epilogue.
// ---------------------------------------------------------------------------
struct VSet {
    const hf *A;
    const hf *B;
    hf *C;
    hf *Nrm;
};

__global__ void __launch_bounds__(512, 2)
gemm_vn3(VSet s0, VSet s1, int Nn) {
    extern __shared__ hf vsm[];
    hf* Bs = vsm;
    hf* As = vsm + 64 * 72;
    const int tid = threadIdx.x, lane = tid & 31, wid = tid >> 5;
    const int wm = wid >> 1, wn = wid & 1;
    const VSet S = blockIdx.y ? s1 : s0;
    const int m0 = blockIdx.x * 128;
    const size_t P = (size_t)Nn * 64;

    auto loadA = [&](int d) {
#pragma unroll
        for (int it = 0; it < 2; it++) {
            int i = tid + it * 512;
            int r = i >> 3, sg = i & 7;
            int m = m0 + r;
            uint32_t sa = smem_u32(As + d * (128 * 72) + r * 72 + sg * 8);
            const hf* ga = S.A + d * P + ((m < Nn) ? ((size_t)m * 64 + sg * 8) : 0);
            CP_ASYNC16_P(sa, ga, (m < Nn) ? 16 : 0);
        }
        CP_COMMIT();
    };

    {
        int r = tid >> 3, c8 = tid & 7;
        CP_ASYNC16(smem_u32(Bs + r * 72 + c8 * 8), S.B + r * 64 + c8 * 8);
    }
    loadA(0);
    loadA(1);
    loadA(2);

    float acc[3][4][4];
#pragma unroll
    for (int d = 0; d < 3; d++)
#pragma unroll
        for (int j = 0; j < 4; j++)
#pragma unroll
            for (int k = 0; k < 4; k++) acc[d][j][k] = 0.f;

    int aOff = (wm * 16 + (lane & 15)) * 72 + (lane >> 4) * 8;
    int bOff;
    {
        int g = lane >> 3, r = lane & 7;
        int nt8 = (g >> 1), ko = (g & 1) * 8;
        bOff = (wn * 32 + nt8 * 8 + r) * 72 + ko;
    }
    uint32_t aBase = smem_u32(As);
    uint32_t bBase = smem_u32(Bs);

#pragma unroll
    for (int d = 0; d < 3; d++) {
        if (d == 0) CP_WAIT2();
        else if (d == 1) CP_WAIT1();
        else CP_WAIT0();
        __syncthreads();
        uint32_t aB = aBase + d * (128 * 72 * 2);
#pragma unroll
        for (int kk = 0; kk < 4; kk++) {
            const int k16 = kk * 16;
            uint32_t a[4];
            LDSM_X4(a[0], a[1], a[2], a[3], aB + (aOff + k16) * 2);
            uint32_t b[4][2];
#pragma unroll
            for (int half = 0; half < 2; half++) {
                uint32_t r0, r1, r2, r3;
                LDSM_X4(r0, r1, r2, r3, bBase + (bOff + half * 16 * 72 + k16) * 2);
                b[half * 2 + 0][0] = r0; b[half * 2 + 0][1] = r1;
                b[half * 2 + 1][0] = r2; b[half * 2 + 1][1] = r3;
            }
#pragma unroll
            for (int nt = 0; nt < 4; nt++)
                MMA16816(acc[d][nt], a, b[nt]);
        }
    }

#pragma unroll
    for (int hh = 0; hh < 2; hh++) {
        int m = m0 + wm * 16 + (lane >> 2) + hh * 8;
        if (m >= Nn) continue;
#pragma unroll
        for (int nt = 0; nt < 4; nt++) {
            int col = wn * 32 + nt * 8 + (lane & 3) * 2;
            float v[3][2];
#pragma unroll
            for (int d = 0; d < 3; d++) {
                v[d][0] = acc[d][nt][hh * 2 + 0];
                v[d][1] = acc[d][nt][hh * 2 + 1];
            }
            if (S.C) {
#pragma unroll
                for (int d = 0; d < 3; d++)
                    store_h2(S.C, d * P + (size_t)m * 64 + col, v[d][0], v[d][1]);
            }
            if (S.Nrm) {
                float n0 = sqrtf(v[0][0] * v[0][0] + v[1][0] * v[1][0] + v[2][0] * v[2][0]);
                float n1 = sqrtf(v[0][1] * v[0][1] + v[1][1] * v[1][1] + v[2][1] * v[2][1]);
                store_h2(S.Nrm, (size_t)m * 64 + col, n0, n1);
            }
        }
    }
}

// ---------------------------------------------------------------------------
// CHAIN kernel: per block of 128 nodes, entirely in smem:
//   u = gate ⊙ (vi @ W2ᵀ) ; d = u @ Wdᵀ ; v = vnlrelu(u,d) ; vi2 = v @ W1pᵀ
// ---------------------------------------------------------------------------
struct CSet {
    const hf* Vin;
    const float* gate;
    const hf *W2, *Wd, *W1p;
    hf* Pout;
    hf* Nrm;
};

__global__ void __launch_bounds__(512, 1)
k_chain(CSet s0, CSet s1, int Nn) {
    constexpr int WP = 64 * 72;
    constexpr int XP = 128 * 72;
    extern __shared__ hf csm[];
    hf* Wsm = csm;
    hf* X   = csm + 3 * WP;
    hf* U   = X + 3 * XP;

    const int tid = threadIdx.x, lane = tid & 31, wid = tid >> 5;
    const int wm = wid >> 1, wn = wid & 1;
    const CSet S = blockIdx.y ? s1 : s0;
    const int m0 = blockIdx.x * 128;
    const size_t P = (size_t)Nn * 64;

    for (int i = tid; i < 1536; i += 512) {
        int w = i >> 9, j = i & 511;
        int r = j >> 3, c8 = j & 7;
        const hf* src = (w == 0) ? S.W2 : ((w == 1) ? S.Wd : S.W1p);
        CP_ASYNC16(smem_u32(Wsm + w * WP + r * 72 + c8 * 8), src + r * 64 + c8 * 8);
    }
    for (int i = tid; i < 3072; i += 512) {
        int d = i >> 10, j = i & 1023;
        int r = j >> 3, sg = j & 7;
        int m = m0 + r;
        uint32_t sa = smem_u32(X + d * XP + r * 72 + sg * 8);
        const hf* ga = S.Vin + d * P + ((m < Nn) ? ((size_t)m * 64 + sg * 8) : 0);
        CP_ASYNC16_P(sa, ga, (m < Nn) ? 16 : 0);
    }
    CP_COMMIT();

    const int aOff = (wm * 16 + (lane & 15)) * 72 + (lane >> 4) * 8;
    int bOff;
    {
        int g = lane >> 3, r = lane & 7;
        int nt8 = (g >> 1), ko = (g & 1) * 8;
        bOff = (wn * 32 + nt8 * 8 + r) * 72 + ko;
    }
    const int mlBase = wm * 16 + (lane >> 2);
    const int colBase = wn * 32 + (lane & 3) * 2;

    auto gemm64 = [&](uint32_t aTile, uint32_t bTile, float acc[4][4]) {
#pragma unroll
        for (int j = 0; j < 4; j++)
#pragma unroll
            for (int k = 0; k < 4; k++) acc[j][k] = 0.f;
#pragma unroll
        for (int kk = 0; kk < 4; kk++) {
            const int k16 = kk * 16;
            uint32_t a[4];
            LDSM_X4(a[0], a[1], a[2], a[3], aTile + (aOff + k16) * 2);
            uint32_t b[4][2];
#pragma unroll
            for (int half = 0; half < 2; half++) {
                uint32_t r0, r1, r2, r3;
                LDSM_X4(r0, r1, r2, r3, bTile + (bOff + half * 16 * 72 + k16) * 2);
                b[half * 2 + 0][0] = r0; b[half * 2 + 0][1] = r1;
                b[half * 2 + 1][0] = r2; b[half * 2 + 1][1] = r3;
            }
#pragma unroll
            for (int nt = 0; nt < 4; nt++)
                MMA16816(acc[nt], a, b[nt]);
        }
    };

    uint32_t xB = smem_u32(X);
    uint32_t uB = smem_u32(U);
    uint32_t wB = smem_u32(Wsm);

    CP_WAIT0();
    __syncthreads();

    // phase 1: u = gate * (vi @ W2^T)
#pragma unroll
    for (int d = 0; d < 3; d++) {
        float acc[4][4];
        gemm64(xB + d * (XP * 2), wB, acc);
#pragma unroll
        for (int hh = 0; hh < 2; hh++) {
            int ml = mlBase + hh * 8;
            int node = m0 + ml;
            if (node >= Nn) continue;
#pragma unroll
            for (int nt = 0; nt < 4; nt++) {
                int col = colBase + nt * 8;
                float2 gg = *(const float2*)(S.gate + (size_t)node * 64 + col);
                float v0 = acc[nt][hh * 2 + 0] * gg.x;
                float v1 = acc[nt][hh * 2 + 1] * gg.y;
                store_h2(U + d * XP, (size_t)ml * 72 + col, v0, v1);
            }
        }
    }
    __syncthreads();

    // phase 2: d = u @ Wd^T ; v = vnlrelu(u, d) -> X
    {
        float acc3[3][4][4];
#pragma unroll
        for (int d = 0; d < 3; d++)
            gemm64(uB + d * (XP * 2), wB + WP * 2, acc3[d]);
#pragma unroll
        for (int hh = 0; hh < 2; hh++) {
            int ml = mlBase + hh * 8;
#pragma unroll
            for (int nt = 0; nt < 4; nt++) {
                int col = colBase + nt * 8;
                float dd[3][2], uu[3][2];
#pragma unroll
                for (int d = 0; d < 3; d++) {
                    dd[d][0] = acc3[d][nt][hh * 2 + 0];
                    dd[d][1] = acc3[d][nt][hh * 2 + 1];
                    __half2 uh = *(const __half2*)(U + d * XP + (size_t)ml * 72 + col);
                    uu[d][0] = __half2float(uh.x);
                    uu[d][1] = __half2float(uh.y);
                }
#pragma unroll
                for (int e = 0; e < 2; e++) {
                    float dot = uu[0][e] * dd[0][e] + uu[1][e] * dd[1][e] + uu[2][e] * dd[2][e];
                    float dsq = dd[0][e] * dd[0][e] + dd[1][e] * dd[1][e] + dd[2][e] * dd[2][e];
                    float sc = dot / (dsq + EPSF);
#pragma unroll
                    for (int d = 0; d < 3; d++) {
                        float x = uu[d][e];
                        dd[d][e] = (dot >= 0.f) ? x
                                 : (SLOPEF * x + (1.f - SLOPEF) * (x - sc * dd[d][e]));
                    }
                }
#pragma unroll
                for (int d = 0; d < 3; d++)
                    store_h2(X + d * XP, (size_t)ml * 72 + col, dd[d][0], dd[d][1]);
            }
        }
    }
    __syncthreads();

    // phase 3: vi2 = v @ W1p^T ; norms + optional planes out
    {
        float acc3[3][4][4];
#pragma unroll
        for (int d = 0; d < 3; d++)
            gemm64(xB + d * (XP * 2), wB + 2 * WP * 2, acc3[d]);
#pragma unroll
        for (int hh = 0; hh < 2; hh++) {
            int ml = mlBase + hh * 8;
            int m = m0 + ml;
            if (m >= Nn) continue;
#pragma unroll
            for (int nt = 0; nt < 4; nt++) {
                int col = colBase + nt * 8;
                float v[3][2];
#pragma unroll
                for (int d = 0; d < 3; d++) {
                    v[d][0] = acc3[d][nt][hh * 2 + 0];
                    v[d][1] = acc3[d][nt][hh * 2 + 1];
                }
                if (S.Pout) {
#pragma unroll
                    for (int d = 0; d < 3; d++)
                        store_h2(S.Pout, d * P + (size_t)m * 64 + col, v[d][0], v[d][1]);
                }
                float n0 = sqrtf(v[0][0] * v[0][0] + v[1][0] * v[1][0] + v[2][0] * v[2][0]);
                float n1 = sqrtf(v[0][1] * v[0][1] + v[1][1] * v[1][1] + v[2][1] * v[2][1]);
                store_h2(S.Nrm, (size_t)m * 64 + col, n0, n1);
            }
        }
    }
}

// ---------------------------------------------------------------------------
struct PPk { const float* w; hf* o; int nc; int k; };
struct PPargs { PPk e[15]; };
__global__ void k_prepack(PPargs pa) {
    PPk p = pa.e[blockIdx.y];
    int tot = p.nc * p.k;
    for (int i = blockIdx.x * 256 + threadIdx.x; i < tot; i += gridDim.x * 256)
        p.o[i] = __float2half(p.w[i]);
}

__global__ void k_prep(const float* __restrict__ h_vec, const float* __restrict__ h_sca,
                       const float* __restrict__ te, const int* __restrict__ tptr,
                       hf* __restrict__ vh, hf* __restrict__ scah, int Nn) {
    int i = blockIdx.x * 256 + threadIdx.x;
    int half = Nn * 64;
    if (i < half) {
        int node = i >> 6, c = i & 63;
#pragma unroll
        for (int d = 0; d < 3; d++) {
            float x = h_vec[(size_t)node * 192 + c * 3 + d];
            vh[(size_t)d * Nn * 64 + (size_t)node * 64 + c] = __float2half(x);
        }
    } else if (i < 2 * half) {
        int j = i - half;
        int node = j >> 6, q4 = (j & 63) * 4;
        int t = *tptr;
        float4 hs = *(const float4*)(h_sca + (size_t)node * 256 + q4);
        float4 tv = *(const float4*)(te + (size_t)t * 256 + q4);
        size_t o = (size_t)node * 256 + q4;
        store_h2(scah, o,     hs.x + tv.x, hs.y + tv.y);
        store_h2(scah, o + 2, hs.z + tv.z, hs.w + tv.w);
    }
}

__global__ void k_att(const hf* __restrict__ Nh, const hf* __restrict__ Sa,
                      const float* __restrict__ Ws, float* __restrict__ att, int Nn) {
    __shared__ float ws[320];
    int tid = threadIdx.x, w = tid >> 5, lane = tid & 31;
    for (int i = tid; i < 320; i += 256) ws[i] = Ws[i];
    __syncthreads();
    int node = blockIdx.x * 8 + w;
    if (node >= Nn) return;
    float p = 0.f;
    for (int c = lane; c < 64; c += 32)
        p = fmaf(ws[c], __half2float(Nh[(size_t)node * 64 + c]), p);
    for (int k = lane; k < 256; k += 32) {
        float sv = __half2float(Sa[(size_t)node * 256 + k]);
        sv = (sv >= 0.f) ? sv : SLOPEF * sv;
        p = fmaf(ws[64 + k], sv, p);
    }
#pragma unroll
    for (int o = 16; o > 0; o >>= 1) p += __shfl_down_sync(0xffffffff, p, o);
    if (lane == 0) att[node] = p;
}

__global__ void k_segstart(const int* __restrict__ bid, int n, int B, int* __restrict__ start) {
    int b = blockIdx.x * blockDim.x + threadIdx.x;
    if (b > B) return;
    int lo = 0, hi = n;
    while (lo < hi) { int mid = (lo + hi) >> 1; if (bid[mid] < b) lo = mid + 1; else hi = mid; }
    start[b] = lo;
}

__global__ void k_softmax(const float* __restrict__ att, const int* __restrict__ start,
                          float* __restrict__ w) {
    int b = blockIdx.x;
    int s = start[b], e = start[b + 1];
    if (s >= e) return;
    __shared__ float red[256];
    int tid = threadIdx.x;
    float m = -INFINITY;
    for (int i = s + tid; i < e; i += 256) m = fmaxf(m, att[i]);
    red[tid] = m; __syncthreads();
    for (int o = 128; o > 0; o >>= 1) { if (tid < o) red[tid] = fmaxf(red[tid], red[tid + o]); __syncthreads(); }
    m = red[0]; __syncthreads();
    float zs = 0.f;
    for (int i = s + tid; i < e; i += 256) zs += __expf(att[i] - m);
    red[tid] = zs; __syncthreads();
    for (int o = 128; o > 0; o >>= 1) { if (tid < o) red[tid] += red[tid + o]; __syncthreads(); }
    float inv = 1.f / red[0];
    for (int i = s + tid; i < e; i += 256) w[i] = __expf(att[i] - m) * inv;
}

__global__ void k_reduce(const float* __restrict__ w, const hf* __restrict__ fs,
                         const hf* __restrict__ fv, const float* __restrict__ pos,
                         const int* __restrict__ start, int B, int Nn, float* __restrict__ out) {
    int b = blockIdx.x, j = threadIdx.x;
    int s = start[b], e = start[b + 1];
    size_t P = (size_t)Nn * 64;
    int c = j / 3, d = j - c * 3;
    float a256 = 0.f, a192 = 0.f, a3 = 0.f;
    for (int i = s; i < e; i++) {
        float wi = w[i];
        a256 = fmaf(wi, __half2float(fs[(size_t)i * 256 + j]), a256);
        if (j < 192)
            a192 = fmaf(wi, __half2float(fv[(size_t)d * P + (size_t)i * 64 + c]), a192);
        if (j < 3) a3 = fmaf(wi, pos[(size_t)i * 3 + j], a3);
    }
    out[(size_t)b * 256 + j] = a256;
    if (j < 192) out[(size_t)B * 256 + (size_t)b * 192 + j] = a192;
    if (j < 3)   out[(size_t)B * 256 + (size_t)B * 192 + (size_t)b * 3 + j] = a3;
}

// ---------------------------------------------------------------------------
extern "C" void kernel_launch(void* const* d_in, const int* in_sizes, int n_in,
                              void* d_out, int out_size) {
    const float* h_sca = (const float*)d_in[0];
    const float* h_vec = (const float*)d_in[1];
    const float* pos   = (const float*)d_in[2];
    const float* te    = (const float*)d_in[3];
    const float* W[26];
    for (int i = 4; i <= 25; i++) W[i] = (const float*)d_in[i];
    const int* tptr = (const int*)d_in[26];
    const int* bid  = (const int*)d_in[27];

    int n = in_sizes[0] / 256;
    int B = out_size / 451;

    hf *vecS, *viAs, *viNs, *uns, *vas, *scaX, *lrS, *Sas, *Sns;
    hf *nA1, *nN1, *nA2, *nN2, *Baug;
    float *Ga, *Gn, *att, *wgt;
    int* segs;
    cudaGetSymbolAddress((void**)&vecS, g_vecS);
    cudaGetSymbolAddress((void**)&viAs, g_viAs);
    cudaGetSymbolAddress((void**)&viNs, g_viNs);
    cudaGetSymbolAddress((void**)&uns,  g_uns);
    cudaGetSymbolAddress((void**)&vas,  g_vas);
    cudaGetSymbolAddress((void**)&scaX, g_scaX);
    cudaGetSymbolAddress((void**)&lrS,  g_lrS);
    cudaGetSymbolAddress((void**)&Sas,  g_Sas);
    cudaGetSymbolAddress((void**)&Sns,  g_Sns);
    cudaGetSymbolAddress((void**)&nA1,  g_nA1);
    cudaGetSymbolAddress((void**)&nN1,  g_nN1);
    cudaGetSymbolAddress((void**)&nA2,  g_nA2);
    cudaGetSymbolAddress((void**)&nN2,  g_nN2);
    cudaGetSymbolAddress((void**)&Baug, g_Baug);
    cudaGetSymbolAddress((void**)&Ga,   g_Ga);
    cudaGetSymbolAddress((void**)&Gn,   g_Gn);
    cudaGetSymbolAddress((void**)&att,  g_att);
    cudaGetSymbolAddress((void**)&wgt,  g_w);
    cudaGetSymbolAddress((void**)&segs, g_seg);

    static const int widx[15] = {4,15, 6,17, 7,18, 5,16, 9,20, 10,21, 23,24,22};
    static const int wnc[15]  = {64,64, 256,256, 64,64, 64,64, 64,64, 64,64, 256,64,64};
    static const int wk[15]   = {64,64, 320,320, 256,256, 64,64, 64,64, 64,64, 320,256,64};
    PPargs pa;
    size_t boff[15]; size_t acc = 0;
    for (int i = 0; i < 15; i++) {
        boff[i] = acc;
        pa.e[i] = PPk{W[widx[i]], Baug + acc, wnc[i], wk[i]};
        acc += (size_t)wnc[i] * wk[i];
    }
    const hf *B_a1Wv1 = Baug + boff[0],  *B_n1Wv1 = Baug + boff[1];
    const hf *B_a1Ws  = Baug + boff[2],  *B_n1Ws  = Baug + boff[3];
    const hf *B_a1Wg  = Baug + boff[4],  *B_n1Wg  = Baug + boff[5];
    const hf *B_a1Wv2 = Baug + boff[6],  *B_n1Wv2 = Baug + boff[7];
    const hf *B_a1Wd  = Baug + boff[8],  *B_n1Wd  = Baug + boff[9];
    const hf *B_a2Wv1 = Baug + boff[10], *B_n2Wv1 = Baug + boff[11];
    const hf *B_n2Ws  = Baug + boff[12], *B_n2Wg  = Baug + boff[13];
    const hf *B_n2Wv2 = Baug + boff[14];

    int M3 = 3 * n;
    int gv = (n + 127) / 128;
    int g3 = (M3 + 127) / 128;

    constexpr int SM64  = 2 * (128 + 64) * 72 * 2;      // 55296 B
    constexpr int SM128 = 3 * (128 + 128) * 72 * 2;     // 110592 B
    constexpr int SMV   = (64 * 72 + 3 * 128 * 72) * 2; // 64512 B
    constexpr int SMC   = (3 * 64 * 72 + 6 * 128 * 72) * 2; // 138240 B
    cudaFuncSetAttribute((const void*)gemm_f16<64, 256, 256>,
                         cudaFuncAttributeMaxDynamicSharedMemorySize, SM64);
    cudaFuncSetAttribute((const void*)gemm_f16<64, 64, 64>,
                         cudaFuncAttributeMaxDynamicSharedMemorySize, SM64);
    cudaFuncSetAttribute((const void*)gemm_f16<128, 320, 64>,
                         cudaFuncAttributeMaxDynamicSharedMemorySize, SM128);
    cudaFuncSetAttribute((const void*)gemm_vn3,
                         cudaFuncAttributeMaxDynamicSharedMemorySize, SMV);
    cudaFuncSetAttribute((const void*)k_chain,
                         cudaFuncAttributeMaxDynamicSharedMemorySize, SMC);

    auto GS = [](const hf* a1, const hf* a2, const hf* b,
                 float* cf, hf* ch, hf* lh,
                 const float* bias, const float* gate, int act) {
        GSet g; g.A1 = a1; g.A2 = a2; g.B = b;
        g.Cf = cf; g.Ch = ch; g.Lh = lh;
        g.bias = bias; g.gate = gate; g.act = act; return g;
    };

    k_prepack<<<dim3(64, 15), 256>>>(pa);
    k_prep<<<(n * 128 + 255) / 256, 256>>>(h_vec, h_sca, te, tptr, vecS, scaX, n);

    // vi pair: planes + norms
    {
        VSet a; a.A = vecS; a.B = B_a1Wv1; a.C = viAs; a.Nrm = nA1;
        VSet b; b.A = vecS; b.B = B_n1Wv1; b.C = viNs; b.Nrm = nN1;
        gemm_vn3<<<dim3(gv, 2), 512, SMV>>>(a, b, n);
    }
    // S pair: A = (norms | sca shared); net side also emits lrelu(Sn)
    gemm_f16<128, 320, 64><<<dim3(gv, 2, 2), 512, SM128>>>(
        GS(nA1, scaX, B_a1Ws, nullptr, Sas, nullptr, nullptr, nullptr, 0),
        GS(nN1, scaX, B_n1Ws, nullptr, Sns, lrS,     nullptr, nullptr, 0),
        n, n, 256);
    // gates pair
    gemm_f16<64, 256, 256><<<dim3(gv, 2, 1), 256, SM64>>>(
        GS(Sas, nullptr, B_a1Wg, Ga, nullptr, nullptr, W[8],  nullptr, 1),
        GS(Sns, nullptr, B_n1Wg, Gn, nullptr, nullptr, W[19], nullptr, 1),
        n, n, 64);
    // fused chain: u -> d -> vnlrelu -> vi2
    {
        CSet a; a.Vin = viAs; a.gate = Ga; a.W2 = B_a1Wv2; a.Wd = B_a1Wd;
        a.W1p = B_a2Wv1; a.Pout = nullptr; a.Nrm = nA2;
        CSet b; b.Vin = viNs; b.gate = Gn; b.W2 = B_n1Wv2; b.Wd = B_n1Wd;
        b.W1p = B_n2Wv1; b.Pout = uns; b.Nrm = nN2;
        k_chain<<<dim3(gv, 2), 512, SMC>>>(a, b, n);
    }
    k_att<<<(n + 7) / 8, 256>>>(nA2, Sas, W[12], att, n);

    // fs = (norms2 | lrelu(Sn)) @ n2Ws -> Sas reuse
    {
        GSet g = GS(nN2, lrS, B_n2Ws, nullptr, Sas, nullptr, nullptr, nullptr, 0);
        gemm_f16<128, 320, 64><<<dim3(gv, 1, 2), 512, SM128>>>(g, g, n, n, 256);
    }
    // gate2 -> Ga reuse
    {
        GSet g = GS(Sas, nullptr, B_n2Wg, Ga, nullptr, nullptr, W[25], nullptr, 1);
        gemm_f16<64, 256, 256><<<dim3(gv, 1, 1), 256, SM64>>>(g, g, n, n, 64);
    }
    // fv = gate2 * (n2Wv2 @ vi2n) -> vas
    {
        GSet g = GS(uns, nullptr, B_n2Wv2, nullptr, vas, nullptr, nullptr, Ga, 0);
        gemm_f16<64, 64, 64><<<dim3(g3, 1, 1), 256, SM64>>>(g, g, M3, n, 64);
    }

    k_segstart<<<(B + 1 + 255) / 256, 256>>>(bid, n, B, segs);
    k_softmax<<<B, 256>>>(att, segs, wgt);
    k_reduce<<<B, 256>>>(wgt, Sas, vas, pos, segs, B, n, (float*)d_out);
}

// round 17
// speedup vs baseline: 2.4809x; 1.0056x over previous
#include <cuda_runtime.h>
#include <cuda_fp16.h>
#include <math.h>
#include <stdint.h>

typedef __half hf;

#define MAXN   120000
#define SLOPEF 0.01f
#define EPSF   1e-6f
#define PVMAX  (3*MAXN*64)

// ---------------- static device scratch (plain fp16) ------------------------
__device__ __align__(16) hf    g_vecS[PVMAX];
__device__ __align__(16) hf    g_viAs[PVMAX];
__device__ __align__(16) hf    g_viNs[PVMAX];
__device__ __align__(16) hf    g_uns [PVMAX];   // vi2n planes (chain output)
__device__ __align__(16) hf    g_vas [PVMAX];   // fv
__device__ __align__(16) hf    g_scaX[MAXN*256];
__device__ __align__(16) hf    g_lrS [MAXN*256];
__device__ __align__(16) hf    g_Sas [MAXN*256]; // later: fs
__device__ __align__(16) hf    g_Sns [MAXN*256];
__device__ __align__(16) hf    g_nA1 [MAXN*64];
__device__ __align__(16) hf    g_nN1 [MAXN*64];
__device__ __align__(16) hf    g_nA2 [MAXN*64];
__device__ __align__(16) hf    g_nN2 [MAXN*64];
__device__ __align__(16) hf    g_Baug[524288];
__device__ float g_Ga  [MAXN*64];
__device__ float g_Gn  [MAXN*64];
__device__ float g_att [MAXN];
__device__ float g_w   [MAXN];
__device__ int   g_seg [4100];

// ---------------- helpers ----------------
__device__ __forceinline__ uint32_t smem_u32(const void* p) {
    return (uint32_t)__cvta_generic_to_shared(p);
}
__device__ __forceinline__ void store_h2(hf* H, size_t o, float v0, float v1) {
    __half2 t; t.x = __float2half(v0); t.y = __float2half(v1);
    *(__half2*)(H + o) = t;
}

#define MMA16816(d, a, b)                                                     \
    asm volatile("mma.sync.aligned.m16n8k16.row.col.f32.f16.f16.f32 "        \
        "{%0,%1,%2,%3}, {%4,%5,%6,%7}, {%8,%9}, {%0,%1,%2,%3};"              \
        : "+f"((d)[0]), "+f"((d)[1]), "+f"((d)[2]), "+f"((d)[3])             \
        : "r"((a)[0]), "r"((a)[1]), "r"((a)[2]), "r"((a)[3]),                \
          "r"((b)[0]), "r"((b)[1]))

#define LDSM_X4(r0, r1, r2, r3, addr)                                        \
    asm volatile("ldmatrix.sync.aligned.m8n8.x4.shared.b16 {%0,%1,%2,%3}, [%4];" \
        : "=r"(r0), "=r"(r1), "=r"(r2), "=r"(r3) : "r"(addr))

#define CP_ASYNC16(sa, ga)                                                   \
    asm volatile("cp.async.cg.shared.global [%0], [%1], 16;" :: "r"(sa), "l"(ga))
#define CP_ASYNC16_P(sa, ga, p)                                              \
    asm volatile("cp.async.cg.shared.global [%0], [%1], 16, %2;" :: "r"(sa), "l"(ga), "r"(p))
#define CP_COMMIT() asm volatile("cp.async.commit_group;")
#define CP_WAIT0()  asm volatile("cp.async.wait_group 0;")
#define CP_WAIT1()  asm volatile("cp.async.wait_group 1;")
#define CP_WAIT2()  asm volatile("cp.async.wait_group 2;")

// ---------------------------------------------------------------------------
// fp16 HMMA GEMM, compile-time K and K1 (two A regions: [0,K1) A1, [K1,K) A2).
// (unchanged from round 16)
// ---------------------------------------------------------------------------
struct GSet {
    const hf *A1, *A2;
    const hf* B;
    float* Cf; hf* Ch;
    hf* Lh;
    const float *bias, *gate;
    int act;
};

template <int NC, int K, int K1>
__global__ void __launch_bounds__(NC >= 128 ? 512 : 256, NC >= 128 ? 2 : 3)
gemm_f16(GSet s0, GSet s1, int M, int Nn, int NCfull) {
    constexpr int NTH   = (NC >= 128) ? 512 : 256;
    constexpr int NST   = (NC >= 128) ? 3 : 2;
    constexpr int NWN   = (NC >= 128) ? 4 : 2;
    constexpr int WCOLS = NC / NWN;
    constexpr int NT    = WCOLS / 8;
    constexpr int A_ST  = 128 * 72;
    constexpr int B_ST  = NC * 72;
    constexpr int ST    = K / 64;
    constexpr int K2w   = K - K1;

    extern __shared__ hf sm[];
    hf* smA = sm;
    hf* smB = sm + NST * A_ST;

    const int tid = threadIdx.x;
    const int lane = tid & 31, wid = tid >> 5;
    const int wm = wid / NWN, wn = wid % NWN;
    const GSet S = (blockIdx.y == 0) ? s0 : s1;
    const int m0 = blockIdx.x * 128;
    const int n0 = blockIdx.z * NC;

    float acc[2][NT][4];
#pragma unroll
    for (int i = 0; i < 2; i++)
#pragma unroll
        for (int j = 0; j < NT; j++)
#pragma unroll
            for (int k = 0; k < 4; k++) acc[i][j][k] = 0.f;

    auto load_stage = [&](int s, int buf) {
        const int kof = s * 64;
#pragma unroll
        for (int it = 0; it < 1024 / NTH; it++) {
            int i = tid + it * NTH;
            int r = i >> 3, sg = i & 7;
            int m = m0 + r;
            uint32_t sa = smem_u32(smA + buf * A_ST + r * 72 + sg * 8);
            const hf* ga;
            if (kof < K1) ga = S.A1 + ((m < M) ? ((size_t)m * K1 + kof + sg * 8) : 0);
            else          ga = S.A2 + ((m < M) ? ((size_t)m * K2w + (kof - K1) + sg * 8) : 0);
            CP_ASYNC16_P(sa, ga, (m < M) ? 16 : 0);
        }
#pragma unroll
        for (int it = 0; it < NC * 8 / NTH; it++) {
            int i = tid + it * NTH;
            int r = i >> 3, sg = i & 7;
            uint32_t sa = smem_u32(smB + buf * B_ST + r * 72 + sg * 8);
            CP_ASYNC16(sa, S.B + (size_t)(n0 + r) * K + kof + sg * 8);
        }
        CP_COMMIT();
    };

    uint32_t aBase = smem_u32(smA);
    uint32_t bBase = smem_u32(smB);
    int aOff[2];
#pragma unroll
    for (int mt = 0; mt < 2; mt++)
        aOff[mt] = (wm * 32 + mt * 16 + (lane & 15)) * 72 + (lane >> 4) * 8;
    int bOff;
    {
        int g = lane >> 3, r = lane & 7;
        int nt8 = (g >> 1), ko = (g & 1) * 8;
        bOff = (wn * WCOLS + nt8 * 8 + r) * 72 + ko;
    }

#pragma unroll
    for (int p = 0; p < NST - 1; p++) {
        if (p < ST) load_stage(p, p);
        else        CP_COMMIT();
    }
#pragma unroll
    for (int s = 0; s < ST; s++) {
        const int buf = s % NST;
        if (NST == 3 && s + 1 < ST) CP_WAIT1();
        else                        CP_WAIT0();
        __syncthreads();
        if (s + NST - 1 < ST)
            load_stage(s + NST - 1, (s + NST - 1) % NST);
        uint32_t aB = aBase + buf * (A_ST * 2);
        uint32_t bB = bBase + buf * (B_ST * 2);
#pragma unroll
        for (int kk = 0; kk < 4; kk++) {
            const int k16 = kk * 16;
            uint32_t a[2][4];
#pragma unroll
            for (int mt = 0; mt < 2; mt++)
                LDSM_X4(a[mt][0], a[mt][1], a[mt][2], a[mt][3],
                        aB + (aOff[mt] + k16) * 2);
            uint32_t b[NT][2];
#pragma unroll
            for (int half = 0; half < NT / 2; half++) {
                uint32_t r0, r1, r2, r3;
                LDSM_X4(r0, r1, r2, r3, bB + (bOff + half * 16 * 72 + k16) * 2);
                b[half * 2 + 0][0] = r0; b[half * 2 + 0][1] = r1;
                b[half * 2 + 1][0] = r2; b[half * 2 + 1][1] = r3;
            }
#pragma unroll
            for (int mt = 0; mt < 2; mt++)
#pragma unroll
                for (int nt = 0; nt < NT; nt++)
                    MMA16816(acc[mt][nt], a[mt], b[nt]);
        }
    }

#pragma unroll
    for (int mt = 0; mt < 2; mt++) {
#pragma unroll
        for (int hh = 0; hh < 2; hh++) {
            int m = m0 + wm * 32 + mt * 16 + (lane >> 2) + hh * 8;
            if (m >= M) continue;
            int node = m % Nn;
#pragma unroll
            for (int nt = 0; nt < NT; nt++) {
                int col = n0 + wn * WCOLS + nt * 8 + (lane & 3) * 2;
                float v0 = acc[mt][nt][hh * 2 + 0];
                float v1 = acc[mt][nt][hh * 2 + 1];
                if (S.act) {
                    v0 = 1.f / (1.f + __expf(-(v0 + S.bias[col])));
                    v1 = 1.f / (1.f + __expf(-(v1 + S.bias[col + 1])));
                }
                if (S.gate) {
                    v0 *= S.gate[(size_t)node * 64 + col];
                    v1 *= S.gate[(size_t)node * 64 + col + 1];
                }
                size_t o = (size_t)m * NCfull + col;
                if (S.Cf) *(float2*)(S.Cf + o) = make_float2(v0, v1);
                if (S.Ch) store_h2(S.Ch, o, v0, v1);
                if (S.Lh) {
                    float l0 = (v0 >= 0.f) ? v0 : SLOPEF * v0;
                    float l1 = (v1 >= 0.f) ? v1 : SLOPEF * v1;
                    store_h2(S.Lh, o, l0, l1);
                }
            }
        }
    }
}

// ---------------------------------------------------------------------------
// 3-plane VN GEMM (vi pair only): preloaded planes, fused norm epilogue.
// ---------------------------------------------------------------------------
struct VSet {
    const hf *A;
    const hf *B;
    hf *C;
    hf *Nrm;
};

__global__ void __launch_bounds__(512, 2)
gemm_vn3(VSet s0, VSet s1, int Nn) {
    extern __shared__ hf vsm[];
    hf* Bs = vsm;
    hf* As = vsm + 64 * 72;
    const int tid = threadIdx.x, lane = tid & 31, wid = tid >> 5;
    const int wm = wid >> 1, wn = wid & 1;
    const VSet S = blockIdx.y ? s1 : s0;
    const int m0 = blockIdx.x * 128;
    const size_t P = (size_t)Nn * 64;

    auto loadA = [&](int d) {
#pragma unroll
        for (int it = 0; it < 2; it++) {
            int i = tid + it * 512;
            int r = i >> 3, sg = i & 7;
            int m = m0 + r;
            uint32_t sa = smem_u32(As + d * (128 * 72) + r * 72 + sg * 8);
            const hf* ga = S.A + d * P + ((m < Nn) ? ((size_t)m * 64 + sg * 8) : 0);
            CP_ASYNC16_P(sa, ga, (m < Nn) ? 16 : 0);
        }
        CP_COMMIT();
    };

    {
        int r = tid >> 3, c8 = tid & 7;
        CP_ASYNC16(smem_u32(Bs + r * 72 + c8 * 8), S.B + r * 64 + c8 * 8);
    }
    loadA(0);
    loadA(1);
    loadA(2);

    float acc[3][4][4];
#pragma unroll
    for (int d = 0; d < 3; d++)
#pragma unroll
        for (int j = 0; j < 4; j++)
#pragma unroll
            for (int k = 0; k < 4; k++) acc[d][j][k] = 0.f;

    int aOff = (wm * 16 + (lane & 15)) * 72 + (lane >> 4) * 8;
    int bOff;
    {
        int g = lane >> 3, r = lane & 7;
        int nt8 = (g >> 1), ko = (g & 1) * 8;
        bOff = (wn * 32 + nt8 * 8 + r) * 72 + ko;
    }
    uint32_t aBase = smem_u32(As);
    uint32_t bBase = smem_u32(Bs);

#pragma unroll
    for (int d = 0; d < 3; d++) {
        if (d == 0) CP_WAIT2();
        else if (d == 1) CP_WAIT1();
        else CP_WAIT0();
        __syncthreads();
        uint32_t aB = aBase + d * (128 * 72 * 2);
#pragma unroll
        for (int kk = 0; kk < 4; kk++) {
            const int k16 = kk * 16;
            uint32_t a[4];
            LDSM_X4(a[0], a[1], a[2], a[3], aB + (aOff + k16) * 2);
            uint32_t b[4][2];
#pragma unroll
            for (int half = 0; half < 2; half++) {
                uint32_t r0, r1, r2, r3;
                LDSM_X4(r0, r1, r2, r3, bBase + (bOff + half * 16 * 72 + k16) * 2);
                b[half * 2 + 0][0] = r0; b[half * 2 + 0][1] = r1;
                b[half * 2 + 1][0] = r2; b[half * 2 + 1][1] = r3;
            }
#pragma unroll
            for (int nt = 0; nt < 4; nt++)
                MMA16816(acc[d][nt], a, b[nt]);
        }
    }

#pragma unroll
    for (int hh = 0; hh < 2; hh++) {
        int m = m0 + wm * 16 + (lane >> 2) + hh * 8;
        if (m >= Nn) continue;
#pragma unroll
        for (int nt = 0; nt < 4; nt++) {
            int col = wn * 32 + nt * 8 + (lane & 3) * 2;
            float v[3][2];
#pragma unroll
            for (int d = 0; d < 3; d++) {
                v[d][0] = acc[d][nt][hh * 2 + 0];
                v[d][1] = acc[d][nt][hh * 2 + 1];
            }
            if (S.C) {
#pragma unroll
                for (int d = 0; d < 3; d++)
                    store_h2(S.C, d * P + (size_t)m * 64 + col, v[d][0], v[d][1]);
            }
            if (S.Nrm) {
                float n0 = sqrtf(v[0][0] * v[0][0] + v[1][0] * v[1][0] + v[2][0] * v[2][0]);
                float n1 = sqrtf(v[0][1] * v[0][1] + v[1][1] * v[1][1] + v[2][1] * v[2][1]);
                store_h2(S.Nrm, (size_t)m * 64 + col, n0, n1);
            }
        }
    }
}

// ---------------------------------------------------------------------------
// CHAIN kernel, 64-row tiles / 256 threads / 2 blocks-per-SM:
//   u = gate ⊙ (vi @ W2ᵀ) ; d = u @ Wdᵀ ; v = vnlrelu(u,d) ; vi2 = v @ W1pᵀ
// 8 warps (4M x 2N), warp tile 16x32 per plane. smem ~83 KB.
// ---------------------------------------------------------------------------
struct CSet {
    const hf* Vin;
    const float* gate;
    const hf *W2, *Wd, *W1p;
    hf* Pout;
    hf* Nrm;
};

__global__ void __launch_bounds__(256, 2)
k_chain(CSet s0, CSet s1, int Nn) {
    constexpr int WP = 64 * 72;
    constexpr int XP = 64 * 72;
    extern __shared__ hf csm[];
    hf* Wsm = csm;                  // [3][64*72]
    hf* X   = csm + 3 * WP;         // [3][64*72]
    hf* U   = X + 3 * XP;           // [3][64*72]

    const int tid = threadIdx.x, lane = tid & 31, wid = tid >> 5;
    const int wm = wid >> 1, wn = wid & 1;   // 4M x 2N
    const CSet S = blockIdx.y ? s1 : s0;
    const int m0 = blockIdx.x * 64;
    const size_t P = (size_t)Nn * 64;

    for (int i = tid; i < 1536; i += 256) {
        int w = i >> 9, j = i & 511;
        int r = j >> 3, c8 = j & 7;
        const hf* src = (w == 0) ? S.W2 : ((w == 1) ? S.Wd : S.W1p);
        CP_ASYNC16(smem_u32(Wsm + w * WP + r * 72 + c8 * 8), src + r * 64 + c8 * 8);
    }
    for (int i = tid; i < 1536; i += 256) {
        int d = i >> 9, j = i & 511;
        int r = j >> 3, sg = j & 7;
        int m = m0 + r;
        uint32_t sa = smem_u32(X + d * XP + r * 72 + sg * 8);
        const hf* ga = S.Vin + d * P + ((m < Nn) ? ((size_t)m * 64 + sg * 8) : 0);
        CP_ASYNC16_P(sa, ga, (m < Nn) ? 16 : 0);
    }
    CP_COMMIT();

    const int aOff = (wm * 16 + (lane & 15)) * 72 + (lane >> 4) * 8;
    int bOff;
    {
        int g = lane >> 3, r = lane & 7;
        int nt8 = (g >> 1), ko = (g & 1) * 8;
        bOff = (wn * 32 + nt8 * 8 + r) * 72 + ko;
    }
    const int mlBase = wm * 16 + (lane >> 2);
    const int colBase = wn * 32 + (lane & 3) * 2;

    auto gemm64 = [&](uint32_t aTile, uint32_t bTile, float acc[4][4]) {
#pragma unroll
        for (int j = 0; j < 4; j++)
#pragma unroll
            for (int k = 0; k < 4; k++) acc[j][k] = 0.f;
#pragma unroll
        for (int kk = 0; kk < 4; kk++) {
            const int k16 = kk * 16;
            uint32_t a[4];
            LDSM_X4(a[0], a[1], a[2], a[3], aTile + (aOff + k16) * 2);
            uint32_t b[4][2];
#pragma unroll
            for (int half = 0; half < 2; half++) {
                uint32_t r0, r1, r2, r3;
                LDSM_X4(r0, r1, r2, r3, bTile + (bOff + half * 16 * 72 + k16) * 2);
                b[half * 2 + 0][0] = r0; b[half * 2 + 0][1] = r1;
                b[half * 2 + 1][0] = r2; b[half * 2 + 1][1] = r3;
            }
#pragma unroll
            for (int nt = 0; nt < 4; nt++)
                MMA16816(acc[nt], a, b[nt]);
        }
    };

    uint32_t xB = smem_u32(X);
    uint32_t uB = smem_u32(U);
    uint32_t wB = smem_u32(Wsm);

    CP_WAIT0();
    __syncthreads();

    // phase 1: u = gate * (vi @ W2^T)
#pragma unroll
    for (int d = 0; d < 3; d++) {
        float acc[4][4];
        gemm64(xB + d * (XP * 2), wB, acc);
#pragma unroll
        for (int hh = 0; hh < 2; hh++) {
            int ml = mlBase + hh * 8;
            int node = m0 + ml;
            if (node >= Nn) continue;
#pragma unroll
            for (int nt = 0; nt < 4; nt++) {
                int col = colBase + nt * 8;
                float2 gg = *(const float2*)(S.gate + (size_t)node * 64 + col);
                float v0 = acc[nt][hh * 2 + 0] * gg.x;
                float v1 = acc[nt][hh * 2 + 1] * gg.y;
                store_h2(U + d * XP, (size_t)ml * 72 + col, v0, v1);
            }
        }
    }
    __syncthreads();

    // phase 2: d = u @ Wd^T ; v = vnlrelu(u, d) -> X
    {
        float acc3[3][4][4];
#pragma unroll
        for (int d = 0; d < 3; d++)
            gemm64(uB + d * (XP * 2), wB + WP * 2, acc3[d]);
#pragma unroll
        for (int hh = 0; hh < 2; hh++) {
            int ml = mlBase + hh * 8;
#pragma unroll
            for (int nt = 0; nt < 4; nt++) {
                int col = colBase + nt * 8;
                float dd[3][2], uu[3][2];
#pragma unroll
                for (int d = 0; d < 3; d++) {
                    dd[d][0] = acc3[d][nt][hh * 2 + 0];
                    dd[d][1] = acc3[d][nt][hh * 2 + 1];
                    __half2 uh = *(const __half2*)(U + d * XP + (size_t)ml * 72 + col);
                    uu[d][0] = __half2float(uh.x);
                    uu[d][1] = __half2float(uh.y);
                }
#pragma unroll
                for (int e = 0; e < 2; e++) {
                    float dot = uu[0][e] * dd[0][e] + uu[1][e] * dd[1][e] + uu[2][e] * dd[2][e];
                    float dsq = dd[0][e] * dd[0][e] + dd[1][e] * dd[1][e] + dd[2][e] * dd[2][e];
                    float sc = dot / (dsq + EPSF);
#pragma unroll
                    for (int d = 0; d < 3; d++) {
                        float x = uu[d][e];
                        dd[d][e] = (dot >= 0.f) ? x
                                 : (SLOPEF * x + (1.f - SLOPEF) * (x - sc * dd[d][e]));
                    }
                }
#pragma unroll
                for (int d = 0; d < 3; d++)
                    store_h2(X + d * XP, (size_t)ml * 72 + col, dd[d][0], dd[d][1]);
            }
        }
    }
    __syncthreads();

    // phase 3: vi2 = v @ W1p^T ; norms + optional planes out
    {
        float acc3[3][4][4];
#pragma unroll
        for (int d = 0; d < 3; d++)
            gemm64(xB + d * (XP * 2), wB + 2 * WP * 2, acc3[d]);
#pragma unroll
        for (int hh = 0; hh < 2; hh++) {
            int ml = mlBase + hh * 8;
            int m = m0 + ml;
            if (m >= Nn) continue;
#pragma unroll
            for (int nt = 0; nt < 4; nt++) {
                int col = colBase + nt * 8;
                float v[3][2];
#pragma unroll
                for (int d = 0; d < 3; d++) {
                    v[d][0] = acc3[d][nt][hh * 2 + 0];
                    v[d][1] = acc3[d][nt][hh * 2 + 1];
                }
                if (S.Pout) {
#pragma unroll
                    for (int d = 0; d < 3; d++)
                        store_h2(S.Pout, d * P + (size_t)m * 64 + col, v[d][0], v[d][1]);
                }
                float n0 = sqrtf(v[0][0] * v[0][0] + v[1][0] * v[1][0] + v[2][0] * v[2][0]);
                float n1 = sqrtf(v[0][1] * v[0][1] + v[1][1] * v[1][1] + v[2][1] * v[2][1]);
                store_h2(S.Nrm, (size_t)m * 64 + col, n0, n1);
            }
        }
    }
}

// ---------------------------------------------------------------------------
struct PPk { const float* w; hf* o; int nc; int k; };
struct PPargs { PPk e[15]; };
__global__ void k_prepack(PPargs pa) {
    PPk p = pa.e[blockIdx.y];
    int tot = p.nc * p.k;
    for (int i = blockIdx.x * 256 + threadIdx.x; i < tot; i += gridDim.x * 256)
        p.o[i] = __float2half(p.w[i]);
}

__global__ void k_prep(const float* __restrict__ h_vec, const float* __restrict__ h_sca,
                       const float* __restrict__ te, const int* __restrict__ tptr,
                       hf* __restrict__ vh, hf* __restrict__ scah, int Nn) {
    int i = blockIdx.x * 256 + threadIdx.x;
    int half = Nn * 64;
    if (i < half) {
        int node = i >> 6, c = i & 63;
#pragma unroll
        for (int d = 0; d < 3; d++) {
            float x = h_vec[(size_t)node * 192 + c * 3 + d];
            vh[(size_t)d * Nn * 64 + (size_t)node * 64 + c] = __float2half(x);
        }
    } else if (i < 2 * half) {
        int j = i - half;
        int node = j >> 6, q4 = (j & 63) * 4;
        int t = *tptr;
        float4 hs = *(const float4*)(h_sca + (size_t)node * 256 + q4);
        float4 tv = *(const float4*)(te + (size_t)t * 256 + q4);
        size_t o = (size_t)node * 256 + q4;
        store_h2(scah, o,     hs.x + tv.x, hs.y + tv.y);
        store_h2(scah, o + 2, hs.z + tv.z, hs.w + tv.w);
    }
}

__global__ void k_att(const hf* __restrict__ Nh, const hf* __restrict__ Sa,
                      const float* __restrict__ Ws, float* __restrict__ att, int Nn) {
    __shared__ float ws[320];
    int tid = threadIdx.x, w = tid >> 5, lane = tid & 31;
    for (int i = tid; i < 320; i += 256) ws[i] = Ws[i];
    __syncthreads();
    int node = blockIdx.x * 8 + w;
    if (node >= Nn) return;
    float p = 0.f;
    for (int c = lane; c < 64; c += 32)
        p = fmaf(ws[c], __half2float(Nh[(size_t)node * 64 + c]), p);
    for (int k = lane; k < 256; k += 32) {
        float sv = __half2float(Sa[(size_t)node * 256 + k]);
        sv = (sv >= 0.f) ? sv : SLOPEF * sv;
        p = fmaf(ws[64 + k], sv, p);
    }
#pragma unroll
    for (int o = 16; o > 0; o >>= 1) p += __shfl_down_sync(0xffffffff, p, o);
    if (lane == 0) att[node] = p;
}

__global__ void k_segstart(const int* __restrict__ bid, int n, int B, int* __restrict__ start) {
    int b = blockIdx.x * blockDim.x + threadIdx.x;
    if (b > B) return;
    int lo = 0, hi = n;
    while (lo < hi) { int mid = (lo + hi) >> 1; if (bid[mid] < b) lo = mid + 1; else hi = mid; }
    start[b] = lo;
}

__global__ void k_softmax(const float* __restrict__ att, const int* __restrict__ start,
                          float* __restrict__ w) {
    int b = blockIdx.x;
    int s = start[b], e = start[b + 1];
    if (s >= e) return;
    __shared__ float red[256];
    int tid = threadIdx.x;
    float m = -INFINITY;
    for (int i = s + tid; i < e; i += 256) m = fmaxf(m, att[i]);
    red[tid] = m; __syncthreads();
    for (int o = 128; o > 0; o >>= 1) { if (tid < o) red[tid] = fmaxf(red[tid], red[tid + o]); __syncthreads(); }
    m = red[0]; __syncthreads();
    float zs = 0.f;
    for (int i = s + tid; i < e; i += 256) zs += __expf(att[i] - m);
    red[tid] = zs; __syncthreads();
    for (int o = 128; o > 0; o >>= 1) { if (tid < o) red[tid] += red[tid + o]; __syncthreads(); }
    float inv = 1.f / red[0];
    for (int i = s + tid; i < e; i += 256) w[i] = __expf(att[i] - m) * inv;
}

__global__ void k_reduce(const float* __restrict__ w, const hf* __restrict__ fs,
                         const hf* __restrict__ fv, const float* __restrict__ pos,
                         const int* __restrict__ start, int B, int Nn, float* __restrict__ out) {
    int b = blockIdx.x, j = threadIdx.x;
    int s = start[b], e = start[b + 1];
    size_t P = (size_t)Nn * 64;
    int c = j / 3, d = j - c * 3;
    float a256 = 0.f, a192 = 0.f, a3 = 0.f;
    float b256 = 0.f, b192 = 0.f, b3 = 0.f;
    int i = s;
    for (; i + 1 < e; i += 2) {
        float w0 = w[i], w1 = w[i + 1];
        a256 = fmaf(w0, __half2float(fs[(size_t)i * 256 + j]), a256);
        b256 = fmaf(w1, __half2float(fs[(size_t)(i + 1) * 256 + j]), b256);
        if (j < 192) {
            size_t q0 = (size_t)d * P + (size_t)i * 64 + c;
            size_t q1 = (size_t)d * P + (size_t)(i + 1) * 64 + c;
            a192 = fmaf(w0, __half2float(fv[q0]), a192);
            b192 = fmaf(w1, __half2float(fv[q1]), b192);
        }
        if (j < 3) {
            a3 = fmaf(w0, pos[(size_t)i * 3 + j], a3);
            b3 = fmaf(w1, pos[(size_t)(i + 1) * 3 + j], b3);
        }
    }
    if (i < e) {
        float w0 = w[i];
        a256 = fmaf(w0, __half2float(fs[(size_t)i * 256 + j]), a256);
        if (j < 192)
            a192 = fmaf(w0, __half2float(fv[(size_t)d * P + (size_t)i * 64 + c]), a192);
        if (j < 3) a3 = fmaf(w0, pos[(size_t)i * 3 + j], a3);
    }
    a256 += b256; a192 += b192; a3 += b3;
    out[(size_t)b * 256 + j] = a256;
    if (j < 192) out[(size_t)B * 256 + (size_t)b * 192 + j] = a192;
    if (j < 3)   out[(size_t)B * 256 + (size_t)B * 192 + (size_t)b * 3 + j] = a3;
}

// ---------------------------------------------------------------------------
extern "C" void kernel_launch(void* const* d_in, const int* in_sizes, int n_in,
                              void* d_out, int out_size) {
    const float* h_sca = (const float*)d_in[0];
    const float* h_vec = (const float*)d_in[1];
    const float* pos   = (const float*)d_in[2];
    const float* te    = (const float*)d_in[3];
    const float* W[26];
    for (int i = 4; i <= 25; i++) W[i] = (const float*)d_in[i];
    const int* tptr = (const int*)d_in[26];
    const int* bid  = (const int*)d_in[27];

    int n = in_sizes[0] / 256;
    int B = out_size / 451;

    hf *vecS, *viAs, *viNs, *uns, *vas, *scaX, *lrS, *Sas, *Sns;
    hf *nA1, *nN1, *nA2, *nN2, *Baug;
    float *Ga, *Gn, *att, *wgt;
    int* segs;
    cudaGetSymbolAddress((void**)&vecS, g_vecS);
    cudaGetSymbolAddress((void**)&viAs, g_viAs);
    cudaGetSymbolAddress((void**)&viNs, g_viNs);
    cudaGetSymbolAddress((void**)&uns,  g_uns);
    cudaGetSymbolAddress((void**)&vas,  g_vas);
    cudaGetSymbolAddress((void**)&scaX, g_scaX);
    cudaGetSymbolAddress((void**)&lrS,  g_lrS);
    cudaGetSymbolAddress((void**)&Sas,  g_Sas);
    cudaGetSymbolAddress((void**)&Sns,  g_Sns);
    cudaGetSymbolAddress((void**)&nA1,  g_nA1);
    cudaGetSymbolAddress((void**)&nN1,  g_nN1);
    cudaGetSymbolAddress((void**)&nA2,  g_nA2);
    cudaGetSymbolAddress((void**)&nN2,  g_nN2);
    cudaGetSymbolAddress((void**)&Baug, g_Baug);
    cudaGetSymbolAddress((void**)&Ga,   g_Ga);
    cudaGetSymbolAddress((void**)&Gn,   g_Gn);
    cudaGetSymbolAddress((void**)&att,  g_att);
    cudaGetSymbolAddress((void**)&wgt,  g_w);
    cudaGetSymbolAddress((void**)&segs, g_seg);

    static const int widx[15] = {4,15, 6,17, 7,18, 5,16, 9,20, 10,21, 23,24,22};
    static const int wnc[15]  = {64,64, 256,256, 64,64, 64,64, 64,64, 64,64, 256,64,64};
    static const int wk[15]   = {64,64, 320,320, 256,256, 64,64, 64,64, 64,64, 320,256,64};
    PPargs pa;
    size_t boff[15]; size_t acc = 0;
    for (int i = 0; i < 15; i++) {
        boff[i] = acc;
        pa.e[i] = PPk{W[widx[i]], Baug + acc, wnc[i], wk[i]};
        acc += (size_t)wnc[i] * wk[i];
    }
    const hf *B_a1Wv1 = Baug + boff[0],  *B_n1Wv1 = Baug + boff[1];
    const hf *B_a1Ws  = Baug + boff[2],  *B_n1Ws  = Baug + boff[3];
    const hf *B_a1Wg  = Baug + boff[4],  *B_n1Wg  = Baug + boff[5];
    const hf *B_a1Wv2 = Baug + boff[6],  *B_n1Wv2 = Baug + boff[7];
    const hf *B_a1Wd  = Baug + boff[8],  *B_n1Wd  = Baug + boff[9];
    const hf *B_a2Wv1 = Baug + boff[10], *B_n2Wv1 = Baug + boff[11];
    const hf *B_n2Ws  = Baug + boff[12], *B_n2Wg  = Baug + boff[13];
    const hf *B_n2Wv2 = Baug + boff[14];

    int M3 = 3 * n;
    int gv = (n + 127) / 128;
    int gc = (n + 63) / 64;
    int g3 = (M3 + 127) / 128;

    constexpr int SM64  = 2 * (128 + 64) * 72 * 2;      // 55296 B
    constexpr int SM128 = 3 * (128 + 128) * 72 * 2;     // 110592 B
    constexpr int SMV   = (64 * 72 + 3 * 128 * 72) * 2; // 64512 B
    constexpr int SMC   = 9 * 64 * 72 * 2;              // 82944 B
    cudaFuncSetAttribute((const void*)gemm_f16<64, 256, 256>,
                         cudaFuncAttributeMaxDynamicSharedMemorySize, SM64);
    cudaFuncSetAttribute((const void*)gemm_f16<64, 64, 64>,
                         cudaFuncAttributeMaxDynamicSharedMemorySize, SM64);
    cudaFuncSetAttribute((const void*)gemm_f16<128, 320, 64>,
                         cudaFuncAttributeMaxDynamicSharedMemorySize, SM128);
    cudaFuncSetAttribute((const void*)gemm_vn3,
                         cudaFuncAttributeMaxDynamicSharedMemorySize, SMV);
    cudaFuncSetAttribute((const void*)k_chain,
                         cudaFuncAttributeMaxDynamicSharedMemorySize, SMC);

    auto GS = [](const hf* a1, const hf* a2, const hf* b,
                 float* cf, hf* ch, hf* lh,
                 const float* bias, const float* gate, int act) {
        GSet g; g.A1 = a1; g.A2 = a2; g.B = b;
        g.Cf = cf; g.Ch = ch; g.Lh = lh;
        g.bias = bias; g.gate = gate; g.act = act; return g;
    };

    k_prepack<<<dim3(64, 15), 256>>>(pa);
    k_prep<<<(n * 128 + 255) / 256, 256>>>(h_vec, h_sca, te, tptr, vecS, scaX, n);

    // vi pair: planes + norms
    {
        VSet a; a.A = vecS; a.B = B_a1Wv1; a.C = viAs; a.Nrm = nA1;
        VSet b; b.A = vecS; b.B = B_n1Wv1; b.C = viNs; b.Nrm = nN1;
        gemm_vn3<<<dim3(gv, 2), 512, SMV>>>(a, b, n);
    }
    // S pair: A = (norms | sca shared); net side also emits lrelu(Sn)
    gemm_f16<128, 320, 64><<<dim3(gv, 2, 2), 512, SM128>>>(
        GS(nA1, scaX, B_a1Ws, nullptr, Sas, nullptr, nullptr, nullptr, 0),
        GS(nN1, scaX, B_n1Ws, nullptr, Sns, lrS,     nullptr, nullptr, 0),
        n, n, 256);
    // gates pair
    gemm_f16<64, 256, 256><<<dim3(gv, 2, 1), 256, SM64>>>(
        GS(Sas, nullptr, B_a1Wg, Ga, nullptr, nullptr, W[8],  nullptr, 1),
        GS(Sns, nullptr, B_n1Wg, Gn, nullptr, nullptr, W[19], nullptr, 1),
        n, n, 64);
    // fused chain: u -> d -> vnlrelu -> vi2
    {
        CSet a; a.Vin = viAs; a.gate = Ga; a.W2 = B_a1Wv2; a.Wd = B_a1Wd;
        a.W1p = B_a2Wv1; a.Pout = nullptr; a.Nrm = nA2;
        CSet b; b.Vin = viNs; b.gate = Gn; b.W2 = B_n1Wv2; b.Wd = B_n1Wd;
        b.W1p = B_n2Wv1; b.Pout = uns; b.Nrm = nN2;
        k_chain<<<dim3(gc, 2), 256, SMC>>>(a, b, n);
    }
    k_att<<<(n + 7) / 8, 256>>>(nA2, Sas, W[12], att, n);

    // fs = (norms2 | lrelu(Sn)) @ n2Ws -> Sas reuse
    {
        GSet g = GS(nN2, lrS, B_n2Ws, nullptr, Sas, nullptr, nullptr, nullptr, 0);
        gemm_f16<128, 320, 64><<<dim3(gv, 1, 2), 512, SM128>>>(g, g, n, n, 256);
    }
    // gate2 -> Ga reuse
    {
        GSet g = GS(Sas, nullptr, B_n2Wg, Ga, nullptr, nullptr, W[25], nullptr, 1);
        gemm_f16<64, 256, 256><<<dim3(gv, 1, 1), 256, SM64>>>(g, g, n, n, 64);
    }
    // fv = gate2 * (n2Wv2 @ vi2n) -> vas
    {
        GSet g = GS(uns, nullptr, B_n2Wv2, nullptr, vas, nullptr, nullptr, Ga, 0);
        gemm_f16<64, 64, 64><<<dim3(g3, 1, 1), 256, SM64>>>(g, g, M3, n, 64);
    }

    k_segstart<<<(B + 1 + 255) / 256, 256>>>(bid, n, B, segs);
    k_softmax<<<B, 256>>>(att, segs, wgt);
    k_reduce<<<B, 256>>>(wgt, Sas, vas, pos, segs, B, n, (float*)d_out);
}